// round 4
// baseline (speedup 1.0000x reference)
#include <cuda_runtime.h>
#include <math.h>

#define Bn   4
#define HWp  16384
#define LSEQ 16384

typedef unsigned long long u64;
__device__ __forceinline__ void fma2(u64 &d, u64 a, u64 b){
    asm("fma.rn.f32x2 %0, %1, %2, %0;" : "+l"(d) : "l"(a), "l"(b));
}
__device__ __forceinline__ float2 unpack2(u64 v){
    float2 r; asm("mov.b64 {%0, %1}, %2;" : "=f"(r.x), "=f"(r.y) : "l"(v)); return r;
}

// ---------------- scratch ----------------
__device__ float g_xT[Bn*HWp*64];        // [b][pix][c]
__device__ float g_rawoff[Bn*10*HWp];    // offset conv out, [b][co][pix]
__device__ float g_ostats[Bn*5*2];
__device__ float g_seq[Bn*9*LSEQ];       // [b][m][l]
__device__ float g_ynew[Bn*9*HWp];       // [b][k][pix]
__device__ float g_dt[Bn*18*LSEQ];
__device__ float g_xi[Bn*18*LSEQ];
__device__ float g_gate[Bn*18*LSEQ];     // silu(z)
__device__ float g_Bsc[Bn*16*LSEQ];
__device__ float g_Csc[Bn*16*LSEQ];
__device__ float g_P[Bn*64*288];
__device__ float g_Q[Bn*64*288];
__device__ float g_hinit[Bn*64*288];
__device__ float g_py[Bn*9*HWp];         // [b][k][pix]
__device__ float g_wT[9*64*64];          // [k][ci][co]
__device__ float g_outraw[Bn*64*HWp];
__device__ float g_fstats[Bn*16*2];

__device__ __forceinline__ float softplusf(float x){
    return x > 20.f ? x : log1pf(expf(x));
}
__device__ __forceinline__ float siluf(float x){
    return x / (1.f + expf(-x));
}

// ---------------- zero stats ----------------
__global__ void kZero(){
    int t = threadIdx.x;
    if (t < 40)  g_ostats[t] = 0.f;
    if (t < 128) g_fstats[t] = 0.f;
}

// ---------------- transpose x ----------------
__global__ void kTranspose(const float* __restrict__ x){
    __shared__ float tile[32][33];
    int b = blockIdx.z, c0 = blockIdx.y*32, p0 = blockIdx.x*32;
    for (int i = threadIdx.y; i < 32; i += 8)
        tile[i][threadIdx.x] = x[(size_t)(b*64 + c0 + i)*HWp + p0 + threadIdx.x];
    __syncthreads();
    for (int i = threadIdx.y; i < 32; i += 8)
        g_xT[(size_t)(b*HWp + p0 + i)*64 + c0 + threadIdx.x] = tile[threadIdx.x][i];
}

// ---------------- weight transpose for deform conv ----------------
__global__ void kPrepW(const float* __restrict__ dscw){
    int idx = blockIdx.x*256 + threadIdx.x;
    if (idx >= 9*64*64) return;
    int k = idx >> 12; int r = idx & 4095;
    int ci = r >> 6;  int co = r & 63;
    g_wT[idx] = dscw[(co*64 + ci)*9 + k];
}

// ---------------- offset conv 3x3 64->10, register-tiled + GN stats ----------------
#define CONV_SMEM ((16*4*132 + 5760)*4)
__global__ void __launch_bounds__(320) kConv(const float* __restrict__ x,
                                             const float* __restrict__ offw,
                                             const float* __restrict__ offb){
    extern __shared__ float sm[];
    float* xs = sm;            // [c][r][ww], stride 132
    float* sW = sm + 16*4*132; // offw direct copy
    int hb = blockIdx.x, b = blockIdx.y, tid = threadIdx.x;
    int h0 = hb*2;
    int hh = tid & 1, wt = (tid >> 1) & 15, co = tid >> 5;
    int w0 = wt*8;

    for (int idx = tid; idx < 5760; idx += 320) sW[idx] = offw[idx];

    float acc[8];
    float bv = offb[co];
    #pragma unroll
    for (int i = 0; i < 8; i++) acc[i] = bv;

    for (int cc = 0; cc < 4; cc++){
        int c0 = cc*16;
        __syncthreads();
        for (int idx = tid; idx < 16*4*130; idx += 320){
            int c = idx / 520;
            int rem = idx - c*520;
            int rr = rem / 130;
            int ww = rem - rr*130;
            int gh = h0 - 1 + rr, gw = ww - 1;
            float v = 0.f;
            if (gh >= 0 && gh < 128 && gw >= 0 && gw < 128)
                v = x[((size_t)(b*64 + c0 + c)*128 + gh)*128 + gw];
            xs[(c*4 + rr)*132 + ww] = v;
        }
        __syncthreads();
        for (int c = 0; c < 16; c++){
            #pragma unroll
            for (int dy = 0; dy < 3; dy++){
                const float* wp = &sW[(co*64 + c0 + c)*9 + dy*3];
                float wA = wp[0], wB = wp[1], wC = wp[2];
                const float* row = &xs[(c*4 + hh + dy)*132];
                float4 vA = *(const float4*)&row[w0];
                float4 vB = *(const float4*)&row[w0+4];
                float v8 = row[w0+8], v9 = row[w0+9];
                float v[10] = {vA.x,vA.y,vA.z,vA.w,vB.x,vB.y,vB.z,vB.w,v8,v9};
                #pragma unroll
                for (int i = 0; i < 8; i++)
                    acc[i] += wA*v[i] + wB*v[i+1] + wC*v[i+2];
            }
        }
    }

    int h = h0 + hh;
    float s = 0.f, ss = 0.f;
    #pragma unroll
    for (int i = 0; i < 8; i++){
        g_rawoff[((size_t)(b*10+co))*HWp + h*128 + w0 + i] = acc[i];
        s += acc[i]; ss += acc[i]*acc[i];
    }
    #pragma unroll
    for (int m = 16; m > 0; m >>= 1){
        s  += __shfl_xor_sync(0xffffffffu, s,  m);
        ss += __shfl_xor_sync(0xffffffffu, ss, m);
    }
    if ((tid & 31) == 0){
        atomicAdd(&g_ostats[(b*5 + (co>>1))*2    ], s);
        atomicAdd(&g_ostats[(b*5 + (co>>1))*2 + 1], ss);
    }
}

// ---------------- GN finalize + tanh + cumsum + seq + y_new ----------------
__global__ void kFinishOff(const float* __restrict__ gnog, const float* __restrict__ gnob){
    __shared__ float sMu[5], sRs[5];
    int b = blockIdx.y, tid = threadIdx.x;
    int p = blockIdx.x*256 + tid;
    if (tid < 5){
        float s  = g_ostats[(b*5+tid)*2];
        float ss = g_ostats[(b*5+tid)*2+1];
        float mu = s * (1.f/32768.f);
        float var = ss * (1.f/32768.f) - mu*mu;
        sMu[tid] = mu;
        sRs[tid] = rsqrtf(var + 1e-5f);
    }
    __syncthreads();

    float tv[9];
    #pragma unroll
    for (int c = 0; c < 9; c++){
        float raw = g_rawoff[((size_t)(b*10+c))*HWp + p];
        float xn = (raw - sMu[c>>1]) * sRs[c>>1] * gnog[c] + gnob[c];
        tv[c] = tanhf(xn);
    }
    float cum[9];
    cum[4] = 0.f;
    cum[5] = tv[5]; cum[6] = cum[5]+tv[6]; cum[7] = cum[6]+tv[7]; cum[8] = cum[7]+tv[8];
    cum[3] = tv[3]; cum[2] = cum[3]+tv[2]; cum[1] = cum[2]+tv[1]; cum[0] = cum[1]+tv[0];

    int h = p >> 7, w = p & 127;
    #pragma unroll
    for (int k = 0; k < 9; k++)
        g_ynew[((size_t)(b*9+k))*HWp + p] = (float)h + cum[k];

    int l = ((h>>1)*128 + w)*2 + (h&1);
    #pragma unroll
    for (int m = 0; m < 9; m++)
        g_seq[((size_t)(b*9+m))*LSEQ + l] = tv[m];
}

// ---------------- mamba front-end ----------------
__global__ void kFrontEnd(const float* __restrict__ ipw, const float* __restrict__ cw,
                          const float* __restrict__ cb,  const float* __restrict__ xpw,
                          const float* __restrict__ dtw, const float* __restrict__ dtb){
    __shared__ float sXP[259*19];
    __shared__ float sIPW[324], sXPW[594], sCW[72], sCB[18], sDTW[18], sDTB[18];
    int b = blockIdx.y, l0 = blockIdx.x*256, tid = threadIdx.x;
    int l = l0 + tid;

    for (int idx = tid; idx < 324; idx += 256) sIPW[idx] = ipw[idx];
    for (int idx = tid; idx < 594; idx += 256) sXPW[idx] = xpw[idx];
    if (tid < 72) sCW[tid] = cw[tid];
    if (tid < 18){ sCB[tid] = cb[tid]; sDTW[tid] = dtw[tid]; sDTB[tid] = dtb[tid]; }
    __syncthreads();

    float sq[9];
    #pragma unroll
    for (int m = 0; m < 9; m++) sq[m] = g_seq[((size_t)(b*9+m))*LSEQ + l];
    #pragma unroll
    for (int n = 0; n < 18; n++){
        float v = 0.f;
        #pragma unroll
        for (int m = 0; m < 9; m++) v += sq[m]*sIPW[n*9+m];
        sXP[(tid+3)*19 + n] = v;
    }
    #pragma unroll
    for (int n = 0; n < 18; n++){
        float z = 0.f;
        #pragma unroll
        for (int m = 0; m < 9; m++) z += sq[m]*sIPW[(18+n)*9+m];
        g_gate[((size_t)(b*18+n))*LSEQ + l] = siluf(z);
    }
    if (tid < 3){
        int l2 = l0 - 3 + tid;
        if (l2 >= 0){
            float s2[9];
            #pragma unroll
            for (int m = 0; m < 9; m++) s2[m] = g_seq[((size_t)(b*9+m))*LSEQ + l2];
            #pragma unroll
            for (int n = 0; n < 18; n++){
                float v = 0.f;
                #pragma unroll
                for (int m = 0; m < 9; m++) v += s2[m]*sIPW[n*9+m];
                sXP[tid*19 + n] = v;
            }
        } else {
            #pragma unroll
            for (int n = 0; n < 18; n++) sXP[tid*19 + n] = 0.f;
        }
    }
    __syncthreads();

    float xi[18];
    #pragma unroll
    for (int d = 0; d < 18; d++){
        float xc = sCB[d];
        #pragma unroll
        for (int j = 0; j < 4; j++) xc += sCW[d*4+j]*sXP[(tid+j)*19 + d];
        xi[d] = siluf(xc);
    }
    float dtr = 0.f;
    #pragma unroll
    for (int d = 0; d < 18; d++) dtr += xi[d]*sXPW[d];
    #pragma unroll
    for (int s = 0; s < 16; s++){
        float bv = 0.f, cv = 0.f;
        #pragma unroll
        for (int d = 0; d < 18; d++){
            bv += xi[d]*sXPW[(1+s)*18 + d];
            cv += xi[d]*sXPW[(17+s)*18 + d];
        }
        g_Bsc[((size_t)(b*16+s))*LSEQ + l] = bv;
        g_Csc[((size_t)(b*16+s))*LSEQ + l] = cv;
    }
    #pragma unroll
    for (int d = 0; d < 18; d++){
        float a = dtr*sDTW[d] + sDTB[d];
        g_dt[((size_t)(b*18+d))*LSEQ + l] = softplusf(a);
        g_xi[((size_t)(b*18+d))*LSEQ + l] = xi[d];
    }
}

// ---------------- scan pass1: per-chunk (P,Q) ----------------
#define SCAN1_SMEM (52*257*4)
__global__ void kScan1(const float* __restrict__ Alog){
    extern __shared__ float sm[];
    float* sDT = sm;
    float* sXI = sm + 18*257;
    float* sB  = sm + 36*257;
    int b = blockIdx.y, c = blockIdx.x, l0 = c*256, t = threadIdx.x;
    for (int idx = t; idx < 18*256; idx += 288){
        int dd = idx >> 8, i = idx & 255;
        sDT[dd*257+i] = g_dt[((size_t)(b*18+dd))*LSEQ + l0 + i];
        sXI[dd*257+i] = g_xi[((size_t)(b*18+dd))*LSEQ + l0 + i];
    }
    for (int idx = t; idx < 16*256; idx += 288){
        int ss = idx >> 8, i = idx & 255;
        sB[ss*257+i] = g_Bsc[((size_t)(b*16+ss))*LSEQ + l0 + i];
    }
    __syncthreads();
    int d = t / 16, s = t % 16;
    float a = -expf(Alog[d*16+s]);
    float p = 1.f, q = 0.f;
    for (int i = 0; i < 256; i++){
        float dt = sDT[d*257+i];
        float da = __expf(dt*a);
        q = da*q + dt*sB[s*257+i]*sXI[d*257+i];
        p *= da;
    }
    g_P[(b*64+c)*288 + t] = p;
    g_Q[(b*64+c)*288 + t] = q;
}

// ---------------- scan pass2: serial carry ----------------
__global__ void kScan2(){
    int b = blockIdx.x, t = threadIdx.x;
    float h = 0.f;
    for (int c = 0; c < 64; c++){
        g_hinit[(b*64+c)*288 + t] = h;
        h = g_P[(b*64+c)*288 + t]*h + g_Q[(b*64+c)*288 + t];
    }
}

// ---------------- scan pass3: replay + output + py ----------------
#define SCAN3_SMEM ((86*257 + 162 + 18)*4)
__global__ void kScan3(const float* __restrict__ Alog, const float* __restrict__ Dp,
                       const float* __restrict__ opw,  const float* __restrict__ altho){
    extern __shared__ float sm[];
    float* sDT = sm;
    float* sXI = sm + 18*257;
    float* sB  = sm + 36*257;
    float* sC  = sm + 52*257;
    float* sYS = sm + 68*257;
    float* sOPW = sm + 86*257;
    float* sDP  = sOPW + 162;
    int b = blockIdx.y, c = blockIdx.x, l0 = c*256, t = threadIdx.x;
    for (int idx = t; idx < 18*256; idx += 288){
        int dd = idx >> 8, i = idx & 255;
        sDT[dd*257+i] = g_dt[((size_t)(b*18+dd))*LSEQ + l0 + i];
        sXI[dd*257+i] = g_xi[((size_t)(b*18+dd))*LSEQ + l0 + i];
    }
    for (int idx = t; idx < 16*256; idx += 288){
        int ss = idx >> 8, i = idx & 255;
        sB[ss*257+i] = g_Bsc[((size_t)(b*16+ss))*LSEQ + l0 + i];
        sC[ss*257+i] = g_Csc[((size_t)(b*16+ss))*LSEQ + l0 + i];
    }
    if (t < 162) sOPW[t] = opw[t];
    if (t < 18)  sDP[t]  = Dp[t];
    __syncthreads();

    int d = t / 16, s = t % 16;
    float a = -expf(Alog[d*16+s]);
    float h = g_hinit[(b*64+c)*288 + t];
    for (int i = 0; i < 256; i++){
        float dt = sDT[d*257+i];
        float da = __expf(dt*a);
        h = da*h + dt*sB[s*257+i]*sXI[d*257+i];
        float v = h * sC[s*257+i];
        v += __shfl_xor_sync(0xffffffffu, v, 1);
        v += __shfl_xor_sync(0xffffffffu, v, 2);
        v += __shfl_xor_sync(0xffffffffu, v, 4);
        v += __shfl_xor_sync(0xffffffffu, v, 8);
        if ((t & 15) == 0) sYS[d*257+i] = v;
    }
    __syncthreads();

    if (t < 256){
        int l = l0 + t;
        float wgt = fmaxf(softplusf(altho[0]), 0.01f);
        float ym[9];
        #pragma unroll
        for (int m = 0; m < 9; m++) ym[m] = 0.f;
        #pragma unroll
        for (int dd = 0; dd < 18; dd++){
            float yv = (sYS[dd*257+t] + sDP[dd]*sXI[dd*257+t]) * g_gate[((size_t)(b*18+dd))*LSEQ + l];
            #pragma unroll
            for (int m = 0; m < 9; m++) ym[m] += yv * sOPW[m*18+dd];
        }
        int tt = l & 1, r = l >> 1;
        int w = r & 127, h2 = r >> 7;
        int pix = (h2*2 + tt)*128 + w;
        #pragma unroll
        for (int m = 0; m < 9; m++){
            float py = wgt*ym[m] + g_ynew[((size_t)(b*9+m))*HWp + pix];
            py = fminf(fmaxf(py, 0.f), 127.f);
            g_py[((size_t)(b*9+m))*HWp + pix] = py;
        }
    }
}

// ---------------- deformable gather + contraction (f32x2 packed) + GN stats ----------------
// sVal holds duplicated pairs (v,v): row ci has 128 pixels * 2 floats (stride 256).
// Inner loop per ci: 4x LDS.64 (pixel pairs) + 2x LDS.128 (weight pairs) + 16 FFMA2.
#define DEF_SMEM ((64*256 + 64*64)*4)
__global__ void __launch_bounds__(256) kDeform(const float* __restrict__ dscb){
    extern __shared__ float sm[];
    float* sVal = sm;           // [ci][2*pix], duplicated values
    float* sW   = sm + 64*256;  // [ci][co]
    int i = blockIdx.x, b = blockIdx.y, t = threadIdx.x;
    int coq = t >> 5, lq = t & 31;
    int j = t & 127, half = t >> 7;   // gather role: 128 pixels x 2 halves of channels

    u64 acc2[4][4];
    #pragma unroll
    for (int a = 0; a < 4; a++)
        #pragma unroll
        for (int p = 0; p < 4; p++) acc2[a][p] = 0ULL;

    for (int k = 0; k < 9; k++){
        #pragma unroll
        for (int r = 0; r < 16; r++) sW[t + 256*r] = g_wT[k*4096 + t + 256*r];

        float pyv = g_py[((size_t)(b*9+k))*HWp + i*128 + j];
        int y0 = (int)floorf(pyv);
        float wy = pyv - (float)y0;
        int y1 = min(y0 + 1, 127);
        int xc = min(max(j + k - 4, 0), 127);
        const float* r0 = &g_xT[((size_t)b*HWp + y0*128 + xc)*64 + half*32];
        const float* r1 = &g_xT[((size_t)b*HWp + y1*128 + xc)*64 + half*32];
        float wy0 = 1.f - wy;
        #pragma unroll
        for (int c2 = 0; c2 < 32; c2++){
            float v = r0[c2]*wy0 + r1[c2]*wy;
            *(float2*)&sVal[(half*32 + c2)*256 + 2*j] = make_float2(v, v);
        }
        __syncthreads();

        #pragma unroll 2
        for (int ci = 0; ci < 64; ci++){
            u64 vp0 = *(const u64*)&sVal[ci*256 + 2*lq];
            u64 vp1 = *(const u64*)&sVal[ci*256 + 2*(lq+32)];
            u64 vp2 = *(const u64*)&sVal[ci*256 + 2*(lq+64)];
            u64 vp3 = *(const u64*)&sVal[ci*256 + 2*(lq+96)];
            ulonglong2 wa = *(const ulonglong2*)&sW[ci*64 + coq*8];
            ulonglong2 wb = *(const ulonglong2*)&sW[ci*64 + coq*8 + 4];
            fma2(acc2[0][0], wa.x, vp0); fma2(acc2[0][1], wa.y, vp0);
            fma2(acc2[0][2], wb.x, vp0); fma2(acc2[0][3], wb.y, vp0);
            fma2(acc2[1][0], wa.x, vp1); fma2(acc2[1][1], wa.y, vp1);
            fma2(acc2[1][2], wb.x, vp1); fma2(acc2[1][3], wb.y, vp1);
            fma2(acc2[2][0], wa.x, vp2); fma2(acc2[2][1], wa.y, vp2);
            fma2(acc2[2][2], wb.x, vp2); fma2(acc2[2][3], wb.y, vp2);
            fma2(acc2[3][0], wa.x, vp3); fma2(acc2[3][1], wa.y, vp3);
            fma2(acc2[3][2], wb.x, vp3); fma2(acc2[3][3], wb.y, vp3);
        }
        __syncthreads();
    }

    float gs[2] = {0.f, 0.f}, gss[2] = {0.f, 0.f};
    #pragma unroll
    for (int p = 0; p < 4; p++){
        int co0 = coq*8 + 2*p, co1 = co0 + 1;
        float b0 = dscb[co0], b1 = dscb[co1];
        int gg = p >> 1;
        #pragma unroll
        for (int jj = 0; jj < 4; jj++){
            float2 v = unpack2(acc2[jj][p]);
            float va = v.x + b0, vb = v.y + b1;
            size_t pix = (size_t)i*128 + lq + 32*jj;
            g_outraw[((size_t)(b*64+co0))*HWp + pix] = va;
            g_outraw[((size_t)(b*64+co1))*HWp + pix] = vb;
            gs[gg] += va + vb; gss[gg] += va*va + vb*vb;
        }
    }
    #pragma unroll
    for (int gg = 0; gg < 2; gg++){
        float s = gs[gg], ss = gss[gg];
        #pragma unroll
        for (int m = 16; m > 0; m >>= 1){
            s  += __shfl_xor_sync(0xffffffffu, s,  m);
            ss += __shfl_xor_sync(0xffffffffu, ss, m);
        }
        if (lq == 0){
            atomicAdd(&g_fstats[(b*16 + coq*2 + gg)*2    ], s);
            atomicAdd(&g_fstats[(b*16 + coq*2 + gg)*2 + 1], ss);
        }
    }
}

// ---------------- final GN ----------------
__global__ void kFinalGN(const float* __restrict__ gng, const float* __restrict__ gnb,
                         float* __restrict__ out){
    int idx = blockIdx.x*256 + threadIdx.x;
    int b = idx >> 20;
    int c = (idx >> 14) & 63;
    int g = c >> 2;
    float s  = g_fstats[(b*16+g)*2];
    float ss = g_fstats[(b*16+g)*2+1];
    float mu = s * (1.f/65536.f);
    float var = ss * (1.f/65536.f) - mu*mu;
    float rs = rsqrtf(var + 1e-5f);
    out[idx] = (g_outraw[idx] - mu)*rs*gng[c] + gnb[c];
}

extern "C" void kernel_launch(void* const* d_in, const int* in_sizes, int n_in,
                              void* d_out, int out_size){
    const float* x     = (const float*)d_in[0];
    const float* offw  = (const float*)d_in[1];
    const float* offb  = (const float*)d_in[2];
    const float* gnog  = (const float*)d_in[3];
    const float* gnob  = (const float*)d_in[4];
    const float* altho = (const float*)d_in[5];
    const float* ipw   = (const float*)d_in[6];
    const float* cw    = (const float*)d_in[7];
    const float* cb    = (const float*)d_in[8];
    const float* xpw   = (const float*)d_in[9];
    const float* dtw   = (const float*)d_in[10];
    const float* dtb   = (const float*)d_in[11];
    const float* Alog  = (const float*)d_in[12];
    const float* Dp    = (const float*)d_in[13];
    const float* opw   = (const float*)d_in[14];
    const float* dscw  = (const float*)d_in[15];
    const float* dscb  = (const float*)d_in[16];
    const float* gng   = (const float*)d_in[17];
    const float* gnb   = (const float*)d_in[18];
    float* out = (float*)d_out;

    cudaFuncSetAttribute(kConv,   cudaFuncAttributeMaxDynamicSharedMemorySize, CONV_SMEM);
    cudaFuncSetAttribute(kScan1,  cudaFuncAttributeMaxDynamicSharedMemorySize, SCAN1_SMEM);
    cudaFuncSetAttribute(kScan3,  cudaFuncAttributeMaxDynamicSharedMemorySize, SCAN3_SMEM);
    cudaFuncSetAttribute(kDeform, cudaFuncAttributeMaxDynamicSharedMemorySize, DEF_SMEM);

    kZero<<<1, 128>>>();
    kTranspose<<<dim3(512, 2, 4), dim3(32, 8)>>>(x);
    kPrepW<<<144, 256>>>(dscw);
    kConv<<<dim3(64, 4), 320, CONV_SMEM>>>(x, offw, offb);
    kFinishOff<<<dim3(64, 4), 256>>>(gnog, gnob);
    kFrontEnd<<<dim3(64, 4), 256>>>(ipw, cw, cb, xpw, dtw, dtb);
    kScan1<<<dim3(64, 4), 288, SCAN1_SMEM>>>(Alog);
    kScan2<<<4, 288>>>();
    kScan3<<<dim3(64, 4), 288, SCAN3_SMEM>>>(Alog, Dp, opw, altho);
    kDeform<<<dim3(128, 4), 256, DEF_SMEM>>>(dscb);
    kFinalGN<<<16384, 256>>>(gng, gnb, out);
}

// round 5
// speedup vs baseline: 1.8326x; 1.8326x over previous
#include <cuda_runtime.h>
#include <math.h>

#define Bn   4
#define HWp  16384
#define LSEQ 16384

typedef unsigned long long u64;
__device__ __forceinline__ void fma2(u64 &d, u64 a, u64 b){
    asm("fma.rn.f32x2 %0, %1, %2, %0;" : "+l"(d) : "l"(a), "l"(b));
}
__device__ __forceinline__ u64 pack2(float v){
    u64 r; asm("mov.b64 %0, {%1, %1};" : "=l"(r) : "f"(v)); return r;
}
__device__ __forceinline__ float2 unpack2(u64 v){
    float2 r; asm("mov.b64 {%0, %1}, %2;" : "=f"(r.x), "=f"(r.y) : "l"(v)); return r;
}

// ---------------- scratch ----------------
__device__ float g_xT[Bn*HWp*64];        // [b][pix][c]
__device__ float g_rawoff[Bn*10*HWp];    // offset conv out, [b][co][pix]
__device__ float g_ostats[Bn*5*2];
__device__ float g_seq[Bn*9*LSEQ];       // [b][m][l]
__device__ float g_ynew[Bn*9*HWp];       // [b][k][pix]
__device__ float g_dt[Bn*18*LSEQ];
__device__ float g_xi[Bn*18*LSEQ];
__device__ float g_gate[Bn*18*LSEQ];     // silu(z)
__device__ float g_Bsc[Bn*16*LSEQ];
__device__ float g_Csc[Bn*16*LSEQ];
__device__ float g_P[Bn*64*288];
__device__ float g_Q[Bn*64*288];
__device__ float g_hinit[Bn*64*288];
__device__ float g_py[Bn*9*HWp];         // [b][k][pix]
__device__ float g_wT[9*64*64];          // [k][ci][co]
__device__ float g_outraw[Bn*64*HWp];
__device__ float g_fstats[Bn*16*2];

__device__ __forceinline__ float softplusf(float x){
    return x > 20.f ? x : log1pf(expf(x));
}
__device__ __forceinline__ float siluf(float x){
    return x / (1.f + expf(-x));
}

// ---------------- zero stats ----------------
__global__ void kZero(){
    int t = threadIdx.x;
    if (t < 40)  g_ostats[t] = 0.f;
    if (t < 128) g_fstats[t] = 0.f;
}

// ---------------- transpose x ----------------
__global__ void kTranspose(const float* __restrict__ x){
    __shared__ float tile[32][33];
    int b = blockIdx.z, c0 = blockIdx.y*32, p0 = blockIdx.x*32;
    for (int i = threadIdx.y; i < 32; i += 8)
        tile[i][threadIdx.x] = x[(size_t)(b*64 + c0 + i)*HWp + p0 + threadIdx.x];
    __syncthreads();
    for (int i = threadIdx.y; i < 32; i += 8)
        g_xT[(size_t)(b*HWp + p0 + i)*64 + c0 + threadIdx.x] = tile[threadIdx.x][i];
}

// ---------------- weight transpose for deform conv ----------------
__global__ void kPrepW(const float* __restrict__ dscw){
    int idx = blockIdx.x*256 + threadIdx.x;
    if (idx >= 9*64*64) return;
    int k = idx >> 12; int r = idx & 4095;
    int ci = r >> 6;  int co = r & 63;
    g_wT[idx] = dscw[(co*64 + ci)*9 + k];
}

// ---------------- offset conv 3x3 64->10, register-tiled + GN stats ----------------
#define CONV_SMEM ((16*4*132 + 5760)*4)
__global__ void __launch_bounds__(320) kConv(const float* __restrict__ x,
                                             const float* __restrict__ offw,
                                             const float* __restrict__ offb){
    extern __shared__ float sm[];
    float* xs = sm;            // [c][r][ww], stride 132
    float* sW = sm + 16*4*132; // offw direct copy
    int hb = blockIdx.x, b = blockIdx.y, tid = threadIdx.x;
    int h0 = hb*2;
    int hh = tid & 1, wt = (tid >> 1) & 15, co = tid >> 5;
    int w0 = wt*8;

    for (int idx = tid; idx < 5760; idx += 320) sW[idx] = offw[idx];

    float acc[8];
    float bv = offb[co];
    #pragma unroll
    for (int i = 0; i < 8; i++) acc[i] = bv;

    for (int cc = 0; cc < 4; cc++){
        int c0 = cc*16;
        __syncthreads();
        for (int idx = tid; idx < 16*4*130; idx += 320){
            int c = idx / 520;
            int rem = idx - c*520;
            int rr = rem / 130;
            int ww = rem - rr*130;
            int gh = h0 - 1 + rr, gw = ww - 1;
            float v = 0.f;
            if (gh >= 0 && gh < 128 && gw >= 0 && gw < 128)
                v = x[((size_t)(b*64 + c0 + c)*128 + gh)*128 + gw];
            xs[(c*4 + rr)*132 + ww] = v;
        }
        __syncthreads();
        for (int c = 0; c < 16; c++){
            #pragma unroll
            for (int dy = 0; dy < 3; dy++){
                const float* wp = &sW[(co*64 + c0 + c)*9 + dy*3];
                float wA = wp[0], wB = wp[1], wC = wp[2];
                const float* row = &xs[(c*4 + hh + dy)*132];
                float4 vA = *(const float4*)&row[w0];
                float4 vB = *(const float4*)&row[w0+4];
                float v8 = row[w0+8], v9 = row[w0+9];
                float v[10] = {vA.x,vA.y,vA.z,vA.w,vB.x,vB.y,vB.z,vB.w,v8,v9};
                #pragma unroll
                for (int i = 0; i < 8; i++)
                    acc[i] += wA*v[i] + wB*v[i+1] + wC*v[i+2];
            }
        }
    }

    int h = h0 + hh;
    float s = 0.f, ss = 0.f;
    #pragma unroll
    for (int i = 0; i < 8; i++){
        g_rawoff[((size_t)(b*10+co))*HWp + h*128 + w0 + i] = acc[i];
        s += acc[i]; ss += acc[i]*acc[i];
    }
    #pragma unroll
    for (int m = 16; m > 0; m >>= 1){
        s  += __shfl_xor_sync(0xffffffffu, s,  m);
        ss += __shfl_xor_sync(0xffffffffu, ss, m);
    }
    if ((tid & 31) == 0){
        atomicAdd(&g_ostats[(b*5 + (co>>1))*2    ], s);
        atomicAdd(&g_ostats[(b*5 + (co>>1))*2 + 1], ss);
    }
}

// ---------------- GN finalize + tanh + cumsum + seq + y_new ----------------
__global__ void kFinishOff(const float* __restrict__ gnog, const float* __restrict__ gnob){
    __shared__ float sMu[5], sRs[5];
    int b = blockIdx.y, tid = threadIdx.x;
    int p = blockIdx.x*256 + tid;
    if (tid < 5){
        float s  = g_ostats[(b*5+tid)*2];
        float ss = g_ostats[(b*5+tid)*2+1];
        float mu = s * (1.f/32768.f);
        float var = ss * (1.f/32768.f) - mu*mu;
        sMu[tid] = mu;
        sRs[tid] = rsqrtf(var + 1e-5f);
    }
    __syncthreads();

    float tv[9];
    #pragma unroll
    for (int c = 0; c < 9; c++){
        float raw = g_rawoff[((size_t)(b*10+c))*HWp + p];
        float xn = (raw - sMu[c>>1]) * sRs[c>>1] * gnog[c] + gnob[c];
        tv[c] = tanhf(xn);
    }
    float cum[9];
    cum[4] = 0.f;
    cum[5] = tv[5]; cum[6] = cum[5]+tv[6]; cum[7] = cum[6]+tv[7]; cum[8] = cum[7]+tv[8];
    cum[3] = tv[3]; cum[2] = cum[3]+tv[2]; cum[1] = cum[2]+tv[1]; cum[0] = cum[1]+tv[0];

    int h = p >> 7, w = p & 127;
    #pragma unroll
    for (int k = 0; k < 9; k++)
        g_ynew[((size_t)(b*9+k))*HWp + p] = (float)h + cum[k];

    int l = ((h>>1)*128 + w)*2 + (h&1);
    #pragma unroll
    for (int m = 0; m < 9; m++)
        g_seq[((size_t)(b*9+m))*LSEQ + l] = tv[m];
}

// ---------------- mamba front-end ----------------
__global__ void kFrontEnd(const float* __restrict__ ipw, const float* __restrict__ cw,
                          const float* __restrict__ cb,  const float* __restrict__ xpw,
                          const float* __restrict__ dtw, const float* __restrict__ dtb){
    __shared__ float sXP[259*19];
    __shared__ float sIPW[324], sXPW[594], sCW[72], sCB[18], sDTW[18], sDTB[18];
    int b = blockIdx.y, l0 = blockIdx.x*256, tid = threadIdx.x;
    int l = l0 + tid;

    for (int idx = tid; idx < 324; idx += 256) sIPW[idx] = ipw[idx];
    for (int idx = tid; idx < 594; idx += 256) sXPW[idx] = xpw[idx];
    if (tid < 72) sCW[tid] = cw[tid];
    if (tid < 18){ sCB[tid] = cb[tid]; sDTW[tid] = dtw[tid]; sDTB[tid] = dtb[tid]; }
    __syncthreads();

    float sq[9];
    #pragma unroll
    for (int m = 0; m < 9; m++) sq[m] = g_seq[((size_t)(b*9+m))*LSEQ + l];
    #pragma unroll
    for (int n = 0; n < 18; n++){
        float v = 0.f;
        #pragma unroll
        for (int m = 0; m < 9; m++) v += sq[m]*sIPW[n*9+m];
        sXP[(tid+3)*19 + n] = v;
    }
    #pragma unroll
    for (int n = 0; n < 18; n++){
        float z = 0.f;
        #pragma unroll
        for (int m = 0; m < 9; m++) z += sq[m]*sIPW[(18+n)*9+m];
        g_gate[((size_t)(b*18+n))*LSEQ + l] = siluf(z);
    }
    if (tid < 3){
        int l2 = l0 - 3 + tid;
        if (l2 >= 0){
            float s2[9];
            #pragma unroll
            for (int m = 0; m < 9; m++) s2[m] = g_seq[((size_t)(b*9+m))*LSEQ + l2];
            #pragma unroll
            for (int n = 0; n < 18; n++){
                float v = 0.f;
                #pragma unroll
                for (int m = 0; m < 9; m++) v += s2[m]*sIPW[n*9+m];
                sXP[tid*19 + n] = v;
            }
        } else {
            #pragma unroll
            for (int n = 0; n < 18; n++) sXP[tid*19 + n] = 0.f;
        }
    }
    __syncthreads();

    float xi[18];
    #pragma unroll
    for (int d = 0; d < 18; d++){
        float xc = sCB[d];
        #pragma unroll
        for (int j = 0; j < 4; j++) xc += sCW[d*4+j]*sXP[(tid+j)*19 + d];
        xi[d] = siluf(xc);
    }
    float dtr = 0.f;
    #pragma unroll
    for (int d = 0; d < 18; d++) dtr += xi[d]*sXPW[d];
    #pragma unroll
    for (int s = 0; s < 16; s++){
        float bv = 0.f, cv = 0.f;
        #pragma unroll
        for (int d = 0; d < 18; d++){
            bv += xi[d]*sXPW[(1+s)*18 + d];
            cv += xi[d]*sXPW[(17+s)*18 + d];
        }
        g_Bsc[((size_t)(b*16+s))*LSEQ + l] = bv;
        g_Csc[((size_t)(b*16+s))*LSEQ + l] = cv;
    }
    #pragma unroll
    for (int d = 0; d < 18; d++){
        float a = dtr*sDTW[d] + sDTB[d];
        g_dt[((size_t)(b*18+d))*LSEQ + l] = softplusf(a);
        g_xi[((size_t)(b*18+d))*LSEQ + l] = xi[d];
    }
}

// ---------------- scan pass1: per-chunk (P,Q) ----------------
#define SCAN1_SMEM (52*257*4)
__global__ void kScan1(const float* __restrict__ Alog){
    extern __shared__ float sm[];
    float* sDT = sm;
    float* sXI = sm + 18*257;
    float* sB  = sm + 36*257;
    int b = blockIdx.y, c = blockIdx.x, l0 = c*256, t = threadIdx.x;
    for (int idx = t; idx < 18*256; idx += 288){
        int dd = idx >> 8, i = idx & 255;
        sDT[dd*257+i] = g_dt[((size_t)(b*18+dd))*LSEQ + l0 + i];
        sXI[dd*257+i] = g_xi[((size_t)(b*18+dd))*LSEQ + l0 + i];
    }
    for (int idx = t; idx < 16*256; idx += 288){
        int ss = idx >> 8, i = idx & 255;
        sB[ss*257+i] = g_Bsc[((size_t)(b*16+ss))*LSEQ + l0 + i];
    }
    __syncthreads();
    int d = t / 16, s = t % 16;
    float a = -expf(Alog[d*16+s]);
    float p = 1.f, q = 0.f;
    for (int i = 0; i < 256; i++){
        float dt = sDT[d*257+i];
        float da = __expf(dt*a);
        q = da*q + dt*sB[s*257+i]*sXI[d*257+i];
        p *= da;
    }
    g_P[(b*64+c)*288 + t] = p;
    g_Q[(b*64+c)*288 + t] = q;
}

// ---------------- scan pass2: serial carry ----------------
__global__ void kScan2(){
    int b = blockIdx.x, t = threadIdx.x;
    float h = 0.f;
    for (int c = 0; c < 64; c++){
        g_hinit[(b*64+c)*288 + t] = h;
        h = g_P[(b*64+c)*288 + t]*h + g_Q[(b*64+c)*288 + t];
    }
}

// ---------------- scan pass3: replay + output + py ----------------
#define SCAN3_SMEM ((86*257 + 162 + 18)*4)
__global__ void kScan3(const float* __restrict__ Alog, const float* __restrict__ Dp,
                       const float* __restrict__ opw,  const float* __restrict__ altho){
    extern __shared__ float sm[];
    float* sDT = sm;
    float* sXI = sm + 18*257;
    float* sB  = sm + 36*257;
    float* sC  = sm + 52*257;
    float* sYS = sm + 68*257;
    float* sOPW = sm + 86*257;
    float* sDP  = sOPW + 162;
    int b = blockIdx.y, c = blockIdx.x, l0 = c*256, t = threadIdx.x;
    for (int idx = t; idx < 18*256; idx += 288){
        int dd = idx >> 8, i = idx & 255;
        sDT[dd*257+i] = g_dt[((size_t)(b*18+dd))*LSEQ + l0 + i];
        sXI[dd*257+i] = g_xi[((size_t)(b*18+dd))*LSEQ + l0 + i];
    }
    for (int idx = t; idx < 16*256; idx += 288){
        int ss = idx >> 8, i = idx & 255;
        sB[ss*257+i] = g_Bsc[((size_t)(b*16+ss))*LSEQ + l0 + i];
        sC[ss*257+i] = g_Csc[((size_t)(b*16+ss))*LSEQ + l0 + i];
    }
    if (t < 162) sOPW[t] = opw[t];
    if (t < 18)  sDP[t]  = Dp[t];
    __syncthreads();

    int d = t / 16, s = t % 16;
    float a = -expf(Alog[d*16+s]);
    float h = g_hinit[(b*64+c)*288 + t];
    for (int i = 0; i < 256; i++){
        float dt = sDT[d*257+i];
        float da = __expf(dt*a);
        h = da*h + dt*sB[s*257+i]*sXI[d*257+i];
        float v = h * sC[s*257+i];
        v += __shfl_xor_sync(0xffffffffu, v, 1);
        v += __shfl_xor_sync(0xffffffffu, v, 2);
        v += __shfl_xor_sync(0xffffffffu, v, 4);
        v += __shfl_xor_sync(0xffffffffu, v, 8);
        if ((t & 15) == 0) sYS[d*257+i] = v;
    }
    __syncthreads();

    if (t < 256){
        int l = l0 + t;
        float wgt = fmaxf(softplusf(altho[0]), 0.01f);
        float ym[9];
        #pragma unroll
        for (int m = 0; m < 9; m++) ym[m] = 0.f;
        #pragma unroll
        for (int dd = 0; dd < 18; dd++){
            float yv = (sYS[dd*257+t] + sDP[dd]*sXI[dd*257+t]) * g_gate[((size_t)(b*18+dd))*LSEQ + l];
            #pragma unroll
            for (int m = 0; m < 9; m++) ym[m] += yv * sOPW[m*18+dd];
        }
        int tt = l & 1, r = l >> 1;
        int w = r & 127, h2 = r >> 7;
        int pix = (h2*2 + tt)*128 + w;
        #pragma unroll
        for (int m = 0; m < 9; m++){
            float py = wgt*ym[m] + g_ynew[((size_t)(b*9+m))*HWp + pix];
            py = fminf(fmaxf(py, 0.f), 127.f);
            g_py[((size_t)(b*9+m))*HWp + pix] = py;
        }
    }
}

// ---------------- deformable gather + contraction + GN stats ----------------
// Gather: warp <-> pixels (16 each), lanes <-> channels: fully coalesced LDG
// (1 line per request). sVal row stride 129 -> STS bank (c+pix)&31 conflict-free.
// Compute: scalar v LDS + register pack (v,v) + LDS.128 weight-pair broadcasts
// + 16 FFMA2 per ci (halved FFMA pipe vs scalar, no extra LDS bytes).
#define SVS 129
#define DEF_SMEM ((64*SVS + 64*64)*4)
__global__ void __launch_bounds__(256) kDeform(const float* __restrict__ dscb){
    extern __shared__ float sm[];
    float* sVal = sm;            // [ci][pix], stride SVS
    float* sW   = sm + 64*SVS;   // [ci][co]
    int i = blockIdx.x, b = blockIdx.y, t = threadIdx.x;
    int coq = t >> 5, lq = t & 31;
    int wid = t >> 5, lane = t & 31;

    u64 acc2[4][4];
    #pragma unroll
    for (int a = 0; a < 4; a++)
        #pragma unroll
        for (int p = 0; p < 4; p++) acc2[a][p] = 0ULL;

    for (int k = 0; k < 9; k++){
        #pragma unroll
        for (int r = 0; r < 16; r++) sW[t + 256*r] = g_wT[k*4096 + t + 256*r];

        // coalesced gather: warp wid handles pixels wid*16 .. wid*16+15
        int p0 = wid*16;
        #pragma unroll
        for (int pp = 0; pp < 16; pp++){
            int j = p0 + pp;
            float pyv = g_py[((size_t)(b*9+k))*HWp + i*128 + j];
            float fy0 = floorf(pyv);
            int y0 = (int)fy0;
            float wy = pyv - fy0;
            float wy0 = 1.f - wy;
            int y1 = min(y0 + 1, 127);
            int xc = min(max(j + k - 4, 0), 127);
            const float* base0 = &g_xT[((size_t)b*HWp + y0*128 + xc)*64];
            const float* base1 = &g_xT[((size_t)b*HWp + y1*128 + xc)*64];
            float aL = base0[lane],    aH = base0[lane+32];
            float bL = base1[lane],    bH = base1[lane+32];
            sVal[lane*SVS + j]      = aL*wy0 + bL*wy;
            sVal[(lane+32)*SVS + j] = aH*wy0 + bH*wy;
        }
        __syncthreads();

        #pragma unroll 2
        for (int ci = 0; ci < 64; ci++){
            const float* vr = &sVal[ci*SVS + lq];
            u64 vp0 = pack2(vr[0]);
            u64 vp1 = pack2(vr[32]);
            u64 vp2 = pack2(vr[64]);
            u64 vp3 = pack2(vr[96]);
            ulonglong2 wa = *(const ulonglong2*)&sW[ci*64 + coq*8];
            ulonglong2 wb = *(const ulonglong2*)&sW[ci*64 + coq*8 + 4];
            fma2(acc2[0][0], wa.x, vp0); fma2(acc2[0][1], wa.y, vp0);
            fma2(acc2[0][2], wb.x, vp0); fma2(acc2[0][3], wb.y, vp0);
            fma2(acc2[1][0], wa.x, vp1); fma2(acc2[1][1], wa.y, vp1);
            fma2(acc2[1][2], wb.x, vp1); fma2(acc2[1][3], wb.y, vp1);
            fma2(acc2[2][0], wa.x, vp2); fma2(acc2[2][1], wa.y, vp2);
            fma2(acc2[2][2], wb.x, vp2); fma2(acc2[2][3], wb.y, vp2);
            fma2(acc2[3][0], wa.x, vp3); fma2(acc2[3][1], wa.y, vp3);
            fma2(acc2[3][2], wb.x, vp3); fma2(acc2[3][3], wb.y, vp3);
        }
        __syncthreads();
    }

    float gs[2] = {0.f, 0.f}, gss[2] = {0.f, 0.f};
    #pragma unroll
    for (int p = 0; p < 4; p++){
        int co0 = coq*8 + 2*p, co1 = co0 + 1;
        float b0 = dscb[co0], b1 = dscb[co1];
        int gg = p >> 1;
        #pragma unroll
        for (int jj = 0; jj < 4; jj++){
            float2 v = unpack2(acc2[jj][p]);
            float va = v.x + b0, vb = v.y + b1;
            size_t pix = (size_t)i*128 + lq + 32*jj;
            g_outraw[((size_t)(b*64+co0))*HWp + pix] = va;
            g_outraw[((size_t)(b*64+co1))*HWp + pix] = vb;
            gs[gg] += va + vb; gss[gg] += va*va + vb*vb;
        }
    }
    #pragma unroll
    for (int gg = 0; gg < 2; gg++){
        float s = gs[gg], ss = gss[gg];
        #pragma unroll
        for (int m = 16; m > 0; m >>= 1){
            s  += __shfl_xor_sync(0xffffffffu, s,  m);
            ss += __shfl_xor_sync(0xffffffffu, ss, m);
        }
        if (lq == 0){
            atomicAdd(&g_fstats[(b*16 + coq*2 + gg)*2    ], s);
            atomicAdd(&g_fstats[(b*16 + coq*2 + gg)*2 + 1], ss);
        }
    }
}

// ---------------- final GN ----------------
__global__ void kFinalGN(const float* __restrict__ gng, const float* __restrict__ gnb,
                         float* __restrict__ out){
    int idx = blockIdx.x*256 + threadIdx.x;
    int b = idx >> 20;
    int c = (idx >> 14) & 63;
    int g = c >> 2;
    float s  = g_fstats[(b*16+g)*2];
    float ss = g_fstats[(b*16+g)*2+1];
    float mu = s * (1.f/65536.f);
    float var = ss * (1.f/65536.f) - mu*mu;
    float rs = rsqrtf(var + 1e-5f);
    out[idx] = (g_outraw[idx] - mu)*rs*gng[c] + gnb[c];
}

extern "C" void kernel_launch(void* const* d_in, const int* in_sizes, int n_in,
                              void* d_out, int out_size){
    const float* x     = (const float*)d_in[0];
    const float* offw  = (const float*)d_in[1];
    const float* offb  = (const float*)d_in[2];
    const float* gnog  = (const float*)d_in[3];
    const float* gnob  = (const float*)d_in[4];
    const float* altho = (const float*)d_in[5];
    const float* ipw   = (const float*)d_in[6];
    const float* cw    = (const float*)d_in[7];
    const float* cb    = (const float*)d_in[8];
    const float* xpw   = (const float*)d_in[9];
    const float* dtw   = (const float*)d_in[10];
    const float* dtb   = (const float*)d_in[11];
    const float* Alog  = (const float*)d_in[12];
    const float* Dp    = (const float*)d_in[13];
    const float* opw   = (const float*)d_in[14];
    const float* dscw  = (const float*)d_in[15];
    const float* dscb  = (const float*)d_in[16];
    const float* gng   = (const float*)d_in[17];
    const float* gnb   = (const float*)d_in[18];
    float* out = (float*)d_out;

    cudaFuncSetAttribute(kConv,   cudaFuncAttributeMaxDynamicSharedMemorySize, CONV_SMEM);
    cudaFuncSetAttribute(kScan1,  cudaFuncAttributeMaxDynamicSharedMemorySize, SCAN1_SMEM);
    cudaFuncSetAttribute(kScan3,  cudaFuncAttributeMaxDynamicSharedMemorySize, SCAN3_SMEM);
    cudaFuncSetAttribute(kDeform, cudaFuncAttributeMaxDynamicSharedMemorySize, DEF_SMEM);

    kZero<<<1, 128>>>();
    kTranspose<<<dim3(512, 2, 4), dim3(32, 8)>>>(x);
    kPrepW<<<144, 256>>>(dscw);
    kConv<<<dim3(64, 4), 320, CONV_SMEM>>>(x, offw, offb);
    kFinishOff<<<dim3(64, 4), 256>>>(gnog, gnob);
    kFrontEnd<<<dim3(64, 4), 256>>>(ipw, cw, cb, xpw, dtw, dtb);
    kScan1<<<dim3(64, 4), 288, SCAN1_SMEM>>>(Alog);
    kScan2<<<4, 288>>>();
    kScan3<<<dim3(64, 4), 288, SCAN3_SMEM>>>(Alog, Dp, opw, altho);
    kDeform<<<dim3(128, 4), 256, DEF_SMEM>>>(dscb);
    kFinalGN<<<16384, 256>>>(gng, gnb, out);
}

// round 6
// speedup vs baseline: 1.9290x; 1.0526x over previous
#include <cuda_runtime.h>
#include <math.h>

#define Bn   4
#define HWp  16384
#define LSEQ 16384

// ---------------- tf32 mma helpers ----------------
__device__ __forceinline__ unsigned tf32cvt(float v){
    unsigned r; asm("cvt.rna.tf32.f32 %0, %1;" : "=r"(r) : "f"(v)); return r;
}
__device__ __forceinline__ void mma_tf32(float* d, unsigned a0, unsigned a1, unsigned a2, unsigned a3,
                                         unsigned b0, unsigned b1){
    asm("mma.sync.aligned.m16n8k8.row.col.f32.tf32.tf32.f32 "
        "{%0,%1,%2,%3}, {%4,%5,%6,%7}, {%8,%9}, {%0,%1,%2,%3};"
        : "+f"(d[0]), "+f"(d[1]), "+f"(d[2]), "+f"(d[3])
        : "r"(a0), "r"(a1), "r"(a2), "r"(a3), "r"(b0), "r"(b1));
}

// ---------------- scratch ----------------
__device__ float g_xT[Bn*HWp*64];        // [b][pix][c]
__device__ float g_rawoff[Bn*10*HWp];    // offset conv out, [b][co][pix]
__device__ float g_ostats[Bn*5*2];
__device__ float g_seq[Bn*9*LSEQ];       // [b][m][l]
__device__ float g_ynew[Bn*9*HWp];       // [b][k][pix]
__device__ float g_dt[Bn*18*LSEQ];
__device__ float g_xi[Bn*18*LSEQ];
__device__ float g_gate[Bn*18*LSEQ];     // silu(z)
__device__ float g_Bsc[Bn*16*LSEQ];
__device__ float g_Csc[Bn*16*LSEQ];
__device__ float g_P[Bn*64*288];
__device__ float g_Q[Bn*64*288];
__device__ float g_hinit[Bn*64*288];
__device__ float g_py[Bn*9*HWp];         // [b][k][pix]
__device__ unsigned g_wA[9*64*64];       // [k][co][ci], tf32 bit patterns
__device__ float g_outraw[Bn*64*HWp];
__device__ float g_fstats[Bn*16*2];

__device__ __forceinline__ float softplusf(float x){
    return x > 20.f ? x : log1pf(expf(x));
}
__device__ __forceinline__ float siluf(float x){
    return x / (1.f + expf(-x));
}

// ---------------- zero stats ----------------
__global__ void kZero(){
    int t = threadIdx.x;
    if (t < 40)  g_ostats[t] = 0.f;
    if (t < 128) g_fstats[t] = 0.f;
}

// ---------------- transpose x ----------------
__global__ void kTranspose(const float* __restrict__ x){
    __shared__ float tile[32][33];
    int b = blockIdx.z, c0 = blockIdx.y*32, p0 = blockIdx.x*32;
    for (int i = threadIdx.y; i < 32; i += 8)
        tile[i][threadIdx.x] = x[(size_t)(b*64 + c0 + i)*HWp + p0 + threadIdx.x];
    __syncthreads();
    for (int i = threadIdx.y; i < 32; i += 8)
        g_xT[(size_t)(b*HWp + p0 + i)*64 + c0 + threadIdx.x] = tile[threadIdx.x][i];
}

// ---------------- weight prep: [k][co][ci] tf32 ----------------
__global__ void kPrepW(const float* __restrict__ dscw){
    int idx = blockIdx.x*256 + threadIdx.x;
    if (idx >= 9*64*64) return;
    int k = idx >> 12; int r = idx & 4095;
    int co = r >> 6;  int ci = r & 63;
    g_wA[idx] = tf32cvt(dscw[(co*64 + ci)*9 + k]);
}

// ---------------- offset conv 3x3 64->10, one row per block + GN stats ----------------
#define CONV_SMEM ((16*3*132 + 5760)*4)
__global__ void __launch_bounds__(320) kConv(const float* __restrict__ x,
                                             const float* __restrict__ offw,
                                             const float* __restrict__ offb){
    extern __shared__ float sm[];
    float* xs = sm;            // [c][r][ww], stride 132
    float* sW = sm + 16*3*132; // offw direct copy
    int h = blockIdx.x, b = blockIdx.y, tid = threadIdx.x;
    int wt = tid & 31, co = tid >> 5;
    int w0 = wt*4;

    for (int idx = tid; idx < 5760; idx += 320) sW[idx] = offw[idx];

    float acc[4];
    float bv = offb[co];
    #pragma unroll
    for (int i = 0; i < 4; i++) acc[i] = bv;

    for (int cc = 0; cc < 4; cc++){
        int c0 = cc*16;
        __syncthreads();
        for (int idx = tid; idx < 16*3*130; idx += 320){
            int c = idx / 390;
            int rem = idx - c*390;
            int rr = rem / 130;
            int ww = rem - rr*130;
            int gh = h - 1 + rr, gw = ww - 1;
            float v = 0.f;
            if (gh >= 0 && gh < 128 && gw >= 0 && gw < 128)
                v = x[((size_t)(b*64 + c0 + c)*128 + gh)*128 + gw];
            xs[(c*3 + rr)*132 + ww] = v;
        }
        __syncthreads();
        for (int c = 0; c < 16; c++){
            #pragma unroll
            for (int dy = 0; dy < 3; dy++){
                const float* wp = &sW[(co*64 + c0 + c)*9 + dy*3];
                float wA = wp[0], wB = wp[1], wC = wp[2];
                const float* row = &xs[(c*3 + dy)*132];
                float4 vA = *(const float4*)&row[w0];
                float4 vB = *(const float4*)&row[w0+4];
                float v[6] = {vA.x,vA.y,vA.z,vA.w,vB.x,vB.y};
                #pragma unroll
                for (int i = 0; i < 4; i++)
                    acc[i] += wA*v[i] + wB*v[i+1] + wC*v[i+2];
            }
        }
    }

    float s = 0.f, ss = 0.f;
    #pragma unroll
    for (int i = 0; i < 4; i++){ s += acc[i]; ss += acc[i]*acc[i]; }
    *(float4*)&g_rawoff[((size_t)(b*10+co))*HWp + h*128 + w0] = *(float4*)acc;
    #pragma unroll
    for (int m = 16; m > 0; m >>= 1){
        s  += __shfl_xor_sync(0xffffffffu, s,  m);
        ss += __shfl_xor_sync(0xffffffffu, ss, m);
    }
    if (wt == 0){
        atomicAdd(&g_ostats[(b*5 + (co>>1))*2    ], s);
        atomicAdd(&g_ostats[(b*5 + (co>>1))*2 + 1], ss);
    }
}

// ---------------- GN finalize + tanh + cumsum + seq + y_new ----------------
__global__ void kFinishOff(const float* __restrict__ gnog, const float* __restrict__ gnob){
    __shared__ float sMu[5], sRs[5];
    int b = blockIdx.y, tid = threadIdx.x;
    int p = blockIdx.x*256 + tid;
    if (tid < 5){
        float s  = g_ostats[(b*5+tid)*2];
        float ss = g_ostats[(b*5+tid)*2+1];
        float mu = s * (1.f/32768.f);
        float var = ss * (1.f/32768.f) - mu*mu;
        sMu[tid] = mu;
        sRs[tid] = rsqrtf(var + 1e-5f);
    }
    __syncthreads();

    float tv[9];
    #pragma unroll
    for (int c = 0; c < 9; c++){
        float raw = g_rawoff[((size_t)(b*10+c))*HWp + p];
        float xn = (raw - sMu[c>>1]) * sRs[c>>1] * gnog[c] + gnob[c];
        tv[c] = tanhf(xn);
    }
    float cum[9];
    cum[4] = 0.f;
    cum[5] = tv[5]; cum[6] = cum[5]+tv[6]; cum[7] = cum[6]+tv[7]; cum[8] = cum[7]+tv[8];
    cum[3] = tv[3]; cum[2] = cum[3]+tv[2]; cum[1] = cum[2]+tv[1]; cum[0] = cum[1]+tv[0];

    int h = p >> 7, w = p & 127;
    #pragma unroll
    for (int k = 0; k < 9; k++)
        g_ynew[((size_t)(b*9+k))*HWp + p] = (float)h + cum[k];

    int l = ((h>>1)*128 + w)*2 + (h&1);
    #pragma unroll
    for (int m = 0; m < 9; m++)
        g_seq[((size_t)(b*9+m))*LSEQ + l] = tv[m];
}

// ---------------- mamba front-end ----------------
__global__ void kFrontEnd(const float* __restrict__ ipw, const float* __restrict__ cw,
                          const float* __restrict__ cb,  const float* __restrict__ xpw,
                          const float* __restrict__ dtw, const float* __restrict__ dtb){
    __shared__ float sXP[259*19];
    __shared__ float sIPW[324], sXPW[594], sCW[72], sCB[18], sDTW[18], sDTB[18];
    int b = blockIdx.y, l0 = blockIdx.x*256, tid = threadIdx.x;
    int l = l0 + tid;

    for (int idx = tid; idx < 324; idx += 256) sIPW[idx] = ipw[idx];
    for (int idx = tid; idx < 594; idx += 256) sXPW[idx] = xpw[idx];
    if (tid < 72) sCW[tid] = cw[tid];
    if (tid < 18){ sCB[tid] = cb[tid]; sDTW[tid] = dtw[tid]; sDTB[tid] = dtb[tid]; }
    __syncthreads();

    float sq[9];
    #pragma unroll
    for (int m = 0; m < 9; m++) sq[m] = g_seq[((size_t)(b*9+m))*LSEQ + l];
    #pragma unroll
    for (int n = 0; n < 18; n++){
        float v = 0.f;
        #pragma unroll
        for (int m = 0; m < 9; m++) v += sq[m]*sIPW[n*9+m];
        sXP[(tid+3)*19 + n] = v;
    }
    #pragma unroll
    for (int n = 0; n < 18; n++){
        float z = 0.f;
        #pragma unroll
        for (int m = 0; m < 9; m++) z += sq[m]*sIPW[(18+n)*9+m];
        g_gate[((size_t)(b*18+n))*LSEQ + l] = siluf(z);
    }
    if (tid < 3){
        int l2 = l0 - 3 + tid;
        if (l2 >= 0){
            float s2[9];
            #pragma unroll
            for (int m = 0; m < 9; m++) s2[m] = g_seq[((size_t)(b*9+m))*LSEQ + l2];
            #pragma unroll
            for (int n = 0; n < 18; n++){
                float v = 0.f;
                #pragma unroll
                for (int m = 0; m < 9; m++) v += s2[m]*sIPW[n*9+m];
                sXP[tid*19 + n] = v;
            }
        } else {
            #pragma unroll
            for (int n = 0; n < 18; n++) sXP[tid*19 + n] = 0.f;
        }
    }
    __syncthreads();

    float xi[18];
    #pragma unroll
    for (int d = 0; d < 18; d++){
        float xc = sCB[d];
        #pragma unroll
        for (int j = 0; j < 4; j++) xc += sCW[d*4+j]*sXP[(tid+j)*19 + d];
        xi[d] = siluf(xc);
    }
    float dtr = 0.f;
    #pragma unroll
    for (int d = 0; d < 18; d++) dtr += xi[d]*sXPW[d];
    #pragma unroll
    for (int s = 0; s < 16; s++){
        float bv = 0.f, cv = 0.f;
        #pragma unroll
        for (int d = 0; d < 18; d++){
            bv += xi[d]*sXPW[(1+s)*18 + d];
            cv += xi[d]*sXPW[(17+s)*18 + d];
        }
        g_Bsc[((size_t)(b*16+s))*LSEQ + l] = bv;
        g_Csc[((size_t)(b*16+s))*LSEQ + l] = cv;
    }
    #pragma unroll
    for (int d = 0; d < 18; d++){
        float a = dtr*sDTW[d] + sDTB[d];
        g_dt[((size_t)(b*18+d))*LSEQ + l] = softplusf(a);
        g_xi[((size_t)(b*18+d))*LSEQ + l] = xi[d];
    }
}

// ---------------- scan pass1: per-chunk (P,Q) ----------------
#define SCAN1_SMEM (52*257*4)
__global__ void kScan1(const float* __restrict__ Alog){
    extern __shared__ float sm[];
    float* sDT = sm;
    float* sXI = sm + 18*257;
    float* sB  = sm + 36*257;
    int b = blockIdx.y, c = blockIdx.x, l0 = c*256, t = threadIdx.x;
    for (int idx = t; idx < 18*256; idx += 288){
        int dd = idx >> 8, i = idx & 255;
        sDT[dd*257+i] = g_dt[((size_t)(b*18+dd))*LSEQ + l0 + i];
        sXI[dd*257+i] = g_xi[((size_t)(b*18+dd))*LSEQ + l0 + i];
    }
    for (int idx = t; idx < 16*256; idx += 288){
        int ss = idx >> 8, i = idx & 255;
        sB[ss*257+i] = g_Bsc[((size_t)(b*16+ss))*LSEQ + l0 + i];
    }
    __syncthreads();
    int d = t / 16, s = t % 16;
    float a = -expf(Alog[d*16+s]);
    float p = 1.f, q = 0.f;
    for (int i = 0; i < 256; i++){
        float dt = sDT[d*257+i];
        float da = __expf(dt*a);
        q = da*q + dt*sB[s*257+i]*sXI[d*257+i];
        p *= da;
    }
    g_P[(b*64+c)*288 + t] = p;
    g_Q[(b*64+c)*288 + t] = q;
}

// ---------------- scan pass2: serial carry ----------------
__global__ void kScan2(){
    int b = blockIdx.x, t = threadIdx.x;
    float h = 0.f;
    for (int c = 0; c < 64; c++){
        g_hinit[(b*64+c)*288 + t] = h;
        h = g_P[(b*64+c)*288 + t]*h + g_Q[(b*64+c)*288 + t];
    }
}

// ---------------- scan pass3: replay + output + py ----------------
#define SCAN3_SMEM ((86*257 + 162 + 18)*4)
__global__ void kScan3(const float* __restrict__ Alog, const float* __restrict__ Dp,
                       const float* __restrict__ opw,  const float* __restrict__ altho){
    extern __shared__ float sm[];
    float* sDT = sm;
    float* sXI = sm + 18*257;
    float* sB  = sm + 36*257;
    float* sC  = sm + 52*257;
    float* sYS = sm + 68*257;
    float* sOPW = sm + 86*257;
    float* sDP  = sOPW + 162;
    int b = blockIdx.y, c = blockIdx.x, l0 = c*256, t = threadIdx.x;
    for (int idx = t; idx < 18*256; idx += 288){
        int dd = idx >> 8, i = idx & 255;
        sDT[dd*257+i] = g_dt[((size_t)(b*18+dd))*LSEQ + l0 + i];
        sXI[dd*257+i] = g_xi[((size_t)(b*18+dd))*LSEQ + l0 + i];
    }
    for (int idx = t; idx < 16*256; idx += 288){
        int ss = idx >> 8, i = idx & 255;
        sB[ss*257+i] = g_Bsc[((size_t)(b*16+ss))*LSEQ + l0 + i];
        sC[ss*257+i] = g_Csc[((size_t)(b*16+ss))*LSEQ + l0 + i];
    }
    if (t < 162) sOPW[t] = opw[t];
    if (t < 18)  sDP[t]  = Dp[t];
    __syncthreads();

    int d = t / 16, s = t % 16;
    float a = -expf(Alog[d*16+s]);
    float h = g_hinit[(b*64+c)*288 + t];
    for (int i = 0; i < 256; i++){
        float dt = sDT[d*257+i];
        float da = __expf(dt*a);
        h = da*h + dt*sB[s*257+i]*sXI[d*257+i];
        float v = h * sC[s*257+i];
        v += __shfl_xor_sync(0xffffffffu, v, 1);
        v += __shfl_xor_sync(0xffffffffu, v, 2);
        v += __shfl_xor_sync(0xffffffffu, v, 4);
        v += __shfl_xor_sync(0xffffffffu, v, 8);
        if ((t & 15) == 0) sYS[d*257+i] = v;
    }
    __syncthreads();

    if (t < 256){
        int l = l0 + t;
        float wgt = fmaxf(softplusf(altho[0]), 0.01f);
        float ym[9];
        #pragma unroll
        for (int m = 0; m < 9; m++) ym[m] = 0.f;
        #pragma unroll
        for (int dd = 0; dd < 18; dd++){
            float yv = (sYS[dd*257+t] + sDP[dd]*sXI[dd*257+t]) * g_gate[((size_t)(b*18+dd))*LSEQ + l];
            #pragma unroll
            for (int m = 0; m < 9; m++) ym[m] += yv * sOPW[m*18+dd];
        }
        int tt = l & 1, r = l >> 1;
        int w = r & 127, h2 = r >> 7;
        int pix = (h2*2 + tt)*128 + w;
        #pragma unroll
        for (int m = 0; m < 9; m++){
            float py = wgt*ym[m] + g_ynew[((size_t)(b*9+m))*HWp + pix];
            py = fminf(fmaxf(py, 0.f), 127.f);
            g_py[((size_t)(b*9+m))*HWp + pix] = py;
        }
    }
}

// ---------------- deformable gather + tf32 tensor-core contraction + GN stats ----------------
// Block = (b, row i). GEMM: O[64co][128pix] += A[co][ci] * V[ci][pix] over 9 k-rounds.
// A smem [co][ci] stride 68; V smem [pix][ci] stride 68 (both conflict-free for
// m16n8k8 fragment loads; gather STS also conflict-free: bank=(4j+lane)%32).
// Warp w: co tile (w&3)*16, pix tile (w>>2)*64. 8 ksteps x 8 ntiles per k-round.
#define DEF_SMEM ((128*68 + 64*68)*4)
__global__ void __launch_bounds__(256) kDeform(const float* __restrict__ dscb){
    extern __shared__ unsigned smu[];
    unsigned* sV = smu;             // [pix][ci] stride 68
    unsigned* sA = smu + 128*68;    // [co][ci] stride 68
    int i = blockIdx.x, b = blockIdx.y, t = threadIdx.x;
    int wid = t >> 5, lane = t & 31;
    int gID = lane >> 2, tig = lane & 3;
    int ct = (wid & 3)*16;
    int pt = (wid >> 2)*64;

    float acc[8][4];
    #pragma unroll
    for (int nt = 0; nt < 8; nt++)
        #pragma unroll
        for (int p = 0; p < 4; p++) acc[nt][p] = 0.f;

    for (int k = 0; k < 9; k++){
        // load A tile [64co][64ci] -> stride 68
        #pragma unroll
        for (int r = 0; r < 16; r++){
            int idx = t + 256*r;
            int co = idx >> 6, ci = idx & 63;
            sA[co*68 + ci] = g_wA[k*4096 + idx];
        }
        // coalesced gather: warp wid handles pixels wid*16 .. +15, lanes = channels
        int p0 = wid*16;
        #pragma unroll
        for (int pp = 0; pp < 16; pp++){
            int j = p0 + pp;
            float pyv = g_py[((size_t)(b*9+k))*HWp + i*128 + j];
            float fy0 = floorf(pyv);
            int y0 = (int)fy0;
            float wy = pyv - fy0;
            float wy0 = 1.f - wy;
            int y1 = min(y0 + 1, 127);
            int xc = min(max(j + k - 4, 0), 127);
            const float* base0 = &g_xT[((size_t)b*HWp + y0*128 + xc)*64];
            const float* base1 = &g_xT[((size_t)b*HWp + y1*128 + xc)*64];
            float vL = base0[lane]*wy0    + base1[lane]*wy;
            float vH = base0[lane+32]*wy0 + base1[lane+32]*wy;
            sV[j*68 + lane]      = tf32cvt(vL);
            sV[j*68 + lane + 32] = tf32cvt(vH);
        }
        __syncthreads();

        #pragma unroll
        for (int ks = 0; ks < 8; ks++){
            int kk = ks*8;
            unsigned a0 = sA[(ct+gID)*68   + kk + tig];
            unsigned a1 = sA[(ct+gID+8)*68 + kk + tig];
            unsigned a2 = sA[(ct+gID)*68   + kk + tig + 4];
            unsigned a3 = sA[(ct+gID+8)*68 + kk + tig + 4];
            #pragma unroll
            for (int nt = 0; nt < 8; nt++){
                int n0 = pt + nt*8;
                unsigned b0 = sV[(n0+gID)*68 + kk + tig];
                unsigned b1 = sV[(n0+gID)*68 + kk + tig + 4];
                mma_tf32(acc[nt], a0, a1, a2, a3, b0, b1);
            }
        }
        __syncthreads();
    }

    // epilogue: bias + store + GN partial stats
    int co0 = ct + gID, co1 = ct + gID + 8;
    float bias0 = dscb[co0], bias1 = dscb[co1];
    float s0 = 0.f, ss0 = 0.f, s1 = 0.f, ss1 = 0.f;
    #pragma unroll
    for (int nt = 0; nt < 8; nt++){
        float c0 = acc[nt][0] + bias0, c1 = acc[nt][1] + bias0;
        float c2 = acc[nt][2] + bias1, c3 = acc[nt][3] + bias1;
        size_t pix = (size_t)i*128 + pt + nt*8 + tig*2;
        *(float2*)&g_outraw[((size_t)(b*64+co0))*HWp + pix] = make_float2(c0, c1);
        *(float2*)&g_outraw[((size_t)(b*64+co1))*HWp + pix] = make_float2(c2, c3);
        s0 += c0 + c1; ss0 += c0*c0 + c1*c1;
        s1 += c2 + c3; ss1 += c2*c2 + c3*c3;
    }
    // reduce within 16-lane halves: lanes 0-15 cover co ct..ct+3 (one GN group),
    // lanes 16-31 cover ct+4..ct+7 (next group); s1 rows are +8 -> +2 groups.
    #pragma unroll
    for (int m = 1; m <= 8; m <<= 1){
        s0  += __shfl_xor_sync(0xffffffffu, s0,  m);
        ss0 += __shfl_xor_sync(0xffffffffu, ss0, m);
        s1  += __shfl_xor_sync(0xffffffffu, s1,  m);
        ss1 += __shfl_xor_sync(0xffffffffu, ss1, m);
    }
    if ((lane & 15) == 0){
        int g0 = (ct >> 2) + (lane >> 4);
        atomicAdd(&g_fstats[(b*16 + g0)*2    ], s0);
        atomicAdd(&g_fstats[(b*16 + g0)*2 + 1], ss0);
        atomicAdd(&g_fstats[(b*16 + g0 + 2)*2    ], s1);
        atomicAdd(&g_fstats[(b*16 + g0 + 2)*2 + 1], ss1);
    }
}

// ---------------- final GN ----------------
__global__ void kFinalGN(const float* __restrict__ gng, const float* __restrict__ gnb,
                         float* __restrict__ out){
    int idx = blockIdx.x*256 + threadIdx.x;
    int b = idx >> 20;
    int c = (idx >> 14) & 63;
    int g = c >> 2;
    float s  = g_fstats[(b*16+g)*2];
    float ss = g_fstats[(b*16+g)*2+1];
    float mu = s * (1.f/65536.f);
    float var = ss * (1.f/65536.f) - mu*mu;
    float rs = rsqrtf(var + 1e-5f);
    out[idx] = (g_outraw[idx] - mu)*rs*gng[c] + gnb[c];
}

extern "C" void kernel_launch(void* const* d_in, const int* in_sizes, int n_in,
                              void* d_out, int out_size){
    const float* x     = (const float*)d_in[0];
    const float* offw  = (const float*)d_in[1];
    const float* offb  = (const float*)d_in[2];
    const float* gnog  = (const float*)d_in[3];
    const float* gnob  = (const float*)d_in[4];
    const float* altho = (const float*)d_in[5];
    const float* ipw   = (const float*)d_in[6];
    const float* cw    = (const float*)d_in[7];
    const float* cb    = (const float*)d_in[8];
    const float* xpw   = (const float*)d_in[9];
    const float* dtw   = (const float*)d_in[10];
    const float* dtb   = (const float*)d_in[11];
    const float* Alog  = (const float*)d_in[12];
    const float* Dp    = (const float*)d_in[13];
    const float* opw   = (const float*)d_in[14];
    const float* dscw  = (const float*)d_in[15];
    const float* dscb  = (const float*)d_in[16];
    const float* gng   = (const float*)d_in[17];
    const float* gnb   = (const float*)d_in[18];
    float* out = (float*)d_out;

    cudaFuncSetAttribute(kConv,   cudaFuncAttributeMaxDynamicSharedMemorySize, CONV_SMEM);
    cudaFuncSetAttribute(kScan1,  cudaFuncAttributeMaxDynamicSharedMemorySize, SCAN1_SMEM);
    cudaFuncSetAttribute(kScan3,  cudaFuncAttributeMaxDynamicSharedMemorySize, SCAN3_SMEM);
    cudaFuncSetAttribute(kDeform, cudaFuncAttributeMaxDynamicSharedMemorySize, DEF_SMEM);

    kZero<<<1, 128>>>();
    kTranspose<<<dim3(512, 2, 4), dim3(32, 8)>>>(x);
    kPrepW<<<144, 256>>>(dscw);
    kConv<<<dim3(128, 4), 320, CONV_SMEM>>>(x, offw, offb);
    kFinishOff<<<dim3(64, 4), 256>>>(gnog, gnob);
    kFrontEnd<<<dim3(64, 4), 256>>>(ipw, cw, cb, xpw, dtw, dtb);
    kScan1<<<dim3(64, 4), 288, SCAN1_SMEM>>>(Alog);
    kScan2<<<4, 288>>>();
    kScan3<<<dim3(64, 4), 288, SCAN3_SMEM>>>(Alog, Dp, opw, altho);
    kDeform<<<dim3(128, 4), 256, DEF_SMEM>>>(dscb);
    kFinalGN<<<16384, 256>>>(gng, gnb, out);
}

// round 7
// speedup vs baseline: 2.1908x; 1.1357x over previous
#include <cuda_runtime.h>
#include <math.h>

#define Bn   4
#define HWp  16384
#define LSEQ 16384

// ---------------- tf32 mma helpers ----------------
__device__ __forceinline__ unsigned tf32cvt(float v){
    unsigned r; asm("cvt.rna.tf32.f32 %0, %1;" : "=r"(r) : "f"(v)); return r;
}
__device__ __forceinline__ void mma_tf32(float* d, unsigned a0, unsigned a1, unsigned a2, unsigned a3,
                                         unsigned b0, unsigned b1){
    asm("mma.sync.aligned.m16n8k8.row.col.f32.tf32.tf32.f32 "
        "{%0,%1,%2,%3}, {%4,%5,%6,%7}, {%8,%9}, {%0,%1,%2,%3};"
        : "+f"(d[0]), "+f"(d[1]), "+f"(d[2]), "+f"(d[3])
        : "r"(a0), "r"(a1), "r"(a2), "r"(a3), "r"(b0), "r"(b1));
}

// ---------------- scratch ----------------
__device__ float g_xT[Bn*HWp*64];        // [b][pix][c]
__device__ float g_rawoff[Bn*10*HWp];    // offset conv out, [b][co][pix]
__device__ float g_ostats[Bn*5*2];
__device__ float g_ynew[Bn*9*HWp];       // [b][k][pix]
__device__ float g_dt[Bn*18*LSEQ];
__device__ float g_xi[Bn*18*LSEQ];
__device__ float g_gate[Bn*18*LSEQ];     // silu(z)
__device__ float g_Bsc[Bn*16*LSEQ];
__device__ float g_Csc[Bn*16*LSEQ];
__device__ float g_P[Bn*64*288];
__device__ float g_Q[Bn*64*288];
__device__ float g_hinit[Bn*64*288];
__device__ float g_py[Bn*9*HWp];         // [b][k][pix]
__device__ unsigned g_wA[9*64*64];       // [k][co][ci], tf32 bit patterns
__device__ float g_outraw[Bn*64*HWp];
__device__ float g_fstats[Bn*16*2];

__device__ __forceinline__ float softplusf(float x){
    return x > 20.f ? x : log1pf(expf(x));
}
__device__ __forceinline__ float siluf(float x){
    return x / (1.f + expf(-x));
}

// ---------------- prep: transpose x + zero stats + weight tf32 conversion ----------------
__global__ void kPrep(const float* __restrict__ x, const float* __restrict__ dscw){
    __shared__ float tile[32][33];
    int b = blockIdx.z, c0 = blockIdx.y*32, p0 = blockIdx.x*32;
    int bid = (blockIdx.z*gridDim.y + blockIdx.y)*gridDim.x + blockIdx.x;
    int gtid = bid*256 + threadIdx.y*32 + threadIdx.x;

    if (gtid < 36864){
        int k = gtid >> 12; int r = gtid & 4095;
        int co = r >> 6;  int ci = r & 63;
        g_wA[gtid] = tf32cvt(dscw[(co*64 + ci)*9 + k]);
    }
    if (gtid >= 65536 && gtid < 65536+40)  g_ostats[gtid-65536] = 0.f;
    if (gtid >= 131072 && gtid < 131072+128) g_fstats[gtid-131072] = 0.f;

    for (int i = threadIdx.y; i < 32; i += 8)
        tile[i][threadIdx.x] = x[(size_t)(b*64 + c0 + i)*HWp + p0 + threadIdx.x];
    __syncthreads();
    for (int i = threadIdx.y; i < 32; i += 8)
        g_xT[(size_t)(b*HWp + p0 + i)*64 + c0 + threadIdx.x] = tile[threadIdx.x][i];
}

// ---------------- offset conv 3x3 64->10, register-tiled + GN stats (R5 config) ----------------
#define CONV_SMEM ((16*4*132 + 5760)*4)
__global__ void __launch_bounds__(320) kConv(const float* __restrict__ x,
                                             const float* __restrict__ offw,
                                             const float* __restrict__ offb){
    extern __shared__ float sm[];
    float* xs = sm;            // [c][r][ww], stride 132
    float* sW = sm + 16*4*132; // offw direct copy
    int hb = blockIdx.x, b = blockIdx.y, tid = threadIdx.x;
    int h0 = hb*2;
    int hh = tid & 1, wt = (tid >> 1) & 15, co = tid >> 5;
    int w0 = wt*8;

    for (int idx = tid; idx < 5760; idx += 320) sW[idx] = offw[idx];

    float acc[8];
    float bv = offb[co];
    #pragma unroll
    for (int i = 0; i < 8; i++) acc[i] = bv;

    for (int cc = 0; cc < 4; cc++){
        int c0 = cc*16;
        __syncthreads();
        for (int idx = tid; idx < 16*4*130; idx += 320){
            int c = idx / 520;
            int rem = idx - c*520;
            int rr = rem / 130;
            int ww = rem - rr*130;
            int gh = h0 - 1 + rr, gw = ww - 1;
            float v = 0.f;
            if (gh >= 0 && gh < 128 && gw >= 0 && gw < 128)
                v = x[((size_t)(b*64 + c0 + c)*128 + gh)*128 + gw];
            xs[(c*4 + rr)*132 + ww] = v;
        }
        __syncthreads();
        for (int c = 0; c < 16; c++){
            #pragma unroll
            for (int dy = 0; dy < 3; dy++){
                const float* wp = &sW[(co*64 + c0 + c)*9 + dy*3];
                float wA = wp[0], wB = wp[1], wC = wp[2];
                const float* row = &xs[(c*4 + hh + dy)*132];
                float4 vA = *(const float4*)&row[w0];
                float4 vB = *(const float4*)&row[w0+4];
                float v8 = row[w0+8], v9 = row[w0+9];
                float v[10] = {vA.x,vA.y,vA.z,vA.w,vB.x,vB.y,vB.z,vB.w,v8,v9};
                #pragma unroll
                for (int i = 0; i < 8; i++)
                    acc[i] += wA*v[i] + wB*v[i+1] + wC*v[i+2];
            }
        }
    }

    int h = h0 + hh;
    float s = 0.f, ss = 0.f;
    #pragma unroll
    for (int i = 0; i < 8; i++){
        g_rawoff[((size_t)(b*10+co))*HWp + h*128 + w0 + i] = acc[i];
        s += acc[i]; ss += acc[i]*acc[i];
    }
    #pragma unroll
    for (int m = 16; m > 0; m >>= 1){
        s  += __shfl_xor_sync(0xffffffffu, s,  m);
        ss += __shfl_xor_sync(0xffffffffu, ss, m);
    }
    if ((tid & 31) == 0){
        atomicAdd(&g_ostats[(b*5 + (co>>1))*2    ], s);
        atomicAdd(&g_ostats[(b*5 + (co>>1))*2 + 1], ss);
    }
}

// ---------------- fused: GN+tanh+cumsum+ynew -> front-end GEMVs -> scan pass1 ----------------
// block = one l-chunk (256 seq positions = pixel-row pair), 288 threads.
__device__ __forceinline__ void comp_tv(int b, int l, const float* sMu, const float* sRs,
                                        const float* __restrict__ gnog,
                                        const float* __restrict__ gnob, float* tv){
    int tt = l & 1, r = l >> 1;
    int w = r & 127, r2 = r >> 7;
    int p = (r2*2 + tt)*128 + w;
    #pragma unroll
    for (int c = 0; c < 9; c++){
        float raw = g_rawoff[((size_t)(b*10+c))*HWp + p];
        float xn = (raw - sMu[c>>1]) * sRs[c>>1] * gnog[c] + gnob[c];
        tv[c] = tanhf(xn);
    }
}

#define FUS_SMEM (19339*4)
__global__ void __launch_bounds__(288) kFused(
        const float* __restrict__ gnog, const float* __restrict__ gnob,
        const float* __restrict__ ipw,  const float* __restrict__ cw,
        const float* __restrict__ cb,   const float* __restrict__ xpw,
        const float* __restrict__ dtw,  const float* __restrict__ dtb,
        const float* __restrict__ Alog){
    extern __shared__ float sm[];
    float* sXP  = sm;            // 259*19
    float* sIPW = sm + 4921;     // 324
    float* sXPW = sm + 5245;     // 594
    float* sCW  = sm + 5839;     // 72
    float* sCB  = sm + 5911;     // 18
    float* sDTW = sm + 5929;     // 18
    float* sDTB = sm + 5947;     // 18
    float* sMu  = sm + 5965;     // 5
    float* sRs  = sm + 5970;     // 5
    float* sDT  = sm + 5975;     // 18*257
    float* sXI  = sm + 10601;    // 18*257
    float* sB   = sm + 15227;    // 16*257
    int b = blockIdx.y, c = blockIdx.x, l0 = c*256, t = threadIdx.x;

    for (int idx = t; idx < 324; idx += 288) sIPW[idx] = ipw[idx];
    for (int idx = t; idx < 594; idx += 288) sXPW[idx] = xpw[idx];
    if (t < 72) sCW[t] = cw[t];
    if (t < 18){ sCB[t] = cb[t]; sDTW[t] = dtw[t]; sDTB[t] = dtb[t]; }
    if (t < 5){
        float s  = g_ostats[(b*5+t)*2];
        float ss = g_ostats[(b*5+t)*2+1];
        float mu = s * (1.f/32768.f);
        float var = ss * (1.f/32768.f) - mu*mu;
        sMu[t] = mu;
        sRs[t] = rsqrtf(var + 1e-5f);
    }
    __syncthreads();

    if (t < 256){
        int l = l0 + t;
        float tv[9];
        comp_tv(b, l, sMu, sRs, gnog, gnob, tv);

        float cum[9];
        cum[4] = 0.f;
        cum[5] = tv[5]; cum[6] = cum[5]+tv[6]; cum[7] = cum[6]+tv[7]; cum[8] = cum[7]+tv[8];
        cum[3] = tv[3]; cum[2] = cum[3]+tv[2]; cum[1] = cum[2]+tv[1]; cum[0] = cum[1]+tv[0];

        int tt = l & 1, r = l >> 1;
        int w = r & 127, r2 = r >> 7;
        int h = r2*2 + tt, p = h*128 + w;
        #pragma unroll
        for (int k = 0; k < 9; k++)
            g_ynew[((size_t)(b*9+k))*HWp + p] = (float)h + cum[k];

        #pragma unroll
        for (int n = 0; n < 18; n++){
            float v = 0.f;
            #pragma unroll
            for (int m = 0; m < 9; m++) v += tv[m]*sIPW[n*9+m];
            sXP[(t+3)*19 + n] = v;
        }
        #pragma unroll
        for (int n = 0; n < 18; n++){
            float z = 0.f;
            #pragma unroll
            for (int m = 0; m < 9; m++) z += tv[m]*sIPW[(18+n)*9+m];
            g_gate[((size_t)(b*18+n))*LSEQ + l] = siluf(z);
        }
    } else if (t < 259){
        int bi = t - 256;
        int l2 = l0 - 3 + bi;
        if (l2 >= 0){
            float tv2[9];
            comp_tv(b, l2, sMu, sRs, gnog, gnob, tv2);
            #pragma unroll
            for (int n = 0; n < 18; n++){
                float v = 0.f;
                #pragma unroll
                for (int m = 0; m < 9; m++) v += tv2[m]*sIPW[n*9+m];
                sXP[bi*19 + n] = v;
            }
        } else {
            #pragma unroll
            for (int n = 0; n < 18; n++) sXP[bi*19 + n] = 0.f;
        }
    }
    __syncthreads();

    if (t < 256){
        int l = l0 + t;
        float xi[18];
        #pragma unroll
        for (int d = 0; d < 18; d++){
            float xc = sCB[d];
            #pragma unroll
            for (int j = 0; j < 4; j++) xc += sCW[d*4+j]*sXP[(t+j)*19 + d];
            xi[d] = siluf(xc);
        }
        float dtr = 0.f;
        #pragma unroll
        for (int d = 0; d < 18; d++) dtr += xi[d]*sXPW[d];
        #pragma unroll
        for (int s = 0; s < 16; s++){
            float bv = 0.f, cv = 0.f;
            #pragma unroll
            for (int d = 0; d < 18; d++){
                bv += xi[d]*sXPW[(1+s)*18 + d];
                cv += xi[d]*sXPW[(17+s)*18 + d];
            }
            sB[s*257 + t] = bv;
            g_Bsc[((size_t)(b*16+s))*LSEQ + l] = bv;
            g_Csc[((size_t)(b*16+s))*LSEQ + l] = cv;
        }
        #pragma unroll
        for (int d = 0; d < 18; d++){
            float a = dtr*sDTW[d] + sDTB[d];
            float dtv = softplusf(a);
            sDT[d*257 + t] = dtv;
            sXI[d*257 + t] = xi[d];
            g_dt[((size_t)(b*18+d))*LSEQ + l] = dtv;
            g_xi[((size_t)(b*18+d))*LSEQ + l] = xi[d];
        }
    }
    __syncthreads();

    // scan pass 1 over this chunk
    int d = t / 16, s = t % 16;
    float a = -expf(Alog[d*16+s]);
    float p = 1.f, q = 0.f;
    for (int i = 0; i < 256; i++){
        float dt = sDT[d*257+i];
        float da = __expf(dt*a);
        q = da*q + dt*sB[s*257+i]*sXI[d*257+i];
        p *= da;
    }
    g_P[(b*64+c)*288 + t] = p;
    g_Q[(b*64+c)*288 + t] = q;
}

// ---------------- scan pass2: serial carry ----------------
__global__ void kScan2(){
    int b = blockIdx.x, t = threadIdx.x;
    float h = 0.f;
    for (int c = 0; c < 64; c++){
        g_hinit[(b*64+c)*288 + t] = h;
        h = g_P[(b*64+c)*288 + t]*h + g_Q[(b*64+c)*288 + t];
    }
}

// ---------------- scan pass3: replay + output + py ----------------
#define SCAN3_SMEM ((86*257 + 162 + 18)*4)
__global__ void kScan3(const float* __restrict__ Alog, const float* __restrict__ Dp,
                       const float* __restrict__ opw,  const float* __restrict__ altho){
    extern __shared__ float sm[];
    float* sDT = sm;
    float* sXI = sm + 18*257;
    float* sB  = sm + 36*257;
    float* sC  = sm + 52*257;
    float* sYS = sm + 68*257;
    float* sOPW = sm + 86*257;
    float* sDP  = sOPW + 162;
    int b = blockIdx.y, c = blockIdx.x, l0 = c*256, t = threadIdx.x;
    for (int idx = t; idx < 18*256; idx += 288){
        int dd = idx >> 8, i = idx & 255;
        sDT[dd*257+i] = g_dt[((size_t)(b*18+dd))*LSEQ + l0 + i];
        sXI[dd*257+i] = g_xi[((size_t)(b*18+dd))*LSEQ + l0 + i];
    }
    for (int idx = t; idx < 16*256; idx += 288){
        int ss = idx >> 8, i = idx & 255;
        sB[ss*257+i] = g_Bsc[((size_t)(b*16+ss))*LSEQ + l0 + i];
        sC[ss*257+i] = g_Csc[((size_t)(b*16+ss))*LSEQ + l0 + i];
    }
    if (t < 162) sOPW[t] = opw[t];
    if (t < 18)  sDP[t]  = Dp[t];
    __syncthreads();

    int d = t / 16, s = t % 16;
    float a = -expf(Alog[d*16+s]);
    float h = g_hinit[(b*64+c)*288 + t];
    for (int i = 0; i < 256; i++){
        float dt = sDT[d*257+i];
        float da = __expf(dt*a);
        h = da*h + dt*sB[s*257+i]*sXI[d*257+i];
        float v = h * sC[s*257+i];
        v += __shfl_xor_sync(0xffffffffu, v, 1);
        v += __shfl_xor_sync(0xffffffffu, v, 2);
        v += __shfl_xor_sync(0xffffffffu, v, 4);
        v += __shfl_xor_sync(0xffffffffu, v, 8);
        if ((t & 15) == 0) sYS[d*257+i] = v;
    }
    __syncthreads();

    if (t < 256){
        int l = l0 + t;
        float wgt = fmaxf(softplusf(altho[0]), 0.01f);
        float ym[9];
        #pragma unroll
        for (int m = 0; m < 9; m++) ym[m] = 0.f;
        #pragma unroll
        for (int dd = 0; dd < 18; dd++){
            float yv = (sYS[dd*257+t] + sDP[dd]*sXI[dd*257+t]) * g_gate[((size_t)(b*18+dd))*LSEQ + l];
            #pragma unroll
            for (int m = 0; m < 9; m++) ym[m] += yv * sOPW[m*18+dd];
        }
        int tt = l & 1, r = l >> 1;
        int w = r & 127, h2 = r >> 7;
        int pix = (h2*2 + tt)*128 + w;
        #pragma unroll
        for (int m = 0; m < 9; m++){
            float py = wgt*ym[m] + g_ynew[((size_t)(b*9+m))*HWp + pix];
            py = fminf(fmaxf(py, 0.f), 127.f);
            g_py[((size_t)(b*9+m))*HWp + pix] = py;
        }
    }
}

// ---------------- deformable gather + tf32 tensor-core contraction + GN stats ----------------
#define DEF_SMEM ((128*68 + 64*68)*4)
__global__ void __launch_bounds__(256) kDeform(const float* __restrict__ dscb){
    extern __shared__ unsigned smu[];
    unsigned* sV = smu;             // [pix][ci] stride 68
    unsigned* sA = smu + 128*68;    // [co][ci] stride 68
    int i = blockIdx.x, b = blockIdx.y, t = threadIdx.x;
    int wid = t >> 5, lane = t & 31;
    int gID = lane >> 2, tig = lane & 3;
    int ct = (wid & 3)*16;
    int pt = (wid >> 2)*64;

    float acc[8][4];
    #pragma unroll
    for (int nt = 0; nt < 8; nt++)
        #pragma unroll
        for (int p = 0; p < 4; p++) acc[nt][p] = 0.f;

    for (int k = 0; k < 9; k++){
        #pragma unroll
        for (int r = 0; r < 16; r++){
            int idx = t + 256*r;
            int co = idx >> 6, ci = idx & 63;
            sA[co*68 + ci] = g_wA[k*4096 + idx];
        }
        int p0 = wid*16;
        #pragma unroll
        for (int pp = 0; pp < 16; pp++){
            int j = p0 + pp;
            float pyv = g_py[((size_t)(b*9+k))*HWp + i*128 + j];
            float fy0 = floorf(pyv);
            int y0 = (int)fy0;
            float wy = pyv - fy0;
            float wy0 = 1.f - wy;
            int y1 = min(y0 + 1, 127);
            int xc = min(max(j + k - 4, 0), 127);
            const float* base0 = &g_xT[((size_t)b*HWp + y0*128 + xc)*64];
            const float* base1 = &g_xT[((size_t)b*HWp + y1*128 + xc)*64];
            float vL = base0[lane]*wy0    + base1[lane]*wy;
            float vH = base0[lane+32]*wy0 + base1[lane+32]*wy;
            sV[j*68 + lane]      = tf32cvt(vL);
            sV[j*68 + lane + 32] = tf32cvt(vH);
        }
        __syncthreads();

        #pragma unroll
        for (int ks = 0; ks < 8; ks++){
            int kk = ks*8;
            unsigned a0 = sA[(ct+gID)*68   + kk + tig];
            unsigned a1 = sA[(ct+gID+8)*68 + kk + tig];
            unsigned a2 = sA[(ct+gID)*68   + kk + tig + 4];
            unsigned a3 = sA[(ct+gID+8)*68 + kk + tig + 4];
            #pragma unroll
            for (int nt = 0; nt < 8; nt++){
                int n0 = pt + nt*8;
                unsigned b0 = sV[(n0+gID)*68 + kk + tig];
                unsigned b1 = sV[(n0+gID)*68 + kk + tig + 4];
                mma_tf32(acc[nt], a0, a1, a2, a3, b0, b1);
            }
        }
        __syncthreads();
    }

    int co0 = ct + gID, co1 = ct + gID + 8;
    float bias0 = dscb[co0], bias1 = dscb[co1];
    float s0 = 0.f, ss0 = 0.f, s1 = 0.f, ss1 = 0.f;
    #pragma unroll
    for (int nt = 0; nt < 8; nt++){
        float c0 = acc[nt][0] + bias0, c1 = acc[nt][1] + bias0;
        float c2 = acc[nt][2] + bias1, c3 = acc[nt][3] + bias1;
        size_t pix = (size_t)i*128 + pt + nt*8 + tig*2;
        *(float2*)&g_outraw[((size_t)(b*64+co0))*HWp + pix] = make_float2(c0, c1);
        *(float2*)&g_outraw[((size_t)(b*64+co1))*HWp + pix] = make_float2(c2, c3);
        s0 += c0 + c1; ss0 += c0*c0 + c1*c1;
        s1 += c2 + c3; ss1 += c2*c2 + c3*c3;
    }
    #pragma unroll
    for (int m = 1; m <= 8; m <<= 1){
        s0  += __shfl_xor_sync(0xffffffffu, s0,  m);
        ss0 += __shfl_xor_sync(0xffffffffu, ss0, m);
        s1  += __shfl_xor_sync(0xffffffffu, s1,  m);
        ss1 += __shfl_xor_sync(0xffffffffu, ss1, m);
    }
    if ((lane & 15) == 0){
        int g0 = (ct >> 2) + (lane >> 4);
        atomicAdd(&g_fstats[(b*16 + g0)*2    ], s0);
        atomicAdd(&g_fstats[(b*16 + g0)*2 + 1], ss0);
        atomicAdd(&g_fstats[(b*16 + g0 + 2)*2    ], s1);
        atomicAdd(&g_fstats[(b*16 + g0 + 2)*2 + 1], ss1);
    }
}

// ---------------- final GN ----------------
__global__ void kFinalGN(const float* __restrict__ gng, const float* __restrict__ gnb,
                         float* __restrict__ out){
    int idx = blockIdx.x*256 + threadIdx.x;
    int b = idx >> 20;
    int c = (idx >> 14) & 63;
    int g = c >> 2;
    float s  = g_fstats[(b*16+g)*2];
    float ss = g_fstats[(b*16+g)*2+1];
    float mu = s * (1.f/65536.f);
    float var = ss * (1.f/65536.f) - mu*mu;
    float rs = rsqrtf(var + 1e-5f);
    out[idx] = (g_outraw[idx] - mu)*rs*gng[c] + gnb[c];
}

extern "C" void kernel_launch(void* const* d_in, const int* in_sizes, int n_in,
                              void* d_out, int out_size){
    const float* x     = (const float*)d_in[0];
    const float* offw  = (const float*)d_in[1];
    const float* offb  = (const float*)d_in[2];
    const float* gnog  = (const float*)d_in[3];
    const float* gnob  = (const float*)d_in[4];
    const float* altho = (const float*)d_in[5];
    const float* ipw   = (const float*)d_in[6];
    const float* cw    = (const float*)d_in[7];
    const float* cb    = (const float*)d_in[8];
    const float* xpw   = (const float*)d_in[9];
    const float* dtw   = (const float*)d_in[10];
    const float* dtb   = (const float*)d_in[11];
    const float* Alog  = (const float*)d_in[12];
    const float* Dp    = (const float*)d_in[13];
    const float* opw   = (const float*)d_in[14];
    const float* dscw  = (const float*)d_in[15];
    const float* dscb  = (const float*)d_in[16];
    const float* gng   = (const float*)d_in[17];
    const float* gnb   = (const float*)d_in[18];
    float* out = (float*)d_out;

    cudaFuncSetAttribute(kConv,   cudaFuncAttributeMaxDynamicSharedMemorySize, CONV_SMEM);
    cudaFuncSetAttribute(kFused,  cudaFuncAttributeMaxDynamicSharedMemorySize, FUS_SMEM);
    cudaFuncSetAttribute(kScan3,  cudaFuncAttributeMaxDynamicSharedMemorySize, SCAN3_SMEM);
    cudaFuncSetAttribute(kDeform, cudaFuncAttributeMaxDynamicSharedMemorySize, DEF_SMEM);

    kPrep<<<dim3(512, 2, 4), dim3(32, 8)>>>(x, dscw);
    kConv<<<dim3(64, 4), 320, CONV_SMEM>>>(x, offw, offb);
    kFused<<<dim3(64, 4), 288, FUS_SMEM>>>(gnog, gnob, ipw, cw, cb, xpw, dtw, dtb, Alog);
    kScan2<<<4, 288>>>();
    kScan3<<<dim3(64, 4), 288, SCAN3_SMEM>>>(Alog, Dp, opw, altho);
    kDeform<<<dim3(128, 4), 256, DEF_SMEM>>>(dscb);
    kFinalGN<<<16384, 256>>>(gng, gnb, out);
}

// round 8
// speedup vs baseline: 2.3050x; 1.0521x over previous
#include <cuda_runtime.h>
#include <math.h>

#define Bn   4
#define HWp  16384
#define LSEQ 16384

// ---------------- tf32 mma helpers ----------------
__device__ __forceinline__ unsigned tf32cvt(float v){
    unsigned r; asm("cvt.rna.tf32.f32 %0, %1;" : "=r"(r) : "f"(v)); return r;
}
__device__ __forceinline__ void mma_tf32(float* d, unsigned a0, unsigned a1, unsigned a2, unsigned a3,
                                         unsigned b0, unsigned b1){
    asm("mma.sync.aligned.m16n8k8.row.col.f32.tf32.tf32.f32 "
        "{%0,%1,%2,%3}, {%4,%5,%6,%7}, {%8,%9}, {%0,%1,%2,%3};"
        : "+f"(d[0]), "+f"(d[1]), "+f"(d[2]), "+f"(d[3])
        : "r"(a0), "r"(a1), "r"(a2), "r"(a3), "r"(b0), "r"(b1));
}

// ---------------- scratch ----------------
__device__ float g_xT[Bn*HWp*64];        // [b][pix][c]
__device__ float g_rawoff[Bn*10*HWp];    // offset conv out, [b][co][pix]
__device__ float g_ostats[Bn*5*2];
__device__ float g_ynew[Bn*9*HWp];       // [b][k][pix]
__device__ float g_dt[Bn*18*LSEQ];
__device__ float g_xi[Bn*18*LSEQ];
__device__ float g_gate[Bn*18*LSEQ];     // silu(z)
__device__ float g_Bsc[Bn*16*LSEQ];
__device__ float g_Csc[Bn*16*LSEQ];
__device__ float g_P[Bn*64*288];
__device__ float g_Q[Bn*64*288];
__device__ float g_hinit[Bn*64*288];
__device__ float g_py[Bn*9*HWp];         // [b][k][pix]
__device__ unsigned g_wA[9*64*64];       // [k][co][ci], tf32 bit patterns
__device__ float g_outraw[Bn*64*HWp];
__device__ float g_fstats[Bn*16*2];

__device__ __forceinline__ float softplusf(float x){
    return x > 20.f ? x : log1pf(expf(x));
}
__device__ __forceinline__ float siluf(float x){
    return x / (1.f + expf(-x));
}

// ---------------- prep: transpose x + zero stats + weight tf32 conversion ----------------
__global__ void kPrep(const float* __restrict__ x, const float* __restrict__ dscw){
    __shared__ float tile[32][33];
    int b = blockIdx.z, c0 = blockIdx.y*32, p0 = blockIdx.x*32;
    int bid = (blockIdx.z*gridDim.y + blockIdx.y)*gridDim.x + blockIdx.x;
    int gtid = bid*256 + threadIdx.y*32 + threadIdx.x;

    if (gtid < 36864){
        int k = gtid >> 12; int r = gtid & 4095;
        int co = r >> 6;  int ci = r & 63;
        g_wA[gtid] = tf32cvt(dscw[(co*64 + ci)*9 + k]);
    }
    if (gtid >= 65536 && gtid < 65536+40)  g_ostats[gtid-65536] = 0.f;
    if (gtid >= 131072 && gtid < 131072+128) g_fstats[gtid-131072] = 0.f;

    for (int i = threadIdx.y; i < 32; i += 8)
        tile[i][threadIdx.x] = x[(size_t)(b*64 + c0 + i)*HWp + p0 + threadIdx.x];
    __syncthreads();
    for (int i = threadIdx.y; i < 32; i += 8)
        g_xT[(size_t)(b*HWp + p0 + i)*64 + c0 + threadIdx.x] = tile[threadIdx.x][i];
}

// ---------------- offset conv 3x3 64->10, register-tiled + GN stats (R5 config) ----------------
#define CONV_SMEM ((16*4*132 + 5760)*4)
__global__ void __launch_bounds__(320) kConv(const float* __restrict__ x,
                                             const float* __restrict__ offw,
                                             const float* __restrict__ offb){
    extern __shared__ float sm[];
    float* xs = sm;            // [c][r][ww], stride 132
    float* sW = sm + 16*4*132; // offw direct copy
    int hb = blockIdx.x, b = blockIdx.y, tid = threadIdx.x;
    int h0 = hb*2;
    int hh = tid & 1, wt = (tid >> 1) & 15, co = tid >> 5;
    int w0 = wt*8;

    for (int idx = tid; idx < 5760; idx += 320) sW[idx] = offw[idx];

    float acc[8];
    float bv = offb[co];
    #pragma unroll
    for (int i = 0; i < 8; i++) acc[i] = bv;

    for (int cc = 0; cc < 4; cc++){
        int c0 = cc*16;
        __syncthreads();
        for (int idx = tid; idx < 16*4*130; idx += 320){
            int c = idx / 520;
            int rem = idx - c*520;
            int rr = rem / 130;
            int ww = rem - rr*130;
            int gh = h0 - 1 + rr, gw = ww - 1;
            float v = 0.f;
            if (gh >= 0 && gh < 128 && gw >= 0 && gw < 128)
                v = x[((size_t)(b*64 + c0 + c)*128 + gh)*128 + gw];
            xs[(c*4 + rr)*132 + ww] = v;
        }
        __syncthreads();
        for (int c = 0; c < 16; c++){
            #pragma unroll
            for (int dy = 0; dy < 3; dy++){
                const float* wp = &sW[(co*64 + c0 + c)*9 + dy*3];
                float wA = wp[0], wB = wp[1], wC = wp[2];
                const float* row = &xs[(c*4 + hh + dy)*132];
                float4 vA = *(const float4*)&row[w0];
                float4 vB = *(const float4*)&row[w0+4];
                float v8 = row[w0+8], v9 = row[w0+9];
                float v[10] = {vA.x,vA.y,vA.z,vA.w,vB.x,vB.y,vB.z,vB.w,v8,v9};
                #pragma unroll
                for (int i = 0; i < 8; i++)
                    acc[i] += wA*v[i] + wB*v[i+1] + wC*v[i+2];
            }
        }
    }

    int h = h0 + hh;
    float s = 0.f, ss = 0.f;
    #pragma unroll
    for (int i = 0; i < 8; i++){
        g_rawoff[((size_t)(b*10+co))*HWp + h*128 + w0 + i] = acc[i];
        s += acc[i]; ss += acc[i]*acc[i];
    }
    #pragma unroll
    for (int m = 16; m > 0; m >>= 1){
        s  += __shfl_xor_sync(0xffffffffu, s,  m);
        ss += __shfl_xor_sync(0xffffffffu, ss, m);
    }
    if ((tid & 31) == 0){
        atomicAdd(&g_ostats[(b*5 + (co>>1))*2    ], s);
        atomicAdd(&g_ostats[(b*5 + (co>>1))*2 + 1], ss);
    }
}

// ---------------- fused: GN+tanh+cumsum+ynew -> front-end GEMVs -> scan pass1 ----------------
__device__ __forceinline__ void comp_tv(int b, int l, const float* sMu, const float* sRs,
                                        const float* __restrict__ gnog,
                                        const float* __restrict__ gnob, float* tv){
    int tt = l & 1, r = l >> 1;
    int w = r & 127, r2 = r >> 7;
    int p = (r2*2 + tt)*128 + w;
    #pragma unroll
    for (int c = 0; c < 9; c++){
        float raw = g_rawoff[((size_t)(b*10+c))*HWp + p];
        float xn = (raw - sMu[c>>1]) * sRs[c>>1] * gnog[c] + gnob[c];
        tv[c] = tanhf(xn);
    }
}

#define FUS_SMEM (19339*4)
__global__ void __launch_bounds__(288) kFused(
        const float* __restrict__ gnog, const float* __restrict__ gnob,
        const float* __restrict__ ipw,  const float* __restrict__ cw,
        const float* __restrict__ cb,   const float* __restrict__ xpw,
        const float* __restrict__ dtw,  const float* __restrict__ dtb,
        const float* __restrict__ Alog){
    extern __shared__ float sm[];
    float* sXP  = sm;            // 259*19
    float* sIPW = sm + 4921;     // 324
    float* sXPW = sm + 5245;     // 594
    float* sCW  = sm + 5839;     // 72
    float* sCB  = sm + 5911;     // 18
    float* sDTW = sm + 5929;     // 18
    float* sDTB = sm + 5947;     // 18
    float* sMu  = sm + 5965;     // 5
    float* sRs  = sm + 5970;     // 5
    float* sDT  = sm + 5975;     // 18*257
    float* sXI  = sm + 10601;    // 18*257
    float* sB   = sm + 15227;    // 16*257
    int b = blockIdx.y, c = blockIdx.x, l0 = c*256, t = threadIdx.x;

    for (int idx = t; idx < 324; idx += 288) sIPW[idx] = ipw[idx];
    for (int idx = t; idx < 594; idx += 288) sXPW[idx] = xpw[idx];
    if (t < 72) sCW[t] = cw[t];
    if (t < 18){ sCB[t] = cb[t]; sDTW[t] = dtw[t]; sDTB[t] = dtb[t]; }
    if (t < 5){
        float s  = g_ostats[(b*5+t)*2];
        float ss = g_ostats[(b*5+t)*2+1];
        float mu = s * (1.f/32768.f);
        float var = ss * (1.f/32768.f) - mu*mu;
        sMu[t] = mu;
        sRs[t] = rsqrtf(var + 1e-5f);
    }
    __syncthreads();

    if (t < 256){
        int l = l0 + t;
        float tv[9];
        comp_tv(b, l, sMu, sRs, gnog, gnob, tv);

        float cum[9];
        cum[4] = 0.f;
        cum[5] = tv[5]; cum[6] = cum[5]+tv[6]; cum[7] = cum[6]+tv[7]; cum[8] = cum[7]+tv[8];
        cum[3] = tv[3]; cum[2] = cum[3]+tv[2]; cum[1] = cum[2]+tv[1]; cum[0] = cum[1]+tv[0];

        int tt = l & 1, r = l >> 1;
        int w = r & 127, r2 = r >> 7;
        int h = r2*2 + tt, p = h*128 + w;
        #pragma unroll
        for (int k = 0; k < 9; k++)
            g_ynew[((size_t)(b*9+k))*HWp + p] = (float)h + cum[k];

        #pragma unroll
        for (int n = 0; n < 18; n++){
            float v = 0.f;
            #pragma unroll
            for (int m = 0; m < 9; m++) v += tv[m]*sIPW[n*9+m];
            sXP[(t+3)*19 + n] = v;
        }
        #pragma unroll
        for (int n = 0; n < 18; n++){
            float z = 0.f;
            #pragma unroll
            for (int m = 0; m < 9; m++) z += tv[m]*sIPW[(18+n)*9+m];
            g_gate[((size_t)(b*18+n))*LSEQ + l] = siluf(z);
        }
    } else if (t < 259){
        int bi = t - 256;
        int l2 = l0 - 3 + bi;
        if (l2 >= 0){
            float tv2[9];
            comp_tv(b, l2, sMu, sRs, gnog, gnob, tv2);
            #pragma unroll
            for (int n = 0; n < 18; n++){
                float v = 0.f;
                #pragma unroll
                for (int m = 0; m < 9; m++) v += tv2[m]*sIPW[n*9+m];
                sXP[bi*19 + n] = v;
            }
        } else {
            #pragma unroll
            for (int n = 0; n < 18; n++) sXP[bi*19 + n] = 0.f;
        }
    }
    __syncthreads();

    if (t < 256){
        int l = l0 + t;
        float xi[18];
        #pragma unroll
        for (int d = 0; d < 18; d++){
            float xc = sCB[d];
            #pragma unroll
            for (int j = 0; j < 4; j++) xc += sCW[d*4+j]*sXP[(t+j)*19 + d];
            xi[d] = siluf(xc);
        }
        float dtr = 0.f;
        #pragma unroll
        for (int d = 0; d < 18; d++) dtr += xi[d]*sXPW[d];
        #pragma unroll
        for (int s = 0; s < 16; s++){
            float bv = 0.f, cv = 0.f;
            #pragma unroll
            for (int d = 0; d < 18; d++){
                bv += xi[d]*sXPW[(1+s)*18 + d];
                cv += xi[d]*sXPW[(17+s)*18 + d];
            }
            sB[s*257 + t] = bv;
            g_Bsc[((size_t)(b*16+s))*LSEQ + l] = bv;
            g_Csc[((size_t)(b*16+s))*LSEQ + l] = cv;
        }
        #pragma unroll
        for (int d = 0; d < 18; d++){
            float a = dtr*sDTW[d] + sDTB[d];
            float dtv = softplusf(a);
            sDT[d*257 + t] = dtv;
            sXI[d*257 + t] = xi[d];
            g_dt[((size_t)(b*18+d))*LSEQ + l] = dtv;
            g_xi[((size_t)(b*18+d))*LSEQ + l] = xi[d];
        }
    }
    __syncthreads();

    int d = t / 16, s = t % 16;
    float a = -expf(Alog[d*16+s]);
    float p = 1.f, q = 0.f;
    for (int i = 0; i < 256; i++){
        float dt = sDT[d*257+i];
        float da = __expf(dt*a);
        q = da*q + dt*sB[s*257+i]*sXI[d*257+i];
        p *= da;
    }
    g_P[(b*64+c)*288 + t] = p;
    g_Q[(b*64+c)*288 + t] = q;
}

// ---------------- scan pass2: serial carry (smem-prefetched) ----------------
#define SCAN2_SMEM (2*64*288*4)
__global__ void __launch_bounds__(288) kScan2(){
    extern __shared__ float sm[];
    float* sP = sm;            // [c][t]
    float* sQ = sm + 64*288;
    int b = blockIdx.x, t = threadIdx.x;
    const float* gp = &g_P[b*64*288];
    const float* gq = &g_Q[b*64*288];
    for (int idx = t; idx < 64*288; idx += 288){
        sP[idx] = gp[idx];
        sQ[idx] = gq[idx];
    }
    __syncthreads();
    float h = 0.f;
    #pragma unroll 8
    for (int c = 0; c < 64; c++){
        g_hinit[(b*64+c)*288 + t] = h;
        h = sP[c*288+t]*h + sQ[c*288+t];
    }
}

// ---------------- scan pass3: replay + output + py ----------------
#define SCAN3_SMEM ((86*257 + 162 + 18)*4)
__global__ void kScan3(const float* __restrict__ Alog, const float* __restrict__ Dp,
                       const float* __restrict__ opw,  const float* __restrict__ altho){
    extern __shared__ float sm[];
    float* sDT = sm;
    float* sXI = sm + 18*257;
    float* sB  = sm + 36*257;
    float* sC  = sm + 52*257;
    float* sYS = sm + 68*257;
    float* sOPW = sm + 86*257;
    float* sDP  = sOPW + 162;
    int b = blockIdx.y, c = blockIdx.x, l0 = c*256, t = threadIdx.x;
    for (int idx = t; idx < 18*256; idx += 288){
        int dd = idx >> 8, i = idx & 255;
        sDT[dd*257+i] = g_dt[((size_t)(b*18+dd))*LSEQ + l0 + i];
        sXI[dd*257+i] = g_xi[((size_t)(b*18+dd))*LSEQ + l0 + i];
    }
    for (int idx = t; idx < 16*256; idx += 288){
        int ss = idx >> 8, i = idx & 255;
        sB[ss*257+i] = g_Bsc[((size_t)(b*16+ss))*LSEQ + l0 + i];
        sC[ss*257+i] = g_Csc[((size_t)(b*16+ss))*LSEQ + l0 + i];
    }
    if (t < 162) sOPW[t] = opw[t];
    if (t < 18)  sDP[t]  = Dp[t];
    __syncthreads();

    int d = t / 16, s = t % 16;
    float a = -expf(Alog[d*16+s]);
    float h = g_hinit[(b*64+c)*288 + t];
    for (int i = 0; i < 256; i++){
        float dt = sDT[d*257+i];
        float da = __expf(dt*a);
        h = da*h + dt*sB[s*257+i]*sXI[d*257+i];
        float v = h * sC[s*257+i];
        v += __shfl_xor_sync(0xffffffffu, v, 1);
        v += __shfl_xor_sync(0xffffffffu, v, 2);
        v += __shfl_xor_sync(0xffffffffu, v, 4);
        v += __shfl_xor_sync(0xffffffffu, v, 8);
        if ((t & 15) == 0) sYS[d*257+i] = v;
    }
    __syncthreads();

    if (t < 256){
        int l = l0 + t;
        float wgt = fmaxf(softplusf(altho[0]), 0.01f);
        float ym[9];
        #pragma unroll
        for (int m = 0; m < 9; m++) ym[m] = 0.f;
        #pragma unroll
        for (int dd = 0; dd < 18; dd++){
            float yv = (sYS[dd*257+t] + sDP[dd]*sXI[dd*257+t]) * g_gate[((size_t)(b*18+dd))*LSEQ + l];
            #pragma unroll
            for (int m = 0; m < 9; m++) ym[m] += yv * sOPW[m*18+dd];
        }
        int tt = l & 1, r = l >> 1;
        int w = r & 127, h2 = r >> 7;
        int pix = (h2*2 + tt)*128 + w;
        #pragma unroll
        for (int m = 0; m < 9; m++){
            float py = wgt*ym[m] + g_ynew[((size_t)(b*9+m))*HWp + pix];
            py = fminf(fmaxf(py, 0.f), 127.f);
            g_py[((size_t)(b*9+m))*HWp + pix] = py;
        }
    }
}

// ---------------- deformable gather + tf32 tensor-core contraction + GN stats ----------------
#define DEF_SMEM ((128*68 + 64*68)*4)
__global__ void __launch_bounds__(256) kDeform(const float* __restrict__ dscb){
    extern __shared__ unsigned smu[];
    unsigned* sV = smu;             // [pix][ci] stride 68
    unsigned* sA = smu + 128*68;    // [co][ci] stride 68
    int i = blockIdx.x, b = blockIdx.y, t = threadIdx.x;
    int wid = t >> 5, lane = t & 31;
    int gID = lane >> 2, tig = lane & 3;
    int ct = (wid & 3)*16;
    int pt = (wid >> 2)*64;

    float acc[8][4];
    #pragma unroll
    for (int nt = 0; nt < 8; nt++)
        #pragma unroll
        for (int p = 0; p < 4; p++) acc[nt][p] = 0.f;

    for (int k = 0; k < 9; k++){
        #pragma unroll
        for (int r = 0; r < 16; r++){
            int idx = t + 256*r;
            int co = idx >> 6, ci = idx & 63;
            sA[co*68 + ci] = g_wA[k*4096 + idx];
        }
        int p0 = wid*16;
        #pragma unroll
        for (int pp = 0; pp < 16; pp++){
            int j = p0 + pp;
            float pyv = g_py[((size_t)(b*9+k))*HWp + i*128 + j];
            float fy0 = floorf(pyv);
            int y0 = (int)fy0;
            float wy = pyv - fy0;
            float wy0 = 1.f - wy;
            int y1 = min(y0 + 1, 127);
            int xc = min(max(j + k - 4, 0), 127);
            const float* base0 = &g_xT[((size_t)b*HWp + y0*128 + xc)*64];
            const float* base1 = &g_xT[((size_t)b*HWp + y1*128 + xc)*64];
            float vL = base0[lane]*wy0    + base1[lane]*wy;
            float vH = base0[lane+32]*wy0 + base1[lane+32]*wy;
            sV[j*68 + lane]      = tf32cvt(vL);
            sV[j*68 + lane + 32] = tf32cvt(vH);
        }
        __syncthreads();

        #pragma unroll
        for (int ks = 0; ks < 8; ks++){
            int kk = ks*8;
            unsigned a0 = sA[(ct+gID)*68   + kk + tig];
            unsigned a1 = sA[(ct+gID+8)*68 + kk + tig];
            unsigned a2 = sA[(ct+gID)*68   + kk + tig + 4];
            unsigned a3 = sA[(ct+gID+8)*68 + kk + tig + 4];
            #pragma unroll
            for (int nt = 0; nt < 8; nt++){
                int n0 = pt + nt*8;
                unsigned b0 = sV[(n0+gID)*68 + kk + tig];
                unsigned b1 = sV[(n0+gID)*68 + kk + tig + 4];
                mma_tf32(acc[nt], a0, a1, a2, a3, b0, b1);
            }
        }
        __syncthreads();
    }

    int co0 = ct + gID, co1 = ct + gID + 8;
    float bias0 = dscb[co0], bias1 = dscb[co1];
    float s0 = 0.f, ss0 = 0.f, s1 = 0.f, ss1 = 0.f;
    #pragma unroll
    for (int nt = 0; nt < 8; nt++){
        float c0 = acc[nt][0] + bias0, c1 = acc[nt][1] + bias0;
        float c2 = acc[nt][2] + bias1, c3 = acc[nt][3] + bias1;
        size_t pix = (size_t)i*128 + pt + nt*8 + tig*2;
        *(float2*)&g_outraw[((size_t)(b*64+co0))*HWp + pix] = make_float2(c0, c1);
        *(float2*)&g_outraw[((size_t)(b*64+co1))*HWp + pix] = make_float2(c2, c3);
        s0 += c0 + c1; ss0 += c0*c0 + c1*c1;
        s1 += c2 + c3; ss1 += c2*c2 + c3*c3;
    }
    #pragma unroll
    for (int m = 1; m <= 8; m <<= 1){
        s0  += __shfl_xor_sync(0xffffffffu, s0,  m);
        ss0 += __shfl_xor_sync(0xffffffffu, ss0, m);
        s1  += __shfl_xor_sync(0xffffffffu, s1,  m);
        ss1 += __shfl_xor_sync(0xffffffffu, ss1, m);
    }
    if ((lane & 15) == 0){
        int g0 = (ct >> 2) + (lane >> 4);
        atomicAdd(&g_fstats[(b*16 + g0)*2    ], s0);
        atomicAdd(&g_fstats[(b*16 + g0)*2 + 1], ss0);
        atomicAdd(&g_fstats[(b*16 + g0 + 2)*2    ], s1);
        atomicAdd(&g_fstats[(b*16 + g0 + 2)*2 + 1], ss1);
    }
}

// ---------------- final GN (float4) ----------------
__global__ void kFinalGN(const float* __restrict__ gng, const float* __restrict__ gnb,
                         float* __restrict__ out){
    int idx4 = blockIdx.x*256 + threadIdx.x;
    int idx = idx4*4;
    int b = idx >> 20;
    int c = (idx >> 14) & 63;
    int g = c >> 2;
    float s  = g_fstats[(b*16+g)*2];
    float ss = g_fstats[(b*16+g)*2+1];
    float mu = s * (1.f/65536.f);
    float var = ss * (1.f/65536.f) - mu*mu;
    float rs = rsqrtf(var + 1e-5f) * gng[c];
    float bb = gnb[c];
    float4 v = *(const float4*)&g_outraw[idx];
    float4 o;
    o.x = (v.x - mu)*rs + bb;
    o.y = (v.y - mu)*rs + bb;
    o.z = (v.z - mu)*rs + bb;
    o.w = (v.w - mu)*rs + bb;
    *(float4*)&out[idx] = o;
}

extern "C" void kernel_launch(void* const* d_in, const int* in_sizes, int n_in,
                              void* d_out, int out_size){
    const float* x     = (const float*)d_in[0];
    const float* offw  = (const float*)d_in[1];
    const float* offb  = (const float*)d_in[2];
    const float* gnog  = (const float*)d_in[3];
    const float* gnob  = (const float*)d_in[4];
    const float* altho = (const float*)d_in[5];
    const float* ipw   = (const float*)d_in[6];
    const float* cw    = (const float*)d_in[7];
    const float* cb    = (const float*)d_in[8];
    const float* xpw   = (const float*)d_in[9];
    const float* dtw   = (const float*)d_in[10];
    const float* dtb   = (const float*)d_in[11];
    const float* Alog  = (const float*)d_in[12];
    const float* Dp    = (const float*)d_in[13];
    const float* opw   = (const float*)d_in[14];
    const float* dscw  = (const float*)d_in[15];
    const float* dscb  = (const float*)d_in[16];
    const float* gng   = (const float*)d_in[17];
    const float* gnb   = (const float*)d_in[18];
    float* out = (float*)d_out;

    cudaFuncSetAttribute(kConv,   cudaFuncAttributeMaxDynamicSharedMemorySize, CONV_SMEM);
    cudaFuncSetAttribute(kFused,  cudaFuncAttributeMaxDynamicSharedMemorySize, FUS_SMEM);
    cudaFuncSetAttribute(kScan2,  cudaFuncAttributeMaxDynamicSharedMemorySize, SCAN2_SMEM);
    cudaFuncSetAttribute(kScan3,  cudaFuncAttributeMaxDynamicSharedMemorySize, SCAN3_SMEM);
    cudaFuncSetAttribute(kDeform, cudaFuncAttributeMaxDynamicSharedMemorySize, DEF_SMEM);

    kPrep<<<dim3(512, 2, 4), dim3(32, 8)>>>(x, dscw);
    kConv<<<dim3(64, 4), 320, CONV_SMEM>>>(x, offw, offb);
    kFused<<<dim3(64, 4), 288, FUS_SMEM>>>(gnog, gnob, ipw, cw, cb, xpw, dtw, dtb, Alog);
    kScan2<<<4, 288, SCAN2_SMEM>>>();
    kScan3<<<dim3(64, 4), 288, SCAN3_SMEM>>>(Alog, Dp, opw, altho);
    kDeform<<<dim3(128, 4), 256, DEF_SMEM>>>(dscb);
    kFinalGN<<<4096, 256>>>(gng, gnb, out);
}

// round 9
// speedup vs baseline: 2.4311x; 1.0547x over previous
#include <cuda_runtime.h>
#include <math.h>

#define Bn   4
#define HWp  16384
#define LSEQ 16384

// ---------------- tf32 mma helpers ----------------
__device__ __forceinline__ unsigned tf32cvt(float v){
    unsigned r; asm("cvt.rna.tf32.f32 %0, %1;" : "=r"(r) : "f"(v)); return r;
}
__device__ __forceinline__ void mma_tf32(float* d, unsigned a0, unsigned a1, unsigned a2, unsigned a3,
                                         unsigned b0, unsigned b1){
    asm("mma.sync.aligned.m16n8k8.row.col.f32.tf32.tf32.f32 "
        "{%0,%1,%2,%3}, {%4,%5,%6,%7}, {%8,%9}, {%0,%1,%2,%3};"
        : "+f"(d[0]), "+f"(d[1]), "+f"(d[2]), "+f"(d[3])
        : "r"(a0), "r"(a1), "r"(a2), "r"(a3), "r"(b0), "r"(b1));
}

// ---------------- scratch ----------------
__device__ float g_xT[Bn*HWp*64];        // [b][pix][c]
__device__ float g_rawoff[Bn*10*HWp];    // offset conv out, [b][co][pix]
__device__ float g_ostats[Bn*5*2];
__device__ float g_ynew[Bn*9*HWp];       // [b][k][pix]
__device__ float g_dt[Bn*18*LSEQ];
__device__ float g_xi[Bn*18*LSEQ];
__device__ float g_gate[Bn*18*LSEQ];     // silu(z)
__device__ float g_Bsc[Bn*16*LSEQ];
__device__ float g_Csc[Bn*16*LSEQ];
__device__ float g_P[Bn*64*288];
__device__ float g_Q[Bn*64*288];
__device__ float g_hinit[Bn*64*288];
__device__ float g_py[Bn*9*HWp];         // [b][k][pix]
__device__ unsigned g_wA[9*64*64];       // [k][co][ci] tf32, deform conv
__device__ unsigned g_wC[9*16*64];       // [tap][co(pad16)][ci] tf32, offset conv
__device__ float g_outraw[Bn*64*HWp];
__device__ float g_fstats[Bn*16*2];

__device__ __forceinline__ float softplusf(float x){
    return x > 20.f ? x : log1pf(expf(x));
}
__device__ __forceinline__ float siluf(float x){
    return x / (1.f + expf(-x));
}

// ---------------- prep: transpose x + zero stats + weight tf32 conversions ----------------
__global__ void kPrep(const float* __restrict__ x, const float* __restrict__ dscw,
                      const float* __restrict__ offw){
    __shared__ float tile[32][33];
    int b = blockIdx.z, c0 = blockIdx.y*32, p0 = blockIdx.x*32;
    int bid = (blockIdx.z*gridDim.y + blockIdx.y)*gridDim.x + blockIdx.x;
    int gtid = bid*256 + threadIdx.y*32 + threadIdx.x;

    if (gtid < 36864){
        int k = gtid >> 12; int r = gtid & 4095;
        int co = r >> 6;  int ci = r & 63;
        g_wA[gtid] = tf32cvt(dscw[(co*64 + ci)*9 + k]);
    }
    if (gtid >= 40960 && gtid < 40960+9216){
        int idx = gtid - 40960;
        int tap = idx >> 10; int r = idx & 1023;
        int co = r >> 6; int ci = r & 63;
        int dy = tap/3, dx = tap - dy*3;
        float v = (co < 10) ? offw[((co*64+ci)*3 + dy)*3 + dx] : 0.f;
        g_wC[idx] = tf32cvt(v);
    }
    if (gtid >= 65536 && gtid < 65536+40)  g_ostats[gtid-65536] = 0.f;
    if (gtid >= 131072 && gtid < 131072+128) g_fstats[gtid-131072] = 0.f;

    for (int i = threadIdx.y; i < 32; i += 8)
        tile[i][threadIdx.x] = x[(size_t)(b*64 + c0 + i)*HWp + p0 + threadIdx.x];
    __syncthreads();
    for (int i = threadIdx.y; i < 32; i += 8)
        g_xT[(size_t)(b*HWp + p0 + i)*64 + c0 + threadIdx.x] = tile[threadIdx.x][i];
}

// ---------------- offset conv 3x3 64->10 via tf32 mma (implicit im2col) ----------------
// block = (row h, batch b), 256 threads = 8 warps. warp n-tile = 16 pixels.
// sV[dy*130+jp][ci] stride 68, jp = w+1 (zero-padded edges);
// tap (dy,dx) reads row dy at jp = j+dx. A: [tap*16+co][ci] stride 68.
#define CONVM_SMEM ((144 + 390)*68*4)
__global__ void __launch_bounds__(256) kConvM(const float* __restrict__ offb){
    extern __shared__ unsigned su[];
    unsigned* sA = su;            // [tap*16+co][68]
    unsigned* sV = su + 144*68;   // [dy*130+jp][68]
    int h = blockIdx.x, b = blockIdx.y, t = threadIdx.x;
    int wid = t >> 5, lane = t & 31, gID = lane >> 2, tig = lane & 3;
    int n0 = wid*16;

    for (int idx = t; idx < 9216; idx += 256){
        int row = idx >> 6, ci = idx & 63;
        sA[row*68 + ci] = g_wC[idx];
    }
    for (int idx = t; idx < 3*130*16; idx += 256){
        int c4 = idx & 15;
        int r = idx >> 4;          // dy*130 + jp
        int jp = r % 130; int dy = r / 130;
        int gh = h - 1 + dy, gw = jp - 1;
        float4 v = make_float4(0.f, 0.f, 0.f, 0.f);
        if (gh >= 0 && gh < 128 && gw >= 0 && gw < 128)
            v = *(const float4*)&g_xT[((size_t)b*HWp + gh*128 + gw)*64 + c4*4];
        uint4 tv;
        tv.x = tf32cvt(v.x); tv.y = tf32cvt(v.y);
        tv.z = tf32cvt(v.z); tv.w = tf32cvt(v.w);
        *(uint4*)&sV[r*68 + c4*4] = tv;
    }
    __syncthreads();

    float acc[2][4];
    #pragma unroll
    for (int nt = 0; nt < 2; nt++)
        #pragma unroll
        for (int p = 0; p < 4; p++) acc[nt][p] = 0.f;

    #pragma unroll
    for (int tap = 0; tap < 9; tap++){
        int dy = tap/3, dx = tap - dy*3;
        int arow = tap*16;
        int vbase = dy*130 + dx;
        #pragma unroll
        for (int ks = 0; ks < 8; ks++){
            int kk = ks*8;
            unsigned a0 = sA[(arow+gID)*68   + kk + tig];
            unsigned a1 = sA[(arow+gID+8)*68 + kk + tig];
            unsigned a2 = sA[(arow+gID)*68   + kk + tig + 4];
            unsigned a3 = sA[(arow+gID+8)*68 + kk + tig + 4];
            #pragma unroll
            for (int nt = 0; nt < 2; nt++){
                int j = n0 + nt*8 + gID;
                unsigned b0 = sV[(vbase + j)*68 + kk + tig];
                unsigned b1 = sV[(vbase + j)*68 + kk + tig + 4];
                mma_tf32(acc[nt], a0, a1, a2, a3, b0, b1);
            }
        }
    }

    // epilogue: co0 = gID (ch 0..7), co1 = gID+8 (ch 8,9 valid; >=10 are exact zeros)
    int co0 = gID, co1 = gID + 8;
    float bias0 = offb[co0];
    float bias1 = (gID < 2) ? offb[co1] : 0.f;
    float s0 = 0.f, ss0 = 0.f, s1 = 0.f, ss1 = 0.f;
    #pragma unroll
    for (int nt = 0; nt < 2; nt++){
        float c0 = acc[nt][0] + bias0, c1 = acc[nt][1] + bias0;
        int pix = h*128 + n0 + nt*8 + tig*2;
        *(float2*)&g_rawoff[((size_t)(b*10+co0))*HWp + pix] = make_float2(c0, c1);
        s0 += c0 + c1; ss0 += c0*c0 + c1*c1;
        if (gID < 2){
            float c2 = acc[nt][2] + bias1, c3 = acc[nt][3] + bias1;
            *(float2*)&g_rawoff[((size_t)(b*10+co1))*HWp + pix] = make_float2(c2, c3);
            s1 += c2 + c3; ss1 += c2*c2 + c3*c3;
        }
    }
    // reduce over tig (xor 1,2) then over co pair (xor 4: gID <-> gID^1)
    #pragma unroll
    for (int m = 1; m <= 4; m <<= 1){
        s0  += __shfl_xor_sync(0xffffffffu, s0,  m);
        ss0 += __shfl_xor_sync(0xffffffffu, ss0, m);
        s1  += __shfl_xor_sync(0xffffffffu, s1,  m);
        ss1 += __shfl_xor_sync(0xffffffffu, ss1, m);
    }
    if (tig == 0 && (gID & 1) == 0){
        int g0 = gID >> 1;
        atomicAdd(&g_ostats[(b*5 + g0)*2    ], s0);
        atomicAdd(&g_ostats[(b*5 + g0)*2 + 1], ss0);
        if (gID == 0){
            atomicAdd(&g_ostats[(b*5 + 4)*2    ], s1);
            atomicAdd(&g_ostats[(b*5 + 4)*2 + 1], ss1);
        }
    }
}

// ---------------- fused: GN+tanh+cumsum+ynew -> front-end GEMVs -> scan pass1 ----------------
__device__ __forceinline__ void comp_tv(int b, int l, const float* sMu, const float* sRs,
                                        const float* __restrict__ gnog,
                                        const float* __restrict__ gnob, float* tv){
    int tt = l & 1, r = l >> 1;
    int w = r & 127, r2 = r >> 7;
    int p = (r2*2 + tt)*128 + w;
    #pragma unroll
    for (int c = 0; c < 9; c++){
        float raw = g_rawoff[((size_t)(b*10+c))*HWp + p];
        float xn = (raw - sMu[c>>1]) * sRs[c>>1] * gnog[c] + gnob[c];
        tv[c] = tanhf(xn);
    }
}

#define FUS_SMEM (19339*4)
__global__ void __launch_bounds__(288) kFused(
        const float* __restrict__ gnog, const float* __restrict__ gnob,
        const float* __restrict__ ipw,  const float* __restrict__ cw,
        const float* __restrict__ cb,   const float* __restrict__ xpw,
        const float* __restrict__ dtw,  const float* __restrict__ dtb,
        const float* __restrict__ Alog){
    extern __shared__ float sm[];
    float* sXP  = sm;            // 259*19
    float* sIPW = sm + 4921;     // 324
    float* sXPW = sm + 5245;     // 594
    float* sCW  = sm + 5839;     // 72
    float* sCB  = sm + 5911;     // 18
    float* sDTW = sm + 5929;     // 18
    float* sDTB = sm + 5947;     // 18
    float* sMu  = sm + 5965;     // 5
    float* sRs  = sm + 5970;     // 5
    float* sDT  = sm + 5975;     // 18*257
    float* sXI  = sm + 10601;    // 18*257
    float* sB   = sm + 15227;    // 16*257
    int b = blockIdx.y, c = blockIdx.x, l0 = c*256, t = threadIdx.x;

    for (int idx = t; idx < 324; idx += 288) sIPW[idx] = ipw[idx];
    for (int idx = t; idx < 594; idx += 288) sXPW[idx] = xpw[idx];
    if (t < 72) sCW[t] = cw[t];
    if (t < 18){ sCB[t] = cb[t]; sDTW[t] = dtw[t]; sDTB[t] = dtb[t]; }
    if (t < 5){
        float s  = g_ostats[(b*5+t)*2];
        float ss = g_ostats[(b*5+t)*2+1];
        float mu = s * (1.f/32768.f);
        float var = ss * (1.f/32768.f) - mu*mu;
        sMu[t] = mu;
        sRs[t] = rsqrtf(var + 1e-5f);
    }
    __syncthreads();

    if (t < 256){
        int l = l0 + t;
        float tv[9];
        comp_tv(b, l, sMu, sRs, gnog, gnob, tv);

        float cum[9];
        cum[4] = 0.f;
        cum[5] = tv[5]; cum[6] = cum[5]+tv[6]; cum[7] = cum[6]+tv[7]; cum[8] = cum[7]+tv[8];
        cum[3] = tv[3]; cum[2] = cum[3]+tv[2]; cum[1] = cum[2]+tv[1]; cum[0] = cum[1]+tv[0];

        int tt = l & 1, r = l >> 1;
        int w = r & 127, r2 = r >> 7;
        int h = r2*2 + tt, p = h*128 + w;
        #pragma unroll
        for (int k = 0; k < 9; k++)
            g_ynew[((size_t)(b*9+k))*HWp + p] = (float)h + cum[k];

        #pragma unroll
        for (int n = 0; n < 18; n++){
            float v = 0.f;
            #pragma unroll
            for (int m = 0; m < 9; m++) v += tv[m]*sIPW[n*9+m];
            sXP[(t+3)*19 + n] = v;
        }
        #pragma unroll
        for (int n = 0; n < 18; n++){
            float z = 0.f;
            #pragma unroll
            for (int m = 0; m < 9; m++) z += tv[m]*sIPW[(18+n)*9+m];
            g_gate[((size_t)(b*18+n))*LSEQ + l] = siluf(z);
        }
    } else if (t < 259){
        int bi = t - 256;
        int l2 = l0 - 3 + bi;
        if (l2 >= 0){
            float tv2[9];
            comp_tv(b, l2, sMu, sRs, gnog, gnob, tv2);
            #pragma unroll
            for (int n = 0; n < 18; n++){
                float v = 0.f;
                #pragma unroll
                for (int m = 0; m < 9; m++) v += tv2[m]*sIPW[n*9+m];
                sXP[bi*19 + n] = v;
            }
        } else {
            #pragma unroll
            for (int n = 0; n < 18; n++) sXP[bi*19 + n] = 0.f;
        }
    }
    __syncthreads();

    if (t < 256){
        int l = l0 + t;
        float xi[18];
        #pragma unroll
        for (int d = 0; d < 18; d++){
            float xc = sCB[d];
            #pragma unroll
            for (int j = 0; j < 4; j++) xc += sCW[d*4+j]*sXP[(t+j)*19 + d];
            xi[d] = siluf(xc);
        }
        float dtr = 0.f;
        #pragma unroll
        for (int d = 0; d < 18; d++) dtr += xi[d]*sXPW[d];
        #pragma unroll
        for (int s = 0; s < 16; s++){
            float bv = 0.f, cv = 0.f;
            #pragma unroll
            for (int d = 0; d < 18; d++){
                bv += xi[d]*sXPW[(1+s)*18 + d];
                cv += xi[d]*sXPW[(17+s)*18 + d];
            }
            sB[s*257 + t] = bv;
            g_Bsc[((size_t)(b*16+s))*LSEQ + l] = bv;
            g_Csc[((size_t)(b*16+s))*LSEQ + l] = cv;
        }
        #pragma unroll
        for (int d = 0; d < 18; d++){
            float a = dtr*sDTW[d] + sDTB[d];
            float dtv = softplusf(a);
            sDT[d*257 + t] = dtv;
            sXI[d*257 + t] = xi[d];
            g_dt[((size_t)(b*18+d))*LSEQ + l] = dtv;
            g_xi[((size_t)(b*18+d))*LSEQ + l] = xi[d];
        }
    }
    __syncthreads();

    int d = t / 16, s = t % 16;
    float a = -expf(Alog[d*16+s]);
    float p = 1.f, q = 0.f;
    for (int i = 0; i < 256; i++){
        float dt = sDT[d*257+i];
        float da = __expf(dt*a);
        q = da*q + dt*sB[s*257+i]*sXI[d*257+i];
        p *= da;
    }
    g_P[(b*64+c)*288 + t] = p;
    g_Q[(b*64+c)*288 + t] = q;
}

// ---------------- scan pass2: serial carry, t-sliced 36/block ----------------
#define SCAN2_SMEM (2*64*36*4)
__global__ void __launch_bounds__(288) kScan2(){
    extern __shared__ float sm[];
    float* sP = sm;            // [c][36]
    float* sQ = sm + 64*36;
    int b = blockIdx.x, sl = blockIdx.y, t = threadIdx.x;
    int t0 = sl*36;
    for (int idx = t; idx < 64*36; idx += 288){
        int c = idx/36, tt = idx - c*36;
        sP[idx] = g_P[(b*64+c)*288 + t0 + tt];
        sQ[idx] = g_Q[(b*64+c)*288 + t0 + tt];
    }
    __syncthreads();
    if (t < 36){
        float h = 0.f;
        #pragma unroll 8
        for (int c = 0; c < 64; c++){
            g_hinit[(b*64+c)*288 + t0 + t] = h;
            h = sP[c*36+t]*h + sQ[c*36+t];
        }
    }
}

// ---------------- scan pass3: replay + output + py ----------------
#define SCAN3_SMEM ((86*257 + 162 + 18)*4)
__global__ void kScan3(const float* __restrict__ Alog, const float* __restrict__ Dp,
                       const float* __restrict__ opw,  const float* __restrict__ altho){
    extern __shared__ float sm[];
    float* sDT = sm;
    float* sXI = sm + 18*257;
    float* sB  = sm + 36*257;
    float* sC  = sm + 52*257;
    float* sYS = sm + 68*257;
    float* sOPW = sm + 86*257;
    float* sDP  = sOPW + 162;
    int b = blockIdx.y, c = blockIdx.x, l0 = c*256, t = threadIdx.x;
    for (int idx = t; idx < 18*256; idx += 288){
        int dd = idx >> 8, i = idx & 255;
        sDT[dd*257+i] = g_dt[((size_t)(b*18+dd))*LSEQ + l0 + i];
        sXI[dd*257+i] = g_xi[((size_t)(b*18+dd))*LSEQ + l0 + i];
    }
    for (int idx = t; idx < 16*256; idx += 288){
        int ss = idx >> 8, i = idx & 255;
        sB[ss*257+i] = g_Bsc[((size_t)(b*16+ss))*LSEQ + l0 + i];
        sC[ss*257+i] = g_Csc[((size_t)(b*16+ss))*LSEQ + l0 + i];
    }
    if (t < 162) sOPW[t] = opw[t];
    if (t < 18)  sDP[t]  = Dp[t];
    __syncthreads();

    int d = t / 16, s = t % 16;
    float a = -expf(Alog[d*16+s]);
    float h = g_hinit[(b*64+c)*288 + t];
    for (int i = 0; i < 256; i++){
        float dt = sDT[d*257+i];
        float da = __expf(dt*a);
        h = da*h + dt*sB[s*257+i]*sXI[d*257+i];
        float v = h * sC[s*257+i];
        v += __shfl_xor_sync(0xffffffffu, v, 1);
        v += __shfl_xor_sync(0xffffffffu, v, 2);
        v += __shfl_xor_sync(0xffffffffu, v, 4);
        v += __shfl_xor_sync(0xffffffffu, v, 8);
        if ((t & 15) == 0) sYS[d*257+i] = v;
    }
    __syncthreads();

    if (t < 256){
        int l = l0 + t;
        float wgt = fmaxf(softplusf(altho[0]), 0.01f);
        float ym[9];
        #pragma unroll
        for (int m = 0; m < 9; m++) ym[m] = 0.f;
        #pragma unroll
        for (int dd = 0; dd < 18; dd++){
            float yv = (sYS[dd*257+t] + sDP[dd]*sXI[dd*257+t]) * g_gate[((size_t)(b*18+dd))*LSEQ + l];
            #pragma unroll
            for (int m = 0; m < 9; m++) ym[m] += yv * sOPW[m*18+dd];
        }
        int tt = l & 1, r = l >> 1;
        int w = r & 127, h2 = r >> 7;
        int pix = (h2*2 + tt)*128 + w;
        #pragma unroll
        for (int m = 0; m < 9; m++){
            float py = wgt*ym[m] + g_ynew[((size_t)(b*9+m))*HWp + pix];
            py = fminf(fmaxf(py, 0.f), 127.f);
            g_py[((size_t)(b*9+m))*HWp + pix] = py;
        }
    }
}

// ---------------- deformable gather + tf32 tensor-core contraction + GN stats ----------------
#define DEF_SMEM ((128*68 + 64*68)*4)
__global__ void __launch_bounds__(256) kDeform(const float* __restrict__ dscb){
    extern __shared__ unsigned smu[];
    unsigned* sV = smu;             // [pix][ci] stride 68
    unsigned* sA = smu + 128*68;    // [co][ci] stride 68
    int i = blockIdx.x, b = blockIdx.y, t = threadIdx.x;
    int wid = t >> 5, lane = t & 31;
    int gID = lane >> 2, tig = lane & 3;
    int ct = (wid & 3)*16;
    int pt = (wid >> 2)*64;

    float acc[8][4];
    #pragma unroll
    for (int nt = 0; nt < 8; nt++)
        #pragma unroll
        for (int p = 0; p < 4; p++) acc[nt][p] = 0.f;

    for (int k = 0; k < 9; k++){
        #pragma unroll
        for (int r = 0; r < 16; r++){
            int idx = t + 256*r;
            int co = idx >> 6, ci = idx & 63;
            sA[co*68 + ci] = g_wA[k*4096 + idx];
        }
        int p0 = wid*16;
        #pragma unroll
        for (int pp = 0; pp < 16; pp++){
            int j = p0 + pp;
            float pyv = g_py[((size_t)(b*9+k))*HWp + i*128 + j];
            float fy0 = floorf(pyv);
            int y0 = (int)fy0;
            float wy = pyv - fy0;
            float wy0 = 1.f - wy;
            int y1 = min(y0 + 1, 127);
            int xc = min(max(j + k - 4, 0), 127);
            const float* base0 = &g_xT[((size_t)b*HWp + y0*128 + xc)*64];
            const float* base1 = &g_xT[((size_t)b*HWp + y1*128 + xc)*64];
            float vL = base0[lane]*wy0    + base1[lane]*wy;
            float vH = base0[lane+32]*wy0 + base1[lane+32]*wy;
            sV[j*68 + lane]      = tf32cvt(vL);
            sV[j*68 + lane + 32] = tf32cvt(vH);
        }
        __syncthreads();

        #pragma unroll
        for (int ks = 0; ks < 8; ks++){
            int kk = ks*8;
            unsigned a0 = sA[(ct+gID)*68   + kk + tig];
            unsigned a1 = sA[(ct+gID+8)*68 + kk + tig];
            unsigned a2 = sA[(ct+gID)*68   + kk + tig + 4];
            unsigned a3 = sA[(ct+gID+8)*68 + kk + tig + 4];
            #pragma unroll
            for (int nt = 0; nt < 8; nt++){
                int n0 = pt + nt*8;
                unsigned b0 = sV[(n0+gID)*68 + kk + tig];
                unsigned b1 = sV[(n0+gID)*68 + kk + tig + 4];
                mma_tf32(acc[nt], a0, a1, a2, a3, b0, b1);
            }
        }
        __syncthreads();
    }

    int co0 = ct + gID, co1 = ct + gID + 8;
    float bias0 = dscb[co0], bias1 = dscb[co1];
    float s0 = 0.f, ss0 = 0.f, s1 = 0.f, ss1 = 0.f;
    #pragma unroll
    for (int nt = 0; nt < 8; nt++){
        float c0 = acc[nt][0] + bias0, c1 = acc[nt][1] + bias0;
        float c2 = acc[nt][2] + bias1, c3 = acc[nt][3] + bias1;
        size_t pix = (size_t)i*128 + pt + nt*8 + tig*2;
        *(float2*)&g_outraw[((size_t)(b*64+co0))*HWp + pix] = make_float2(c0, c1);
        *(float2*)&g_outraw[((size_t)(b*64+co1))*HWp + pix] = make_float2(c2, c3);
        s0 += c0 + c1; ss0 += c0*c0 + c1*c1;
        s1 += c2 + c3; ss1 += c2*c2 + c3*c3;
    }
    #pragma unroll
    for (int m = 1; m <= 8; m <<= 1){
        s0  += __shfl_xor_sync(0xffffffffu, s0,  m);
        ss0 += __shfl_xor_sync(0xffffffffu, ss0, m);
        s1  += __shfl_xor_sync(0xffffffffu, s1,  m);
        ss1 += __shfl_xor_sync(0xffffffffu, ss1, m);
    }
    if ((lane & 15) == 0){
        int g0 = (ct >> 2) + (lane >> 4);
        atomicAdd(&g_fstats[(b*16 + g0)*2    ], s0);
        atomicAdd(&g_fstats[(b*16 + g0)*2 + 1], ss0);
        atomicAdd(&g_fstats[(b*16 + g0 + 2)*2    ], s1);
        atomicAdd(&g_fstats[(b*16 + g0 + 2)*2 + 1], ss1);
    }
}

// ---------------- final GN (float4) ----------------
__global__ void kFinalGN(const float* __restrict__ gng, const float* __restrict__ gnb,
                         float* __restrict__ out){
    int idx4 = blockIdx.x*256 + threadIdx.x;
    int idx = idx4*4;
    int b = idx >> 20;
    int c = (idx >> 14) & 63;
    int g = c >> 2;
    float s  = g_fstats[(b*16+g)*2];
    float ss = g_fstats[(b*16+g)*2+1];
    float mu = s * (1.f/65536.f);
    float var = ss * (1.f/65536.f) - mu*mu;
    float rs = rsqrtf(var + 1e-5f) * gng[c];
    float bb = gnb[c];
    float4 v = *(const float4*)&g_outraw[idx];
    float4 o;
    o.x = (v.x - mu)*rs + bb;
    o.y = (v.y - mu)*rs + bb;
    o.z = (v.z - mu)*rs + bb;
    o.w = (v.w - mu)*rs + bb;
    *(float4*)&out[idx] = o;
}

extern "C" void kernel_launch(void* const* d_in, const int* in_sizes, int n_in,
                              void* d_out, int out_size){
    const float* x     = (const float*)d_in[0];
    const float* offw  = (const float*)d_in[1];
    const float* offb  = (const float*)d_in[2];
    const float* gnog  = (const float*)d_in[3];
    const float* gnob  = (const float*)d_in[4];
    const float* altho = (const float*)d_in[5];
    const float* ipw   = (const float*)d_in[6];
    const float* cw    = (const float*)d_in[7];
    const float* cb    = (const float*)d_in[8];
    const float* xpw   = (const float*)d_in[9];
    const float* dtw   = (const float*)d_in[10];
    const float* dtb   = (const float*)d_in[11];
    const float* Alog  = (const float*)d_in[12];
    const float* Dp    = (const float*)d_in[13];
    const float* opw   = (const float*)d_in[14];
    const float* dscw  = (const float*)d_in[15];
    const float* dscb  = (const float*)d_in[16];
    const float* gng   = (const float*)d_in[17];
    const float* gnb   = (const float*)d_in[18];
    float* out = (float*)d_out;

    cudaFuncSetAttribute(kConvM, cudaFuncAttributeMaxDynamicSharedMemorySize, CONVM_SMEM);
    cudaFuncSetAttribute(kFused,  cudaFuncAttributeMaxDynamicSharedMemorySize, FUS_SMEM);
    cudaFuncSetAttribute(kScan3,  cudaFuncAttributeMaxDynamicSharedMemorySize, SCAN3_SMEM);
    cudaFuncSetAttribute(kDeform, cudaFuncAttributeMaxDynamicSharedMemorySize, DEF_SMEM);

    kPrep<<<dim3(512, 2, 4), dim3(32, 8)>>>(x, dscw, offw);
    kConvM<<<dim3(128, 4), 256, CONVM_SMEM>>>(offb);
    kFused<<<dim3(64, 4), 288, FUS_SMEM>>>(gnog, gnob, ipw, cw, cb, xpw, dtw, dtb, Alog);
    kScan2<<<dim3(4, 8), 288, SCAN2_SMEM>>>();
    kScan3<<<dim3(64, 4), 288, SCAN3_SMEM>>>(Alog, Dp, opw, altho);
    kDeform<<<dim3(128, 4), 256, DEF_SMEM>>>(dscb);
    kFinalGN<<<4096, 256>>>(gng, gnb, out);
}

// round 10
// speedup vs baseline: 2.5039x; 1.0300x over previous
#include <cuda_runtime.h>
#include <math.h>

#define Bn   4
#define HWp  16384
#define LSEQ 16384

// ---------------- tf32 mma helpers ----------------
__device__ __forceinline__ unsigned tf32cvt(float v){
    unsigned r; asm("cvt.rna.tf32.f32 %0, %1;" : "=r"(r) : "f"(v)); return r;
}
__device__ __forceinline__ void mma_tf32(float* d, unsigned a0, unsigned a1, unsigned a2, unsigned a3,
                                         unsigned b0, unsigned b1){
    asm("mma.sync.aligned.m16n8k8.row.col.f32.tf32.tf32.f32 "
        "{%0,%1,%2,%3}, {%4,%5,%6,%7}, {%8,%9}, {%0,%1,%2,%3};"
        : "+f"(d[0]), "+f"(d[1]), "+f"(d[2]), "+f"(d[3])
        : "r"(a0), "r"(a1), "r"(a2), "r"(a3), "r"(b0), "r"(b1));
}

// ---------------- scratch ----------------
__device__ float g_xT[Bn*HWp*64];        // [b][pix][c]
__device__ float g_rawoff[Bn*10*HWp];    // offset conv out, [b][co][pix]
__device__ float g_ostats[Bn*5*2];
__device__ float g_ynew[Bn*9*HWp];       // [b][k][pix]
__device__ float g_dt[Bn*18*LSEQ];
__device__ float g_xi[Bn*18*LSEQ];
__device__ float g_gate[Bn*18*LSEQ];     // silu(z)
__device__ float g_Bsc[Bn*16*LSEQ];
__device__ float g_Csc[Bn*16*LSEQ];
__device__ float g_P[Bn*64*288];
__device__ float g_Q[Bn*64*288];
__device__ float g_hinit[Bn*64*288];
__device__ float g_py[Bn*9*HWp];         // [b][k][pix]
__device__ unsigned g_wA[9*64*64];       // [k][co][ci] tf32, deform conv
__device__ unsigned g_wCf[9*8*128];      // offset conv A in mma fragment order
__device__ float g_outraw[Bn*64*HWp];
__device__ float g_fstats[Bn*16*2];

__device__ __forceinline__ float softplusf(float x){
    return x > 20.f ? x : log1pf(expf(x));
}
__device__ __forceinline__ float siluf(float x){
    return x / (1.f + expf(-x));
}

// ---------------- prep: transpose x + zero stats + weight tf32 conversions ----------------
__global__ void kPrep(const float* __restrict__ x, const float* __restrict__ dscw,
                      const float* __restrict__ offw){
    __shared__ float tile[32][33];
    int b = blockIdx.z, c0 = blockIdx.y*32, p0 = blockIdx.x*32;
    int bid = (blockIdx.z*gridDim.y + blockIdx.y)*gridDim.x + blockIdx.x;
    int gtid = bid*256 + threadIdx.y*32 + threadIdx.x;

    if (gtid < 36864){
        int k = gtid >> 12; int r = gtid & 4095;
        int co = r >> 6;  int ci = r & 63;
        g_wA[gtid] = tf32cvt(dscw[(co*64 + ci)*9 + k]);
    }
    if (gtid >= 40960 && gtid < 40960+9216){
        int idx = gtid - 40960;
        // fragment-order pack: idx = (tap*8+ks)*128 + lane*4 + q
        int tap = idx >> 10; int rem = idx & 1023;
        int ks = rem >> 7;   int r = rem & 127;
        int lane = r >> 2,   q = r & 3;
        int gID = lane >> 2, tig = lane & 3;
        int co = gID + 8*(q & 1);
        int ci = ks*8 + tig + 4*(q >> 1);
        int dy = tap/3, dx = tap - dy*3;
        float v = (co < 10) ? offw[((co*64+ci)*3 + dy)*3 + dx] : 0.f;
        g_wCf[idx] = tf32cvt(v);
    }
    if (gtid >= 65536 && gtid < 65536+40)  g_ostats[gtid-65536] = 0.f;
    if (gtid >= 131072 && gtid < 131072+128) g_fstats[gtid-131072] = 0.f;

    for (int i = threadIdx.y; i < 32; i += 8)
        tile[i][threadIdx.x] = x[(size_t)(b*64 + c0 + i)*HWp + p0 + threadIdx.x];
    __syncthreads();
    for (int i = threadIdx.y; i < 32; i += 8)
        g_xT[(size_t)(b*HWp + p0 + i)*64 + c0 + threadIdx.x] = tile[threadIdx.x][i];
}

// ---------------- offset conv 3x3 64->10 via tf32 mma (implicit im2col) ----------------
// block = (row h, batch b), 256 threads = 8 warps. warp n-tile = 16 pixels.
// V only in smem (106 KB -> 2 blocks/SM); A fragments loaded as coalesced
// uint4 from g_wCf (identical 36 KB for all warps -> L1-resident).
#define CONVM_SMEM (390*68*4)
__global__ void __launch_bounds__(256) kConvM(const float* __restrict__ offb){
    extern __shared__ unsigned su[];
    unsigned* sV = su;            // [dy*130+jp][68]
    int h = blockIdx.x, b = blockIdx.y, t = threadIdx.x;
    int wid = t >> 5, lane = t & 31, gID = lane >> 2, tig = lane & 3;
    int n0 = wid*16;

    for (int idx = t; idx < 3*130*16; idx += 256){
        int c4 = idx & 15;
        int r = idx >> 4;          // dy*130 + jp
        int jp = r % 130; int dy = r / 130;
        int gh = h - 1 + dy, gw = jp - 1;
        float4 v = make_float4(0.f, 0.f, 0.f, 0.f);
        if (gh >= 0 && gh < 128 && gw >= 0 && gw < 128)
            v = *(const float4*)&g_xT[((size_t)b*HWp + gh*128 + gw)*64 + c4*4];
        uint4 tv;
        tv.x = tf32cvt(v.x); tv.y = tf32cvt(v.y);
        tv.z = tf32cvt(v.z); tv.w = tf32cvt(v.w);
        *(uint4*)&sV[r*68 + c4*4] = tv;
    }
    __syncthreads();

    float acc[2][4];
    #pragma unroll
    for (int nt = 0; nt < 2; nt++)
        #pragma unroll
        for (int p = 0; p < 4; p++) acc[nt][p] = 0.f;

    #pragma unroll
    for (int tap = 0; tap < 9; tap++){
        int dy = tap/3, dx = tap - dy*3;
        int vbase = dy*130 + dx;
        #pragma unroll
        for (int ks = 0; ks < 8; ks++){
            int kk = ks*8;
            uint4 f = *(const uint4*)&g_wCf[((tap*8 + ks) << 7) + (lane << 2)];
            #pragma unroll
            for (int nt = 0; nt < 2; nt++){
                int j = n0 + nt*8 + gID;
                unsigned b0 = sV[(vbase + j)*68 + kk + tig];
                unsigned b1 = sV[(vbase + j)*68 + kk + tig + 4];
                mma_tf32(acc[nt], f.x, f.y, f.z, f.w, b0, b1);
            }
        }
    }

    // epilogue: co0 = gID (ch 0..7), co1 = gID+8 (ch 8,9 valid; >=10 exact zeros)
    int co0 = gID, co1 = gID + 8;
    float bias0 = offb[co0];
    float bias1 = (gID < 2) ? offb[co1] : 0.f;
    float s0 = 0.f, ss0 = 0.f, s1 = 0.f, ss1 = 0.f;
    #pragma unroll
    for (int nt = 0; nt < 2; nt++){
        float c0 = acc[nt][0] + bias0, c1 = acc[nt][1] + bias0;
        int pix = h*128 + n0 + nt*8 + tig*2;
        *(float2*)&g_rawoff[((size_t)(b*10+co0))*HWp + pix] = make_float2(c0, c1);
        s0 += c0 + c1; ss0 += c0*c0 + c1*c1;
        if (gID < 2){
            float c2 = acc[nt][2] + bias1, c3 = acc[nt][3] + bias1;
            *(float2*)&g_rawoff[((size_t)(b*10+co1))*HWp + pix] = make_float2(c2, c3);
            s1 += c2 + c3; ss1 += c2*c2 + c3*c3;
        }
    }
    #pragma unroll
    for (int m = 1; m <= 4; m <<= 1){
        s0  += __shfl_xor_sync(0xffffffffu, s0,  m);
        ss0 += __shfl_xor_sync(0xffffffffu, ss0, m);
        s1  += __shfl_xor_sync(0xffffffffu, s1,  m);
        ss1 += __shfl_xor_sync(0xffffffffu, ss1, m);
    }
    if (tig == 0 && (gID & 1) == 0){
        int g0 = gID >> 1;
        atomicAdd(&g_ostats[(b*5 + g0)*2    ], s0);
        atomicAdd(&g_ostats[(b*5 + g0)*2 + 1], ss0);
        if (gID == 0){
            atomicAdd(&g_ostats[(b*5 + 4)*2    ], s1);
            atomicAdd(&g_ostats[(b*5 + 4)*2 + 1], ss1);
        }
    }
}

// ---------------- fused: GN+tanh+cumsum+ynew -> front-end GEMVs -> scan pass1 ----------------
__device__ __forceinline__ void comp_tv(int b, int l, const float* sMu, const float* sRs,
                                        const float* __restrict__ gnog,
                                        const float* __restrict__ gnob, float* tv){
    int tt = l & 1, r = l >> 1;
    int w = r & 127, r2 = r >> 7;
    int p = (r2*2 + tt)*128 + w;
    #pragma unroll
    for (int c = 0; c < 9; c++){
        float raw = g_rawoff[((size_t)(b*10+c))*HWp + p];
        float xn = (raw - sMu[c>>1]) * sRs[c>>1] * gnog[c] + gnob[c];
        tv[c] = tanhf(xn);
    }
}

#define FUS_SMEM (19339*4)
__global__ void __launch_bounds__(288) kFused(
        const float* __restrict__ gnog, const float* __restrict__ gnob,
        const float* __restrict__ ipw,  const float* __restrict__ cw,
        const float* __restrict__ cb,   const float* __restrict__ xpw,
        const float* __restrict__ dtw,  const float* __restrict__ dtb,
        const float* __restrict__ Alog){
    extern __shared__ float sm[];
    float* sXP  = sm;            // 259*19
    float* sIPW = sm + 4921;     // 324
    float* sXPW = sm + 5245;     // 594
    float* sCW  = sm + 5839;     // 72
    float* sCB  = sm + 5911;     // 18
    float* sDTW = sm + 5929;     // 18
    float* sDTB = sm + 5947;     // 18
    float* sMu  = sm + 5965;     // 5
    float* sRs  = sm + 5970;     // 5
    float* sDT  = sm + 5975;     // 18*257
    float* sXI  = sm + 10601;    // 18*257
    float* sB   = sm + 15227;    // 16*257
    int b = blockIdx.y, c = blockIdx.x, l0 = c*256, t = threadIdx.x;

    for (int idx = t; idx < 324; idx += 288) sIPW[idx] = ipw[idx];
    for (int idx = t; idx < 594; idx += 288) sXPW[idx] = xpw[idx];
    if (t < 72) sCW[t] = cw[t];
    if (t < 18){ sCB[t] = cb[t]; sDTW[t] = dtw[t]; sDTB[t] = dtb[t]; }
    if (t < 5){
        float s  = g_ostats[(b*5+t)*2];
        float ss = g_ostats[(b*5+t)*2+1];
        float mu = s * (1.f/32768.f);
        float var = ss * (1.f/32768.f) - mu*mu;
        sMu[t] = mu;
        sRs[t] = rsqrtf(var + 1e-5f);
    }
    __syncthreads();

    if (t < 256){
        int l = l0 + t;
        float tv[9];
        comp_tv(b, l, sMu, sRs, gnog, gnob, tv);

        float cum[9];
        cum[4] = 0.f;
        cum[5] = tv[5]; cum[6] = cum[5]+tv[6]; cum[7] = cum[6]+tv[7]; cum[8] = cum[7]+tv[8];
        cum[3] = tv[3]; cum[2] = cum[3]+tv[2]; cum[1] = cum[2]+tv[1]; cum[0] = cum[1]+tv[0];

        int tt = l & 1, r = l >> 1;
        int w = r & 127, r2 = r >> 7;
        int h = r2*2 + tt, p = h*128 + w;
        #pragma unroll
        for (int k = 0; k < 9; k++)
            g_ynew[((size_t)(b*9+k))*HWp + p] = (float)h + cum[k];

        #pragma unroll
        for (int n = 0; n < 18; n++){
            float v = 0.f;
            #pragma unroll
            for (int m = 0; m < 9; m++) v += tv[m]*sIPW[n*9+m];
            sXP[(t+3)*19 + n] = v;
        }
        #pragma unroll
        for (int n = 0; n < 18; n++){
            float z = 0.f;
            #pragma unroll
            for (int m = 0; m < 9; m++) z += tv[m]*sIPW[(18+n)*9+m];
            g_gate[((size_t)(b*18+n))*LSEQ + l] = siluf(z);
        }
    } else if (t < 259){
        int bi = t - 256;
        int l2 = l0 - 3 + bi;
        if (l2 >= 0){
            float tv2[9];
            comp_tv(b, l2, sMu, sRs, gnog, gnob, tv2);
            #pragma unroll
            for (int n = 0; n < 18; n++){
                float v = 0.f;
                #pragma unroll
                for (int m = 0; m < 9; m++) v += tv2[m]*sIPW[n*9+m];
                sXP[bi*19 + n] = v;
            }
        } else {
            #pragma unroll
            for (int n = 0; n < 18; n++) sXP[bi*19 + n] = 0.f;
        }
    }
    __syncthreads();

    if (t < 256){
        int l = l0 + t;
        float xi[18];
        #pragma unroll
        for (int d = 0; d < 18; d++){
            float xc = sCB[d];
            #pragma unroll
            for (int j = 0; j < 4; j++) xc += sCW[d*4+j]*sXP[(t+j)*19 + d];
            xi[d] = siluf(xc);
        }
        float dtr = 0.f;
        #pragma unroll
        for (int d = 0; d < 18; d++) dtr += xi[d]*sXPW[d];
        #pragma unroll
        for (int s = 0; s < 16; s++){
            float bv = 0.f, cv = 0.f;
            #pragma unroll
            for (int d = 0; d < 18; d++){
                bv += xi[d]*sXPW[(1+s)*18 + d];
                cv += xi[d]*sXPW[(17+s)*18 + d];
            }
            sB[s*257 + t] = bv;
            g_Bsc[((size_t)(b*16+s))*LSEQ + l] = bv;
            g_Csc[((size_t)(b*16+s))*LSEQ + l] = cv;
        }
        #pragma unroll
        for (int d = 0; d < 18; d++){
            float a = dtr*sDTW[d] + sDTB[d];
            float dtv = softplusf(a);
            sDT[d*257 + t] = dtv;
            sXI[d*257 + t] = xi[d];
            g_dt[((size_t)(b*18+d))*LSEQ + l] = dtv;
            g_xi[((size_t)(b*18+d))*LSEQ + l] = xi[d];
        }
    }
    __syncthreads();

    int d = t / 16, s = t % 16;
    float a = -expf(Alog[d*16+s]);
    float p = 1.f, q = 0.f;
    for (int i = 0; i < 256; i++){
        float dt = sDT[d*257+i];
        float da = __expf(dt*a);
        q = da*q + dt*sB[s*257+i]*sXI[d*257+i];
        p *= da;
    }
    g_P[(b*64+c)*288 + t] = p;
    g_Q[(b*64+c)*288 + t] = q;
}

// ---------------- scan pass2: serial carry, t-sliced 18/block ----------------
#define SCAN2_SMEM (2*64*18*4)
__global__ void __launch_bounds__(288) kScan2(){
    extern __shared__ float sm[];
    float* sP = sm;            // [c][18]
    float* sQ = sm + 64*18;
    int b = blockIdx.x, sl = blockIdx.y, t = threadIdx.x;
    int t0 = sl*18;
    for (int idx = t; idx < 64*18; idx += 288){
        int c = idx/18, tt = idx - c*18;
        sP[idx] = g_P[(b*64+c)*288 + t0 + tt];
        sQ[idx] = g_Q[(b*64+c)*288 + t0 + tt];
    }
    __syncthreads();
    if (t < 18){
        float h = 0.f;
        #pragma unroll 8
        for (int c = 0; c < 64; c++){
            g_hinit[(b*64+c)*288 + t0 + t] = h;
            h = sP[c*18+t]*h + sQ[c*18+t];
        }
    }
}

// ---------------- scan pass3: replay + output + py ----------------
#define SCAN3_SMEM ((86*257 + 162 + 18)*4)
__global__ void kScan3(const float* __restrict__ Alog, const float* __restrict__ Dp,
                       const float* __restrict__ opw,  const float* __restrict__ altho){
    extern __shared__ float sm[];
    float* sDT = sm;
    float* sXI = sm + 18*257;
    float* sB  = sm + 36*257;
    float* sC  = sm + 52*257;
    float* sYS = sm + 68*257;
    float* sOPW = sm + 86*257;
    float* sDP  = sOPW + 162;
    int b = blockIdx.y, c = blockIdx.x, l0 = c*256, t = threadIdx.x;
    for (int idx = t; idx < 18*256; idx += 288){
        int dd = idx >> 8, i = idx & 255;
        sDT[dd*257+i] = g_dt[((size_t)(b*18+dd))*LSEQ + l0 + i];
        sXI[dd*257+i] = g_xi[((size_t)(b*18+dd))*LSEQ + l0 + i];
    }
    for (int idx = t; idx < 16*256; idx += 288){
        int ss = idx >> 8, i = idx & 255;
        sB[ss*257+i] = g_Bsc[((size_t)(b*16+ss))*LSEQ + l0 + i];
        sC[ss*257+i] = g_Csc[((size_t)(b*16+ss))*LSEQ + l0 + i];
    }
    if (t < 162) sOPW[t] = opw[t];
    if (t < 18)  sDP[t]  = Dp[t];
    __syncthreads();

    int d = t / 16, s = t % 16;
    float a = -expf(Alog[d*16+s]);
    float h = g_hinit[(b*64+c)*288 + t];
    for (int i = 0; i < 256; i++){
        float dt = sDT[d*257+i];
        float da = __expf(dt*a);
        h = da*h + dt*sB[s*257+i]*sXI[d*257+i];
        float v = h * sC[s*257+i];
        v += __shfl_xor_sync(0xffffffffu, v, 1);
        v += __shfl_xor_sync(0xffffffffu, v, 2);
        v += __shfl_xor_sync(0xffffffffu, v, 4);
        v += __shfl_xor_sync(0xffffffffu, v, 8);
        if ((t & 15) == 0) sYS[d*257+i] = v;
    }
    __syncthreads();

    if (t < 256){
        int l = l0 + t;
        float wgt = fmaxf(softplusf(altho[0]), 0.01f);
        float ym[9];
        #pragma unroll
        for (int m = 0; m < 9; m++) ym[m] = 0.f;
        #pragma unroll
        for (int dd = 0; dd < 18; dd++){
            float yv = (sYS[dd*257+t] + sDP[dd]*sXI[dd*257+t]) * g_gate[((size_t)(b*18+dd))*LSEQ + l];
            #pragma unroll
            for (int m = 0; m < 9; m++) ym[m] += yv * sOPW[m*18+dd];
        }
        int tt = l & 1, r = l >> 1;
        int w = r & 127, h2 = r >> 7;
        int pix = (h2*2 + tt)*128 + w;
        #pragma unroll
        for (int m = 0; m < 9; m++){
            float py = wgt*ym[m] + g_ynew[((size_t)(b*9+m))*HWp + pix];
            py = fminf(fmaxf(py, 0.f), 127.f);
            g_py[((size_t)(b*9+m))*HWp + pix] = py;
        }
    }
}

// ---------------- deformable gather + tf32 tensor-core contraction + GN stats ----------------
#define DEF_SMEM ((128*68 + 64*68)*4)
__global__ void __launch_bounds__(256) kDeform(const float* __restrict__ dscb){
    extern __shared__ unsigned smu[];
    unsigned* sV = smu;             // [pix][ci] stride 68
    unsigned* sA = smu + 128*68;    // [co][ci] stride 68
    int i = blockIdx.x, b = blockIdx.y, t = threadIdx.x;
    int wid = t >> 5, lane = t & 31;
    int gID = lane >> 2, tig = lane & 3;
    int ct = (wid & 3)*16;
    int pt = (wid >> 2)*64;

    float acc[8][4];
    #pragma unroll
    for (int nt = 0; nt < 8; nt++)
        #pragma unroll
        for (int p = 0; p < 4; p++) acc[nt][p] = 0.f;

    for (int k = 0; k < 9; k++){
        #pragma unroll
        for (int r = 0; r < 16; r++){
            int idx = t + 256*r;
            int co = idx >> 6, ci = idx & 63;
            sA[co*68 + ci] = g_wA[k*4096 + idx];
        }
        int p0 = wid*16;
        #pragma unroll
        for (int pp = 0; pp < 16; pp++){
            int j = p0 + pp;
            float pyv = g_py[((size_t)(b*9+k))*HWp + i*128 + j];
            float fy0 = floorf(pyv);
            int y0 = (int)fy0;
            float wy = pyv - fy0;
            float wy0 = 1.f - wy;
            int y1 = min(y0 + 1, 127);
            int xc = min(max(j + k - 4, 0), 127);
            const float* base0 = &g_xT[((size_t)b*HWp + y0*128 + xc)*64];
            const float* base1 = &g_xT[((size_t)b*HWp + y1*128 + xc)*64];
            float vL = base0[lane]*wy0    + base1[lane]*wy;
            float vH = base0[lane+32]*wy0 + base1[lane+32]*wy;
            sV[j*68 + lane]      = tf32cvt(vL);
            sV[j*68 + lane + 32] = tf32cvt(vH);
        }
        __syncthreads();

        #pragma unroll
        for (int ks = 0; ks < 8; ks++){
            int kk = ks*8;
            unsigned a0 = sA[(ct+gID)*68   + kk + tig];
            unsigned a1 = sA[(ct+gID+8)*68 + kk + tig];
            unsigned a2 = sA[(ct+gID)*68   + kk + tig + 4];
            unsigned a3 = sA[(ct+gID+8)*68 + kk + tig + 4];
            #pragma unroll
            for (int nt = 0; nt < 8; nt++){
                int n0 = pt + nt*8;
                unsigned b0 = sV[(n0+gID)*68 + kk + tig];
                unsigned b1 = sV[(n0+gID)*68 + kk + tig + 4];
                mma_tf32(acc[nt], a0, a1, a2, a3, b0, b1);
            }
        }
        __syncthreads();
    }

    int co0 = ct + gID, co1 = ct + gID + 8;
    float bias0 = dscb[co0], bias1 = dscb[co1];
    float s0 = 0.f, ss0 = 0.f, s1 = 0.f, ss1 = 0.f;
    #pragma unroll
    for (int nt = 0; nt < 8; nt++){
        float c0 = acc[nt][0] + bias0, c1 = acc[nt][1] + bias0;
        float c2 = acc[nt][2] + bias1, c3 = acc[nt][3] + bias1;
        size_t pix = (size_t)i*128 + pt + nt*8 + tig*2;
        *(float2*)&g_outraw[((size_t)(b*64+co0))*HWp + pix] = make_float2(c0, c1);
        *(float2*)&g_outraw[((size_t)(b*64+co1))*HWp + pix] = make_float2(c2, c3);
        s0 += c0 + c1; ss0 += c0*c0 + c1*c1;
        s1 += c2 + c3; ss1 += c2*c2 + c3*c3;
    }
    #pragma unroll
    for (int m = 1; m <= 8; m <<= 1){
        s0  += __shfl_xor_sync(0xffffffffu, s0,  m);
        ss0 += __shfl_xor_sync(0xffffffffu, ss0, m);
        s1  += __shfl_xor_sync(0xffffffffu, s1,  m);
        ss1 += __shfl_xor_sync(0xffffffffu, ss1, m);
    }
    if ((lane & 15) == 0){
        int g0 = (ct >> 2) + (lane >> 4);
        atomicAdd(&g_fstats[(b*16 + g0)*2    ], s0);
        atomicAdd(&g_fstats[(b*16 + g0)*2 + 1], ss0);
        atomicAdd(&g_fstats[(b*16 + g0 + 2)*2    ], s1);
        atomicAdd(&g_fstats[(b*16 + g0 + 2)*2 + 1], ss1);
    }
}

// ---------------- final GN (float4) ----------------
__global__ void kFinalGN(const float* __restrict__ gng, const float* __restrict__ gnb,
                         float* __restrict__ out){
    int idx4 = blockIdx.x*256 + threadIdx.x;
    int idx = idx4*4;
    int b = idx >> 20;
    int c = (idx >> 14) & 63;
    int g = c >> 2;
    float s  = g_fstats[(b*16+g)*2];
    float ss = g_fstats[(b*16+g)*2+1];
    float mu = s * (1.f/65536.f);
    float var = ss * (1.f/65536.f) - mu*mu;
    float rs = rsqrtf(var + 1e-5f) * gng[c];
    float bb = gnb[c];
    float4 v = *(const float4*)&g_outraw[idx];
    float4 o;
    o.x = (v.x - mu)*rs + bb;
    o.y = (v.y - mu)*rs + bb;
    o.z = (v.z - mu)*rs + bb;
    o.w = (v.w - mu)*rs + bb;
    *(float4*)&out[idx] = o;
}

extern "C" void kernel_launch(void* const* d_in, const int* in_sizes, int n_in,
                              void* d_out, int out_size){
    const float* x     = (const float*)d_in[0];
    const float* offw  = (const float*)d_in[1];
    const float* offb  = (const float*)d_in[2];
    const float* gnog  = (const float*)d_in[3];
    const float* gnob  = (const float*)d_in[4];
    const float* altho = (const float*)d_in[5];
    const float* ipw   = (const float*)d_in[6];
    const float* cw    = (const float*)d_in[7];
    const float* cb    = (const float*)d_in[8];
    const float* xpw   = (const float*)d_in[9];
    const float* dtw   = (const float*)d_in[10];
    const float* dtb   = (const float*)d_in[11];
    const float* Alog  = (const float*)d_in[12];
    const float* Dp    = (const float*)d_in[13];
    const float* opw   = (const float*)d_in[14];
    const float* dscw  = (const float*)d_in[15];
    const float* dscb  = (const float*)d_in[16];
    const float* gng   = (const float*)d_in[17];
    const float* gnb   = (const float*)d_in[18];
    float* out = (float*)d_out;

    cudaFuncSetAttribute(kConvM, cudaFuncAttributeMaxDynamicSharedMemorySize, CONVM_SMEM);
    cudaFuncSetAttribute(kFused,  cudaFuncAttributeMaxDynamicSharedMemorySize, FUS_SMEM);
    cudaFuncSetAttribute(kScan3,  cudaFuncAttributeMaxDynamicSharedMemorySize, SCAN3_SMEM);
    cudaFuncSetAttribute(kDeform, cudaFuncAttributeMaxDynamicSharedMemorySize, DEF_SMEM);

    kPrep<<<dim3(512, 2, 4), dim3(32, 8)>>>(x, dscw, offw);
    kConvM<<<dim3(128, 4), 256, CONVM_SMEM>>>(offb);
    kFused<<<dim3(64, 4), 288, FUS_SMEM>>>(gnog, gnob, ipw, cw, cb, xpw, dtw, dtb, Alog);
    kScan2<<<dim3(4, 16), 288, SCAN2_SMEM>>>();
    kScan3<<<dim3(64, 4), 288, SCAN3_SMEM>>>(Alog, Dp, opw, altho);
    kDeform<<<dim3(128, 4), 256, DEF_SMEM>>>(dscb);
    kFinalGN<<<4096, 256>>>(gng, gnb, out);
}

// round 11
// speedup vs baseline: 3.0726x; 1.2271x over previous
#include <cuda_runtime.h>
#include <math.h>

#define Bn   4
#define HWp  16384
#define LSEQ 16384

// ---------------- tf32 mma helpers ----------------
__device__ __forceinline__ unsigned tf32cvt(float v){
    unsigned r; asm("cvt.rna.tf32.f32 %0, %1;" : "=r"(r) : "f"(v)); return r;
}
__device__ __forceinline__ void mma_tf32(float* d, unsigned a0, unsigned a1, unsigned a2, unsigned a3,
                                         unsigned b0, unsigned b1){
    asm("mma.sync.aligned.m16n8k8.row.col.f32.tf32.tf32.f32 "
        "{%0,%1,%2,%3}, {%4,%5,%6,%7}, {%8,%9}, {%0,%1,%2,%3};"
        : "+f"(d[0]), "+f"(d[1]), "+f"(d[2]), "+f"(d[3])
        : "r"(a0), "r"(a1), "r"(a2), "r"(a3), "r"(b0), "r"(b1));
}

// ---------------- scratch ----------------
__device__ float g_xT[Bn*HWp*64];        // [b][pix][c]
__device__ float g_rawoff[Bn*10*HWp];    // offset conv out, [b][co][pix]
__device__ float g_ostats[Bn*5*2];
__device__ float g_ynew[Bn*9*HWp];       // [b][k][pix]
__device__ float g_dt[Bn*18*LSEQ];
__device__ float g_xi[Bn*18*LSEQ];
__device__ float g_gate[Bn*18*LSEQ];     // silu(z)
__device__ float g_Bsc[Bn*16*LSEQ];
__device__ float g_Csc[Bn*16*LSEQ];
__device__ float g_P[Bn*64*288];
__device__ float g_Q[Bn*64*288];
__device__ float g_hinit[Bn*64*288];
__device__ float g_py[Bn*9*HWp];         // [b][k][pix]
__device__ unsigned g_wAf[9*64*64];      // deform conv A, mma fragment order
__device__ unsigned g_wCf[9*8*128];      // offset conv A, mma fragment order
__device__ float g_outraw[Bn*64*HWp];
__device__ float g_fstats[Bn*16*2];

__device__ __forceinline__ float softplusf(float x){
    return x > 20.f ? x : log1pf(expf(x));
}
__device__ __forceinline__ float siluf(float x){
    return x / (1.f + expf(-x));
}

// ---------------- prep: transpose x + zero stats + weight tf32 conversions ----------------
__global__ void kPrep(const float* __restrict__ x, const float* __restrict__ dscw,
                      const float* __restrict__ offw){
    __shared__ float tile[32][33];
    int b = blockIdx.z, c0 = blockIdx.y*32, p0 = blockIdx.x*32;
    int bid = (blockIdx.z*gridDim.y + blockIdx.y)*gridDim.x + blockIdx.x;
    int gtid = bid*256 + threadIdx.y*32 + threadIdx.x;

    if (gtid < 36864){
        // fragment pack: gtid = (((k*4+ctq)*8+ks)*128) + lane*4 + q
        int k = gtid >> 12;
        int rem = gtid & 4095;
        int ctq = rem >> 10;
        int rem2 = rem & 1023;
        int ks = rem2 >> 7;
        int r = rem2 & 127;
        int lane = r >> 2, q = r & 3;
        int gID = lane >> 2, tig = lane & 3;
        int co = ctq*16 + gID + ((q & 1) << 3);
        int ci = ks*8 + tig + ((q >> 1) << 2);
        g_wAf[gtid] = tf32cvt(dscw[(co*64 + ci)*9 + k]);
    }
    if (gtid >= 40960 && gtid < 40960+9216){
        int idx = gtid - 40960;
        int tap = idx >> 10; int rem = idx & 1023;
        int ks = rem >> 7;   int r = rem & 127;
        int lane = r >> 2,   q = r & 3;
        int gID = lane >> 2, tig = lane & 3;
        int co = gID + 8*(q & 1);
        int ci = ks*8 + tig + 4*(q >> 1);
        int dy = tap/3, dx = tap - dy*3;
        float v = (co < 10) ? offw[((co*64+ci)*3 + dy)*3 + dx] : 0.f;
        g_wCf[idx] = tf32cvt(v);
    }
    if (gtid >= 65536 && gtid < 65536+40)  g_ostats[gtid-65536] = 0.f;
    if (gtid >= 131072 && gtid < 131072+128) g_fstats[gtid-131072] = 0.f;

    for (int i = threadIdx.y; i < 32; i += 8)
        tile[i][threadIdx.x] = x[(size_t)(b*64 + c0 + i)*HWp + p0 + threadIdx.x];
    __syncthreads();
    for (int i = threadIdx.y; i < 32; i += 8)
        g_xT[(size_t)(b*HWp + p0 + i)*64 + c0 + threadIdx.x] = tile[threadIdx.x][i];
}

// ---------------- offset conv 3x3 64->10 via tf32 mma (implicit im2col) ----------------
#define CONVM_SMEM (390*68*4)
__global__ void __launch_bounds__(256) kConvM(const float* __restrict__ offb){
    extern __shared__ unsigned su[];
    unsigned* sV = su;            // [dy*130+jp][68]
    int h = blockIdx.x, b = blockIdx.y, t = threadIdx.x;
    int wid = t >> 5, lane = t & 31, gID = lane >> 2, tig = lane & 3;
    int n0 = wid*16;

    for (int idx = t; idx < 3*130*16; idx += 256){
        int c4 = idx & 15;
        int r = idx >> 4;          // dy*130 + jp
        int jp = r % 130; int dy = r / 130;
        int gh = h - 1 + dy, gw = jp - 1;
        float4 v = make_float4(0.f, 0.f, 0.f, 0.f);
        if (gh >= 0 && gh < 128 && gw >= 0 && gw < 128)
            v = *(const float4*)&g_xT[((size_t)b*HWp + gh*128 + gw)*64 + c4*4];
        uint4 tv;
        tv.x = tf32cvt(v.x); tv.y = tf32cvt(v.y);
        tv.z = tf32cvt(v.z); tv.w = tf32cvt(v.w);
        *(uint4*)&sV[r*68 + c4*4] = tv;
    }
    __syncthreads();

    float acc[2][4];
    #pragma unroll
    for (int nt = 0; nt < 2; nt++)
        #pragma unroll
        for (int p = 0; p < 4; p++) acc[nt][p] = 0.f;

    #pragma unroll
    for (int tap = 0; tap < 9; tap++){
        int dy = tap/3, dx = tap - dy*3;
        int vbase = dy*130 + dx;
        #pragma unroll
        for (int ks = 0; ks < 8; ks++){
            int kk = ks*8;
            uint4 f = *(const uint4*)&g_wCf[((tap*8 + ks) << 7) + (lane << 2)];
            #pragma unroll
            for (int nt = 0; nt < 2; nt++){
                int j = n0 + nt*8 + gID;
                unsigned b0 = sV[(vbase + j)*68 + kk + tig];
                unsigned b1 = sV[(vbase + j)*68 + kk + tig + 4];
                mma_tf32(acc[nt], f.x, f.y, f.z, f.w, b0, b1);
            }
        }
    }

    int co0 = gID, co1 = gID + 8;
    float bias0 = offb[co0];
    float bias1 = (gID < 2) ? offb[co1] : 0.f;
    float s0 = 0.f, ss0 = 0.f, s1 = 0.f, ss1 = 0.f;
    #pragma unroll
    for (int nt = 0; nt < 2; nt++){
        float c0 = acc[nt][0] + bias0, c1 = acc[nt][1] + bias0;
        int pix = h*128 + n0 + nt*8 + tig*2;
        *(float2*)&g_rawoff[((size_t)(b*10+co0))*HWp + pix] = make_float2(c0, c1);
        s0 += c0 + c1; ss0 += c0*c0 + c1*c1;
        if (gID < 2){
            float c2 = acc[nt][2] + bias1, c3 = acc[nt][3] + bias1;
            *(float2*)&g_rawoff[((size_t)(b*10+co1))*HWp + pix] = make_float2(c2, c3);
            s1 += c2 + c3; ss1 += c2*c2 + c3*c3;
        }
    }
    #pragma unroll
    for (int m = 1; m <= 4; m <<= 1){
        s0  += __shfl_xor_sync(0xffffffffu, s0,  m);
        ss0 += __shfl_xor_sync(0xffffffffu, ss0, m);
        s1  += __shfl_xor_sync(0xffffffffu, s1,  m);
        ss1 += __shfl_xor_sync(0xffffffffu, ss1, m);
    }
    if (tig == 0 && (gID & 1) == 0){
        int g0 = gID >> 1;
        atomicAdd(&g_ostats[(b*5 + g0)*2    ], s0);
        atomicAdd(&g_ostats[(b*5 + g0)*2 + 1], ss0);
        if (gID == 0){
            atomicAdd(&g_ostats[(b*5 + 4)*2    ], s1);
            atomicAdd(&g_ostats[(b*5 + 4)*2 + 1], ss1);
        }
    }
}

// ---------------- fused: GN+tanh+cumsum+ynew -> front-end GEMVs -> scan pass1 ----------------
__device__ __forceinline__ void comp_tv(int b, int l, const float* sMu, const float* sRs,
                                        const float* __restrict__ gnog,
                                        const float* __restrict__ gnob, float* tv){
    int tt = l & 1, r = l >> 1;
    int w = r & 127, r2 = r >> 7;
    int p = (r2*2 + tt)*128 + w;
    #pragma unroll
    for (int c = 0; c < 9; c++){
        float raw = g_rawoff[((size_t)(b*10+c))*HWp + p];
        float xn = (raw - sMu[c>>1]) * sRs[c>>1] * gnog[c] + gnob[c];
        tv[c] = tanhf(xn);
    }
}

#define FUS_SMEM (19339*4)
__global__ void __launch_bounds__(288) kFused(
        const float* __restrict__ gnog, const float* __restrict__ gnob,
        const float* __restrict__ ipw,  const float* __restrict__ cw,
        const float* __restrict__ cb,   const float* __restrict__ xpw,
        const float* __restrict__ dtw,  const float* __restrict__ dtb,
        const float* __restrict__ Alog){
    extern __shared__ float sm[];
    float* sXP  = sm;            // 259*19
    float* sIPW = sm + 4921;     // 324
    float* sXPW = sm + 5245;     // 594
    float* sCW  = sm + 5839;     // 72
    float* sCB  = sm + 5911;     // 18
    float* sDTW = sm + 5929;     // 18
    float* sDTB = sm + 5947;     // 18
    float* sMu  = sm + 5965;     // 5
    float* sRs  = sm + 5970;     // 5
    float* sDT  = sm + 5975;     // 18*257
    float* sXI  = sm + 10601;    // 18*257
    float* sB   = sm + 15227;    // 16*257
    int b = blockIdx.y, c = blockIdx.x, l0 = c*256, t = threadIdx.x;

    for (int idx = t; idx < 324; idx += 288) sIPW[idx] = ipw[idx];
    for (int idx = t; idx < 594; idx += 288) sXPW[idx] = xpw[idx];
    if (t < 72) sCW[t] = cw[t];
    if (t < 18){ sCB[t] = cb[t]; sDTW[t] = dtw[t]; sDTB[t] = dtb[t]; }
    if (t < 5){
        float s  = g_ostats[(b*5+t)*2];
        float ss = g_ostats[(b*5+t)*2+1];
        float mu = s * (1.f/32768.f);
        float var = ss * (1.f/32768.f) - mu*mu;
        sMu[t] = mu;
        sRs[t] = rsqrtf(var + 1e-5f);
    }
    __syncthreads();

    if (t < 256){
        int l = l0 + t;
        float tv[9];
        comp_tv(b, l, sMu, sRs, gnog, gnob, tv);

        float cum[9];
        cum[4] = 0.f;
        cum[5] = tv[5]; cum[6] = cum[5]+tv[6]; cum[7] = cum[6]+tv[7]; cum[8] = cum[7]+tv[8];
        cum[3] = tv[3]; cum[2] = cum[3]+tv[2]; cum[1] = cum[2]+tv[1]; cum[0] = cum[1]+tv[0];

        int tt = l & 1, r = l >> 1;
        int w = r & 127, r2 = r >> 7;
        int h = r2*2 + tt, p = h*128 + w;
        #pragma unroll
        for (int k = 0; k < 9; k++)
            g_ynew[((size_t)(b*9+k))*HWp + p] = (float)h + cum[k];

        #pragma unroll
        for (int n = 0; n < 18; n++){
            float v = 0.f;
            #pragma unroll
            for (int m = 0; m < 9; m++) v += tv[m]*sIPW[n*9+m];
            sXP[(t+3)*19 + n] = v;
        }
        #pragma unroll
        for (int n = 0; n < 18; n++){
            float z = 0.f;
            #pragma unroll
            for (int m = 0; m < 9; m++) z += tv[m]*sIPW[(18+n)*9+m];
            g_gate[((size_t)(b*18+n))*LSEQ + l] = siluf(z);
        }
    } else if (t < 259){
        int bi = t - 256;
        int l2 = l0 - 3 + bi;
        if (l2 >= 0){
            float tv2[9];
            comp_tv(b, l2, sMu, sRs, gnog, gnob, tv2);
            #pragma unroll
            for (int n = 0; n < 18; n++){
                float v = 0.f;
                #pragma unroll
                for (int m = 0; m < 9; m++) v += tv2[m]*sIPW[n*9+m];
                sXP[bi*19 + n] = v;
            }
        } else {
            #pragma unroll
            for (int n = 0; n < 18; n++) sXP[bi*19 + n] = 0.f;
        }
    }
    __syncthreads();

    if (t < 256){
        int l = l0 + t;
        float xi[18];
        #pragma unroll
        for (int d = 0; d < 18; d++){
            float xc = sCB[d];
            #pragma unroll
            for (int j = 0; j < 4; j++) xc += sCW[d*4+j]*sXP[(t+j)*19 + d];
            xi[d] = siluf(xc);
        }
        float dtr = 0.f;
        #pragma unroll
        for (int d = 0; d < 18; d++) dtr += xi[d]*sXPW[d];
        #pragma unroll
        for (int s = 0; s < 16; s++){
            float bv = 0.f, cv = 0.f;
            #pragma unroll
            for (int d = 0; d < 18; d++){
                bv += xi[d]*sXPW[(1+s)*18 + d];
                cv += xi[d]*sXPW[(17+s)*18 + d];
            }
            sB[s*257 + t] = bv;
            g_Bsc[((size_t)(b*16+s))*LSEQ + l] = bv;
            g_Csc[((size_t)(b*16+s))*LSEQ + l] = cv;
        }
        #pragma unroll
        for (int d = 0; d < 18; d++){
            float a = dtr*sDTW[d] + sDTB[d];
            float dtv = softplusf(a);
            sDT[d*257 + t] = dtv;
            sXI[d*257 + t] = xi[d];
            g_dt[((size_t)(b*18+d))*LSEQ + l] = dtv;
            g_xi[((size_t)(b*18+d))*LSEQ + l] = xi[d];
        }
    }
    __syncthreads();

    int d = t / 16, s = t % 16;
    float a = -expf(Alog[d*16+s]);
    float p = 1.f, q = 0.f;
    for (int i = 0; i < 256; i++){
        float dt = sDT[d*257+i];
        float da = __expf(dt*a);
        q = da*q + dt*sB[s*257+i]*sXI[d*257+i];
        p *= da;
    }
    g_P[(b*64+c)*288 + t] = p;
    g_Q[(b*64+c)*288 + t] = q;
}

// ---------------- scan pass2: serial carry, t-sliced 18/block ----------------
#define SCAN2_SMEM (2*64*18*4)
__global__ void __launch_bounds__(288) kScan2(){
    extern __shared__ float sm[];
    float* sP = sm;            // [c][18]
    float* sQ = sm + 64*18;
    int b = blockIdx.x, sl = blockIdx.y, t = threadIdx.x;
    int t0 = sl*18;
    for (int idx = t; idx < 64*18; idx += 288){
        int c = idx/18, tt = idx - c*18;
        sP[idx] = g_P[(b*64+c)*288 + t0 + tt];
        sQ[idx] = g_Q[(b*64+c)*288 + t0 + tt];
    }
    __syncthreads();
    if (t < 18){
        float h = 0.f;
        #pragma unroll 8
        for (int c = 0; c < 64; c++){
            g_hinit[(b*64+c)*288 + t0 + t] = h;
            h = sP[c*18+t]*h + sQ[c*18+t];
        }
    }
}

// ---------------- scan pass3: replay + output + py ----------------
#define SCAN3_SMEM ((86*257 + 162 + 18)*4)
__global__ void kScan3(const float* __restrict__ Alog, const float* __restrict__ Dp,
                       const float* __restrict__ opw,  const float* __restrict__ altho){
    extern __shared__ float sm[];
    float* sDT = sm;
    float* sXI = sm + 18*257;
    float* sB  = sm + 36*257;
    float* sC  = sm + 52*257;
    float* sYS = sm + 68*257;
    float* sOPW = sm + 86*257;
    float* sDP  = sOPW + 162;
    int b = blockIdx.y, c = blockIdx.x, l0 = c*256, t = threadIdx.x;
    for (int idx = t; idx < 18*256; idx += 288){
        int dd = idx >> 8, i = idx & 255;
        sDT[dd*257+i] = g_dt[((size_t)(b*18+dd))*LSEQ + l0 + i];
        sXI[dd*257+i] = g_xi[((size_t)(b*18+dd))*LSEQ + l0 + i];
    }
    for (int idx = t; idx < 16*256; idx += 288){
        int ss = idx >> 8, i = idx & 255;
        sB[ss*257+i] = g_Bsc[((size_t)(b*16+ss))*LSEQ + l0 + i];
        sC[ss*257+i] = g_Csc[((size_t)(b*16+ss))*LSEQ + l0 + i];
    }
    if (t < 162) sOPW[t] = opw[t];
    if (t < 18)  sDP[t]  = Dp[t];
    __syncthreads();

    int d = t / 16, s = t % 16;
    float a = -expf(Alog[d*16+s]);
    float h = g_hinit[(b*64+c)*288 + t];
    for (int i = 0; i < 256; i++){
        float dt = sDT[d*257+i];
        float da = __expf(dt*a);
        h = da*h + dt*sB[s*257+i]*sXI[d*257+i];
        float v = h * sC[s*257+i];
        v += __shfl_xor_sync(0xffffffffu, v, 1);
        v += __shfl_xor_sync(0xffffffffu, v, 2);
        v += __shfl_xor_sync(0xffffffffu, v, 4);
        v += __shfl_xor_sync(0xffffffffu, v, 8);
        if ((t & 15) == 0) sYS[d*257+i] = v;
    }
    __syncthreads();

    if (t < 256){
        int l = l0 + t;
        float wgt = fmaxf(softplusf(altho[0]), 0.01f);
        float ym[9];
        #pragma unroll
        for (int m = 0; m < 9; m++) ym[m] = 0.f;
        #pragma unroll
        for (int dd = 0; dd < 18; dd++){
            float yv = (sYS[dd*257+t] + sDP[dd]*sXI[dd*257+t]) * g_gate[((size_t)(b*18+dd))*LSEQ + l];
            #pragma unroll
            for (int m = 0; m < 9; m++) ym[m] += yv * sOPW[m*18+dd];
        }
        int tt = l & 1, r = l >> 1;
        int w = r & 127, h2 = r >> 7;
        int pix = (h2*2 + tt)*128 + w;
        #pragma unroll
        for (int m = 0; m < 9; m++){
            float py = wgt*ym[m] + g_ynew[((size_t)(b*9+m))*HWp + pix];
            py = fminf(fmaxf(py, 0.f), 127.f);
            g_py[((size_t)(b*9+m))*HWp + pix] = py;
        }
    }
}

// ---------------- deformable gather + tf32 tensor-core contraction + GN stats ----------------
// sV only in smem (34.8 KB -> 4+ blocks/SM); A fragments via coalesced uint4 LDG
// from g_wAf (36 KB, L1-resident). Gather latency of one block overlaps mma of others.
#define DEF_SMEM (128*68*4)
__global__ void __launch_bounds__(256) kDeform(const float* __restrict__ dscb){
    extern __shared__ unsigned sV[];    // [pix][ci] stride 68
    int i = blockIdx.x, b = blockIdx.y, t = threadIdx.x;
    int wid = t >> 5, lane = t & 31;
    int gID = lane >> 2, tig = lane & 3;
    int ctq = wid & 3, ct = ctq*16;
    int pt = (wid >> 2)*64;

    float acc[8][4];
    #pragma unroll
    for (int nt = 0; nt < 8; nt++)
        #pragma unroll
        for (int p = 0; p < 4; p++) acc[nt][p] = 0.f;

    for (int k = 0; k < 9; k++){
        int p0 = wid*16;
        #pragma unroll
        for (int pp = 0; pp < 16; pp++){
            int j = p0 + pp;
            float pyv = g_py[((size_t)(b*9+k))*HWp + i*128 + j];
            float fy0 = floorf(pyv);
            int y0 = (int)fy0;
            float wy = pyv - fy0;
            float wy0 = 1.f - wy;
            int y1 = min(y0 + 1, 127);
            int xc = min(max(j + k - 4, 0), 127);
            const float* base0 = &g_xT[((size_t)b*HWp + y0*128 + xc)*64];
            const float* base1 = &g_xT[((size_t)b*HWp + y1*128 + xc)*64];
            float vL = base0[lane]*wy0    + base1[lane]*wy;
            float vH = base0[lane+32]*wy0 + base1[lane+32]*wy;
            sV[j*68 + lane]      = tf32cvt(vL);
            sV[j*68 + lane + 32] = tf32cvt(vH);
        }
        __syncthreads();

        #pragma unroll
        for (int ks = 0; ks < 8; ks++){
            int kk = ks*8;
            uint4 f = *(const uint4*)&g_wAf[((((k*4 + ctq)*8) + ks) << 7) + (lane << 2)];
            #pragma unroll
            for (int nt = 0; nt < 8; nt++){
                int n0 = pt + nt*8;
                unsigned b0 = sV[(n0+gID)*68 + kk + tig];
                unsigned b1 = sV[(n0+gID)*68 + kk + tig + 4];
                mma_tf32(acc[nt], f.x, f.y, f.z, f.w, b0, b1);
            }
        }
        __syncthreads();
    }

    int co0 = ct + gID, co1 = ct + gID + 8;
    float bias0 = dscb[co0], bias1 = dscb[co1];
    float s0 = 0.f, ss0 = 0.f, s1 = 0.f, ss1 = 0.f;
    #pragma unroll
    for (int nt = 0; nt < 8; nt++){
        float c0 = acc[nt][0] + bias0, c1 = acc[nt][1] + bias0;
        float c2 = acc[nt][2] + bias1, c3 = acc[nt][3] + bias1;
        size_t pix = (size_t)i*128 + pt + nt*8 + tig*2;
        *(float2*)&g_outraw[((size_t)(b*64+co0))*HWp + pix] = make_float2(c0, c1);
        *(float2*)&g_outraw[((size_t)(b*64+co1))*HWp + pix] = make_float2(c2, c3);
        s0 += c0 + c1; ss0 += c0*c0 + c1*c1;
        s1 += c2 + c3; ss1 += c2*c2 + c3*c3;
    }
    #pragma unroll
    for (int m = 1; m <= 8; m <<= 1){
        s0  += __shfl_xor_sync(0xffffffffu, s0,  m);
        ss0 += __shfl_xor_sync(0xffffffffu, ss0, m);
        s1  += __shfl_xor_sync(0xffffffffu, s1,  m);
        ss1 += __shfl_xor_sync(0xffffffffu, ss1, m);
    }
    if ((lane & 15) == 0){
        int g0 = (ct >> 2) + (lane >> 4);
        atomicAdd(&g_fstats[(b*16 + g0)*2    ], s0);
        atomicAdd(&g_fstats[(b*16 + g0)*2 + 1], ss0);
        atomicAdd(&g_fstats[(b*16 + g0 + 2)*2    ], s1);
        atomicAdd(&g_fstats[(b*16 + g0 + 2)*2 + 1], ss1);
    }
}

// ---------------- final GN (float4) ----------------
__global__ void kFinalGN(const float* __restrict__ gng, const float* __restrict__ gnb,
                         float* __restrict__ out){
    int idx4 = blockIdx.x*256 + threadIdx.x;
    int idx = idx4*4;
    int b = idx >> 20;
    int c = (idx >> 14) & 63;
    int g = c >> 2;
    float s  = g_fstats[(b*16+g)*2];
    float ss = g_fstats[(b*16+g)*2+1];
    float mu = s * (1.f/65536.f);
    float var = ss * (1.f/65536.f) - mu*mu;
    float rs = rsqrtf(var + 1e-5f) * gng[c];
    float bb = gnb[c];
    float4 v = *(const float4*)&g_outraw[idx];
    float4 o;
    o.x = (v.x - mu)*rs + bb;
    o.y = (v.y - mu)*rs + bb;
    o.z = (v.z - mu)*rs + bb;
    o.w = (v.w - mu)*rs + bb;
    *(float4*)&out[idx] = o;
}

extern "C" void kernel_launch(void* const* d_in, const int* in_sizes, int n_in,
                              void* d_out, int out_size){
    const float* x     = (const float*)d_in[0];
    const float* offw  = (const float*)d_in[1];
    const float* offb  = (const float*)d_in[2];
    const float* gnog  = (const float*)d_in[3];
    const float* gnob  = (const float*)d_in[4];
    const float* altho = (const float*)d_in[5];
    const float* ipw   = (const float*)d_in[6];
    const float* cw    = (const float*)d_in[7];
    const float* cb    = (const float*)d_in[8];
    const float* xpw   = (const float*)d_in[9];
    const float* dtw   = (const float*)d_in[10];
    const float* dtb   = (const float*)d_in[11];
    const float* Alog  = (const float*)d_in[12];
    const float* Dp    = (const float*)d_in[13];
    const float* opw   = (const float*)d_in[14];
    const float* dscw  = (const float*)d_in[15];
    const float* dscb  = (const float*)d_in[16];
    const float* gng   = (const float*)d_in[17];
    const float* gnb   = (const float*)d_in[18];
    float* out = (float*)d_out;

    cudaFuncSetAttribute(kConvM, cudaFuncAttributeMaxDynamicSharedMemorySize, CONVM_SMEM);
    cudaFuncSetAttribute(kFused,  cudaFuncAttributeMaxDynamicSharedMemorySize, FUS_SMEM);
    cudaFuncSetAttribute(kScan3,  cudaFuncAttributeMaxDynamicSharedMemorySize, SCAN3_SMEM);
    cudaFuncSetAttribute(kDeform, cudaFuncAttributeMaxDynamicSharedMemorySize, DEF_SMEM);

    kPrep<<<dim3(512, 2, 4), dim3(32, 8)>>>(x, dscw, offw);
    kConvM<<<dim3(128, 4), 256, CONVM_SMEM>>>(offb);
    kFused<<<dim3(64, 4), 288, FUS_SMEM>>>(gnog, gnob, ipw, cw, cb, xpw, dtw, dtb, Alog);
    kScan2<<<dim3(4, 16), 288, SCAN2_SMEM>>>();
    kScan3<<<dim3(64, 4), 288, SCAN3_SMEM>>>(Alog, Dp, opw, altho);
    kDeform<<<dim3(128, 4), 256, DEF_SMEM>>>(dscb);
    kFinalGN<<<4096, 256>>>(gng, gnb, out);
}